// round 1
// baseline (speedup 1.0000x reference)
#include <cuda_runtime.h>
#include <math.h>

#define BB   64
#define SS   1024
#define SZS  256
#define CC   256
#define NN   64
#define NKD  67
#define EPSV 1e-5f

// scratch (no allocations allowed -> __device__ globals)
__device__ float g_xn[BB * SS * NN];      // 16 MB  x_n
__device__ float g_kz[BB * NN * CC];      // 4 MB   kernels (z path)
__device__ float g_kx[BB * NN * CC];      // 4 MB   kernels_x raw
__device__ float g_ka[BB * NN * CC];      // 4 MB   kernels_x after atten+layernorm
__device__ float g_tem[BB * CC];          // 64 KB

// ---------------------------------------------------------------------------
// Kernel A: per batch  z_core = Z @ Wz + bz  (256x64),  kz = z_core^T @ Z (64x256)
// grid(64), block(256), dyn smem 98304 B
// ---------------------------------------------------------------------------
__global__ void kA(const float* __restrict__ z_feat, const float* __restrict__ Wz,
                   const float* __restrict__ bz) {
    extern __shared__ float sm[];
    float* szc = sm;                       // 256*64
    float* sZ  = sm + 16384;               // 256*17 (phase 1)
    float* sW  = sm + 16384 + 256 * 17;    // 16*64  (phase 1)
    float* sZ2 = sm + 16384;               // 32*256 (phase 2, overlaps)
    int b = blockIdx.x;
    int t = threadIdx.x;
    int tx = t & 15, ty = t >> 4;
    const float* Z = z_feat + (size_t)b * SZS * CC;

    // phase 1: z_core
    float4 acc1[16];
#pragma unroll
    for (int i = 0; i < 16; i++) acc1[i] = make_float4(0.f, 0.f, 0.f, 0.f);
    for (int kc = 0; kc < CC; kc += 16) {
        for (int idx = t; idx < 256 * 16; idx += 256) {
            int r = idx >> 4, k = idx & 15;
            sZ[r * 17 + k] = Z[r * CC + kc + k];
        }
        for (int idx = t; idx < 16 * 64; idx += 256) {
            int k = idx >> 6, n = idx & 63;
            sW[k * 64 + n] = Wz[(kc + k) * NN + n];
        }
        __syncthreads();
#pragma unroll
        for (int k = 0; k < 16; k++) {
            float4 w = ((const float4*)sW)[k * 16 + tx];
#pragma unroll
            for (int i = 0; i < 16; i++) {
                float a = sZ[(ty * 16 + i) * 17 + k];
                acc1[i].x += a * w.x; acc1[i].y += a * w.y;
                acc1[i].z += a * w.z; acc1[i].w += a * w.w;
            }
        }
        __syncthreads();
    }
    {
        float4 b4 = ((const float4*)bz)[tx];
#pragma unroll
        for (int i = 0; i < 16; i++) {
            float4 v = acc1[i];
            v.x += b4.x; v.y += b4.y; v.z += b4.z; v.w += b4.w;
            ((float4*)szc)[(ty * 16 + i) * 16 + tx] = v;
        }
    }
    __syncthreads();

    // phase 2: kz[n,c] = sum_s z_core[s,n] * Z[s,c]
    float acc2[4][16];
#pragma unroll
    for (int i = 0; i < 4; i++)
#pragma unroll
        for (int j = 0; j < 16; j++) acc2[i][j] = 0.f;

    for (int s0 = 0; s0 < SZS; s0 += 32) {
        for (int idx = t; idx < 32 * 256; idx += 256)
            sZ2[idx] = Z[(s0 + (idx >> 8)) * CC + (idx & 255)];
        __syncthreads();
        for (int s = 0; s < 32; s++) {
            float a[4];
#pragma unroll
            for (int i = 0; i < 4; i++) a[i] = szc[(s0 + s) * 64 + ty * 4 + i];
            float zr[16];
#pragma unroll
            for (int j = 0; j < 16; j++) zr[j] = sZ2[s * 256 + tx + 16 * j];
#pragma unroll
            for (int i = 0; i < 4; i++)
#pragma unroll
                for (int j = 0; j < 16; j++) acc2[i][j] += a[i] * zr[j];
        }
        __syncthreads();
    }
    float* kzb = g_kz + (size_t)b * NN * CC;
#pragma unroll
    for (int i = 0; i < 4; i++)
#pragma unroll
        for (int j = 0; j < 16; j++)
            kzb[(ty * 4 + i) * CC + tx + 16 * j] = acc2[i][j];
}

// ---------------------------------------------------------------------------
// Kernel B: x_n = X @ Wx + bx  ->  g_xn.  grid(8,64), block(256), smem 12800 B
// ---------------------------------------------------------------------------
__global__ void kB(const float* __restrict__ x_feat, const float* __restrict__ Wx,
                   const float* __restrict__ bx) {
    extern __shared__ float sm[];
    float* sX = sm;               // 128*17
    float* sW = sm + 128 * 17;    // 16*64
    int b = blockIdx.y;
    int row0 = blockIdx.x * 128;
    int t = threadIdx.x, tx = t & 15, ty = t >> 4;
    const float* X = x_feat + (size_t)b * SS * CC;

    float4 acc[8];
#pragma unroll
    for (int i = 0; i < 8; i++) acc[i] = make_float4(0.f, 0.f, 0.f, 0.f);

    for (int kc = 0; kc < CC; kc += 16) {
        for (int idx = t; idx < 128 * 16; idx += 256) {
            int r = idx >> 4, k = idx & 15;
            sX[r * 17 + k] = X[(row0 + r) * CC + kc + k];
        }
        for (int idx = t; idx < 16 * 64; idx += 256) {
            int k = idx >> 6, n = idx & 63;
            sW[k * 64 + n] = Wx[(kc + k) * NN + n];
        }
        __syncthreads();
#pragma unroll
        for (int k = 0; k < 16; k++) {
            float4 w = ((const float4*)sW)[k * 16 + tx];
#pragma unroll
            for (int i = 0; i < 8; i++) {
                float a = sX[(ty * 8 + i) * 17 + k];
                acc[i].x += a * w.x; acc[i].y += a * w.y;
                acc[i].z += a * w.z; acc[i].w += a * w.w;
            }
        }
        __syncthreads();
    }
    float4 b4 = ((const float4*)bx)[tx];
    float* xnb = g_xn + ((size_t)b * SS + row0) * NN;
#pragma unroll
    for (int i = 0; i < 8; i++) {
        float4 v = acc[i];
        v.x += b4.x; v.y += b4.y; v.z += b4.z; v.w += b4.w;
        ((float4*)xnb)[(ty * 8 + i) * 16 + tx] = v;
    }
}

// ---------------------------------------------------------------------------
// Kernel C: kx[n,c] = sum_s x_n[s,n] * X[s,c].  grid(4,64), block(256), smem 16 KB
// ---------------------------------------------------------------------------
__global__ void kC(const float* __restrict__ x_feat) {
    extern __shared__ float sm[];
    float* sXn = sm;          // 32*64
    float* sXf = sm + 2048;   // 32*64
    int b = blockIdx.y;
    int c0 = blockIdx.x * 64;
    int t = threadIdx.x, tx = t & 15, ty = t >> 4;
    const float* X  = x_feat + (size_t)b * SS * CC;
    const float* xn = g_xn + (size_t)b * SS * NN;

    float4 acc[4];
#pragma unroll
    for (int i = 0; i < 4; i++) acc[i] = make_float4(0.f, 0.f, 0.f, 0.f);

    for (int s0 = 0; s0 < SS; s0 += 32) {
        for (int idx = t; idx < 2048; idx += 256) {
            int r = idx >> 6, j = idx & 63;
            sXn[idx] = xn[(s0 + r) * NN + j];
            sXf[idx] = X[(s0 + r) * CC + c0 + j];
        }
        __syncthreads();
        for (int s = 0; s < 32; s++) {
            float4 f4 = ((const float4*)sXf)[s * 16 + tx];
#pragma unroll
            for (int i = 0; i < 4; i++) {
                float a = sXn[s * 64 + ty * 4 + i];
                acc[i].x += a * f4.x; acc[i].y += a * f4.y;
                acc[i].z += a * f4.z; acc[i].w += a * f4.w;
            }
        }
        __syncthreads();
    }
    float* kxb = g_kx + (size_t)b * NN * CC;
#pragma unroll
    for (int i = 0; i < 4; i++)
        ((float4*)(kxb + (ty * 4 + i) * CC + c0))[tx] = acc[i];
}

// ---------------------------------------------------------------------------
// Kernel D: dysep conv atten + layernorm + proto + tem, one block per batch.
// grid(64), block(256), dyn smem 214272 B
// ---------------------------------------------------------------------------
__global__ void kD(const float* __restrict__ Wdyn, const float* __restrict__ bdyn,
                   const float* __restrict__ gn, const float* __restrict__ bn,
                   const float* __restrict__ Wp, const float* __restrict__ bp) {
    extern __shared__ float sm[];
    float* sKz = sm;                         // 64*256 (later reused as sP)
    float* sV  = sm + 16384;                 // 64*256
    float* sD  = sm + 32768;                 // 64*256 (Wdyn staging overlaps here)
    float* sDy = sm + 49152;                 // 64*68
    float* sPr = sm + 49152 + 64 * 68;       // 64
    int b = blockIdx.x, t = threadIdx.x;
    const float* kz = g_kz + (size_t)b * NN * CC;
    const float* kx = g_kx + (size_t)b * NN * CC;

    for (int idx = t; idx < NN * CC; idx += 256) { sKz[idx] = kz[idx]; sV[idx] = kx[idx]; }
    __syncthreads();

    // dy = kz @ Wdyn + bdyn  (64 x 67)
    const int nout = NN * NKD;  // 4288
    float accD[17];
#pragma unroll
    for (int k2 = 0; k2 < 17; k2++) {
        int o = t + k2 * 256;
        accD[k2] = (o < nout) ? bdyn[o % NKD] : 0.f;
    }
    for (int c0 = 0; c0 < CC; c0 += 64) {
        float* sWd = sD;  // staging
        for (int idx = t; idx < 64 * NKD; idx += 256)
            sWd[(idx / NKD) * 68 + (idx % NKD)] = Wdyn[(c0 + idx / NKD) * NKD + (idx % NKD)];
        __syncthreads();
#pragma unroll
        for (int k2 = 0; k2 < 17; k2++) {
            int o = t + k2 * 256;
            if (o < nout) {
                int m = o / NKD, jj = o % NKD;
                float a = accD[k2];
                for (int c = 0; c < 64; c++)
                    a += sKz[m * CC + c0 + c] * sWd[c * 68 + jj];
                accD[k2] = a;
            }
        }
        __syncthreads();
    }
#pragma unroll
    for (int k2 = 0; k2 < 17; k2++) {
        int o = t + k2 * 256;
        if (o < nout) sDy[(o / NKD) * 68 + (o % NKD)] = accD[k2];
    }
    __syncthreads();

    // depth(m,c) = relu(w0*v[c-1] + w1*v[c] + w2*v[c+1])
    for (int idx = t; idx < NN * CC; idx += 256) {
        int m = idx >> 8, c = idx & 255;
        float w0 = sDy[m * 68 + 0], w1 = sDy[m * 68 + 1], w2 = sDy[m * 68 + 2];
        float vm = (c > 0)   ? sV[idx - 1] : 0.f;
        float v0 = sV[idx];
        float vp = (c < 255) ? sV[idx + 1] : 0.f;
        float d = w0 * vm + w1 * v0 + w2 * vp;
        sD[idx] = d > 0.f ? d : 0.f;
    }
    __syncthreads();

    // point(n,c) = sum_m wp[n,m]*depth[m,c], then layernorm over c
    int tx = t & 15, ty = t >> 4;
    float acc[4][16];
#pragma unroll
    for (int i = 0; i < 4; i++)
#pragma unroll
        for (int j = 0; j < 16; j++) acc[i][j] = 0.f;
    for (int m = 0; m < NN; m++) {
        float dr[16];
#pragma unroll
        for (int j = 0; j < 16; j++) dr[j] = sD[m * CC + tx + 16 * j];
#pragma unroll
        for (int i = 0; i < 4; i++) {
            float w = sDy[(ty * 4 + i) * 68 + 3 + m];
#pragma unroll
            for (int j = 0; j < 16; j++) acc[i][j] += w * dr[j];
        }
    }
    __syncthreads();

    float* sP = sKz;  // reuse
#pragma unroll
    for (int i = 0; i < 4; i++) {
        int n = ty * 4 + i;
        float sum = 0.f, sq = 0.f;
#pragma unroll
        for (int j = 0; j < 16; j++) { sum += acc[i][j]; sq += acc[i][j] * acc[i][j]; }
#pragma unroll
        for (int off = 8; off >= 1; off >>= 1) {
            sum += __shfl_xor_sync(0xffffffffu, sum, off);
            sq  += __shfl_xor_sync(0xffffffffu, sq, off);
        }
        float mu = sum * (1.f / 256.f);
        float var = sq * (1.f / 256.f) - mu * mu;
        float rs = rsqrtf(var + EPSV);
#pragma unroll
        for (int j = 0; j < 16; j++) {
            int c = tx + 16 * j;
            sP[n * CC + c] = (acc[i][j] - mu) * rs * gn[c] + bn[c];
        }
    }
    __syncthreads();

    float* kab = g_ka + (size_t)b * NN * CC;
    for (int idx = t; idx < NN * CC; idx += 256) kab[idx] = sP[idx];

    // proto[n] = ka[n,:] . Wp + bp
    if (t < 64) {
        float p = bp[0];
        for (int c = 0; c < CC; c++) p += sP[t * CC + c] * Wp[c];
        sPr[t] = p;
    }
    __syncthreads();
    // tem[c] = sigmoid(sum_n proto[n] * ka[n,c])
    {
        float s = 0.f;
        for (int n = 0; n < NN; n++) s += sPr[n] * sP[n * CC + t];
        g_tem[b * CC + t] = 1.f / (1.f + expf(-s));
    }
}

// ---------------------------------------------------------------------------
// Kernel F: x_corr = x_n @ ka, *tem, layernorm, relu, +x_feat -> out
// grid(16,64), block(256), dyn smem 84992 B
// ---------------------------------------------------------------------------
__global__ void kF(const float* __restrict__ x_feat, const float* __restrict__ g_ln,
                   const float* __restrict__ b_ln, float* __restrict__ out) {
    extern __shared__ float sm[];
    float* sKa  = sm;                    // 64*256
    float* sXn  = sm + 16384;            // 64*64
    float* sTem = sm + 16384 + 4096;     // 256
    float* sG   = sTem + 256;            // 256
    float* sB2  = sG + 256;              // 256
    int b = blockIdx.y;
    int r0 = blockIdx.x * 64;
    int t = threadIdx.x, tx = t & 15, ty = t >> 4;
    const float* kab = g_ka + (size_t)b * NN * CC;
    const float* xnb = g_xn + ((size_t)b * SS + r0) * NN;

    for (int idx = t; idx < 16384; idx += 256) sKa[idx] = kab[idx];
    for (int idx = t; idx < 4096; idx += 256) sXn[idx] = xnb[idx];
    { sTem[t] = g_tem[b * CC + t]; sG[t] = g_ln[t]; sB2[t] = b_ln[t]; }
    __syncthreads();

    float4 acc[4][4];
#pragma unroll
    for (int i = 0; i < 4; i++)
#pragma unroll
        for (int jj = 0; jj < 4; jj++) acc[i][jj] = make_float4(0.f, 0.f, 0.f, 0.f);

    for (int n = 0; n < NN; n++) {
        float4 kv[4];
#pragma unroll
        for (int jj = 0; jj < 4; jj++) kv[jj] = ((const float4*)sKa)[n * 64 + jj * 16 + tx];
#pragma unroll
        for (int i = 0; i < 4; i++) {
            float a = sXn[(ty * 4 + i) * 64 + n];
#pragma unroll
            for (int jj = 0; jj < 4; jj++) {
                acc[i][jj].x += a * kv[jj].x; acc[i][jj].y += a * kv[jj].y;
                acc[i][jj].z += a * kv[jj].z; acc[i][jj].w += a * kv[jj].w;
            }
        }
    }

    const float* Xb = x_feat + ((size_t)b * SS + r0) * CC;
    float* Ob = out + ((size_t)b * SS + r0) * CC;
#pragma unroll
    for (int i = 0; i < 4; i++) {
        int r = ty * 4 + i;
        float4 v[4];
        float sum = 0.f, sq = 0.f;
#pragma unroll
        for (int jj = 0; jj < 4; jj++) {
            float4 tm = ((const float4*)sTem)[jj * 16 + tx];
            v[jj] = acc[i][jj];
            v[jj].x *= tm.x; v[jj].y *= tm.y; v[jj].z *= tm.z; v[jj].w *= tm.w;
            sum += v[jj].x + v[jj].y + v[jj].z + v[jj].w;
            sq  += v[jj].x * v[jj].x + v[jj].y * v[jj].y + v[jj].z * v[jj].z + v[jj].w * v[jj].w;
        }
#pragma unroll
        for (int off = 8; off >= 1; off >>= 1) {
            sum += __shfl_xor_sync(0xffffffffu, sum, off);
            sq  += __shfl_xor_sync(0xffffffffu, sq, off);
        }
        float mu = sum * (1.f / 256.f);
        float var = sq * (1.f / 256.f) - mu * mu;
        float rs = rsqrtf(var + EPSV);
#pragma unroll
        for (int jj = 0; jj < 4; jj++) {
            int c4 = jj * 16 + tx;
            float4 g = ((const float4*)sG)[c4];
            float4 bb = ((const float4*)sB2)[c4];
            float4 xf = ((const float4*)(Xb + (size_t)r * CC))[c4];
            float4 o;
            o.x = fmaxf((v[jj].x - mu) * rs * g.x + bb.x, 0.f) + xf.x;
            o.y = fmaxf((v[jj].y - mu) * rs * g.y + bb.y, 0.f) + xf.y;
            o.z = fmaxf((v[jj].z - mu) * rs * g.z + bb.z, 0.f) + xf.z;
            o.w = fmaxf((v[jj].w - mu) * rs * g.w + bb.w, 0.f) + xf.w;
            ((float4*)(Ob + (size_t)r * CC))[c4] = o;
        }
    }
}

// ---------------------------------------------------------------------------
extern "C" void kernel_launch(void* const* d_in, const int* in_sizes, int n_in,
                              void* d_out, int out_size) {
    const float* x_feat = (const float*)d_in[0];
    const float* z_feat = (const float*)d_in[1];
    const float* Wz     = (const float*)d_in[2];
    const float* bz     = (const float*)d_in[3];
    const float* Wx     = (const float*)d_in[4];
    const float* bx     = (const float*)d_in[5];
    const float* Wdyn   = (const float*)d_in[6];
    const float* bdyn   = (const float*)d_in[7];
    const float* gnorm  = (const float*)d_in[8];
    const float* bnorm  = (const float*)d_in[9];
    const float* Wp     = (const float*)d_in[10];
    const float* bp     = (const float*)d_in[11];
    const float* g_ln   = (const float*)d_in[12];
    const float* b_ln   = (const float*)d_in[13];
    float* out = (float*)d_out;

    cudaFuncSetAttribute(kA, cudaFuncAttributeMaxDynamicSharedMemorySize, 98304);
    cudaFuncSetAttribute(kD, cudaFuncAttributeMaxDynamicSharedMemorySize, 214272);
    cudaFuncSetAttribute(kF, cudaFuncAttributeMaxDynamicSharedMemorySize, 84992);

    kA<<<BB, 256, 98304>>>(z_feat, Wz, bz);
    kB<<<dim3(8, BB), 256, 12800>>>(x_feat, Wx, bx);
    kC<<<dim3(4, BB), 256, 16384>>>(x_feat);
    kD<<<BB, 256, 214272>>>(Wdyn, bdyn, gnorm, bnorm, Wp, bp);
    kF<<<dim3(16, BB), 256, 84992>>>(x_feat, g_ln, b_ln, out);
}

// round 2
// speedup vs baseline: 1.3703x; 1.3703x over previous
#include <cuda_runtime.h>
#include <math.h>

#define BB   64
#define SS   1024
#define SZS  256
#define CC   256
#define NN   64
#define NKD  67
#define EPSV 1e-5f

// scratch (no allocations allowed -> __device__ globals)
__device__ float g_xn[BB * SS * NN];          // x_n          (16 MB)
__device__ float g_zc[BB * SZS * NN];         // z_core       (4 MB)
__device__ float g_kzp[2 * BB * NN * CC];     // kz partials  (8 MB)
__device__ float g_kxp[2 * BB * NN * CC];     // kx partials  (8 MB)
__device__ float g_ka[BB * NN * CC];          // kernels_x post-LN (4 MB)
__device__ float g_tem[BB * CC];

// ---------------------------------------------------------------------------
// kLin<TILE_S>:  out[s,n] = feat[s,:] @ W + bias   (N = 64, C = 256)
// grid(Stotal/TILE_S, BB), 256 threads.
// thread: tx = t&7 (n = tx*4 + u*32, u<2), ty = t>>3 (rows ty*RPT..)
// ---------------------------------------------------------------------------
template<int TILE_S>
__global__ void kLin(const float* __restrict__ feat, const float* __restrict__ W,
                     const float* __restrict__ bias, float* __restrict__ outp,
                     int Stotal) {
    extern __shared__ float sm[];
    float* sX = sm;                 // TILE_S x 17 (padded)
    float* sW = sm + TILE_S * 17;   // 16 x 64
    constexpr int RPT = TILE_S / 32;
    int b = blockIdx.y;
    int row0 = blockIdx.x * TILE_S;
    int t = threadIdx.x, tx = t & 7, ty = t >> 3;
    const float* X = feat + (size_t)b * Stotal * CC;

    float4 acc[RPT][2];
#pragma unroll
    for (int i = 0; i < RPT; i++) {
        acc[i][0] = make_float4(0.f, 0.f, 0.f, 0.f);
        acc[i][1] = make_float4(0.f, 0.f, 0.f, 0.f);
    }

    for (int kc = 0; kc < CC; kc += 16) {
        for (int f = t; f < TILE_S * 4; f += 256) {
            int r = f >> 2, kq = f & 3;
            float4 v = *(const float4*)(X + (size_t)(row0 + r) * CC + kc + kq * 4);
            float* d = sX + r * 17 + kq * 4;
            d[0] = v.x; d[1] = v.y; d[2] = v.z; d[3] = v.w;
        }
        ((float4*)sW)[t] = ((const float4*)(W + kc * NN))[t];
        __syncthreads();
#pragma unroll
        for (int k = 0; k < 16; k++) {
            float4 w0 = *(const float4*)(sW + k * NN + tx * 4);
            float4 w1 = *(const float4*)(sW + k * NN + tx * 4 + 32);
#pragma unroll
            for (int i = 0; i < RPT; i++) {
                float a = sX[(ty * RPT + i) * 17 + k];
                acc[i][0].x += a * w0.x; acc[i][0].y += a * w0.y;
                acc[i][0].z += a * w0.z; acc[i][0].w += a * w0.w;
                acc[i][1].x += a * w1.x; acc[i][1].y += a * w1.y;
                acc[i][1].z += a * w1.z; acc[i][1].w += a * w1.w;
            }
        }
        __syncthreads();
    }
    float4 b0 = *(const float4*)(bias + tx * 4);
    float4 b1 = *(const float4*)(bias + tx * 4 + 32);
#pragma unroll
    for (int i = 0; i < RPT; i++) {
        int r = row0 + ty * RPT + i;
        float4 v0 = acc[i][0], v1 = acc[i][1];
        v0.x += b0.x; v0.y += b0.y; v0.z += b0.z; v0.w += b0.w;
        v1.x += b1.x; v1.y += b1.y; v1.z += b1.z; v1.w += b1.w;
        *(float4*)(outp + ((size_t)b * Stotal + r) * NN + tx * 4) = v0;
        *(float4*)(outp + ((size_t)b * Stotal + r) * NN + tx * 4 + 32) = v1;
    }
}

// ---------------------------------------------------------------------------
// kOuter<SH>: partial[n,c] = sum_{s in half} xn[s,n] * feat[s,c]
// grid(2 c-tiles, 2 s-halves, BB), 256 threads.
// thread: tx = t&31 (c = c0 + tx*4), ty = t>>5 (n = ty*8 .. +7)
// ---------------------------------------------------------------------------
template<int SH>
__global__ void kOuter(const float* __restrict__ feat, const float* __restrict__ xn,
                       float* __restrict__ outp) {
    extern __shared__ float sm[];
    float* sN = sm;           // 32 x 64
    float* sF = sm + 2048;    // 32 x 128
    int c0 = blockIdx.x * 128;
    int sh = blockIdx.y;
    int b = blockIdx.z;
    int t = threadIdx.x, tx = t & 31, ty = t >> 5;
    const float* F  = feat + ((size_t)b * (SH * 2) + sh * SH) * CC;
    const float* XN = xn   + ((size_t)b * (SH * 2) + sh * SH) * NN;

    float4 acc[8];
#pragma unroll
    for (int i = 0; i < 8; i++) acc[i] = make_float4(0.f, 0.f, 0.f, 0.f);

    for (int s0 = 0; s0 < SH; s0 += 32) {
        for (int f = t; f < 512; f += 256)
            ((float4*)sN)[f] = *(const float4*)(XN + (size_t)s0 * NN + f * 4);
        for (int f = t; f < 1024; f += 256) {
            int r = f >> 5, cq = f & 31;
            ((float4*)sF)[f] = *(const float4*)(F + (size_t)(s0 + r) * CC + c0 + cq * 4);
        }
        __syncthreads();
#pragma unroll 4
        for (int s = 0; s < 32; s++) {
            float4 xv = *(const float4*)(sF + s * 128 + tx * 4);
#pragma unroll
            for (int i = 0; i < 8; i++) {
                float a = sN[s * NN + ty * 8 + i];
                acc[i].x += a * xv.x; acc[i].y += a * xv.y;
                acc[i].z += a * xv.z; acc[i].w += a * xv.w;
            }
        }
        __syncthreads();
    }
    float* O = outp + (size_t)sh * BB * NN * CC + (size_t)b * NN * CC;
#pragma unroll
    for (int i = 0; i < 8; i++)
        *(float4*)(O + (ty * 8 + i) * CC + c0 + tx * 4) = acc[i];
}

// ---------------------------------------------------------------------------
// kD: dysep conv atten + layernorm + proto + tem. grid(64), 512 threads.
// ---------------------------------------------------------------------------
__global__ void kD(const float* __restrict__ Wdyn, const float* __restrict__ bdyn,
                   const float* __restrict__ gn, const float* __restrict__ bn,
                   const float* __restrict__ Wp, const float* __restrict__ bp) {
    extern __shared__ float sm[];
    float* sKz = sm;            // 16384  (later reused as sP)
    float* sV  = sm + 16384;    // 16384
    float* sU  = sm + 32768;    // 17408  (WdynT staging, then depth)
    float* sDy = sm + 50176;    // 64 x 68
    float* sPr = sm + 54528;    // 64
    int b = blockIdx.x, t = threadIdx.x;

    const float* kz0 = g_kzp + (size_t)b * NN * CC;
    const float* kz1 = kz0 + (size_t)BB * NN * CC;
    const float* kx0 = g_kxp + (size_t)b * NN * CC;
    const float* kx1 = kx0 + (size_t)BB * NN * CC;
    for (int idx = t; idx < NN * CC; idx += 512) {
        sKz[idx] = kz0[idx] + kz1[idx];
        sV[idx]  = kx0[idx] + kx1[idx];
    }
    // stage Wdyn transposed-padded: sU[c*68 + jj]
    for (int idx = t; idx < CC * NKD; idx += 512) {
        int c = idx / NKD, jj = idx - c * NKD;
        sU[c * 68 + jj] = Wdyn[idx];
    }
    __syncthreads();

    // dy[m,jj] = kz[m,:] . Wdyn[:,jj] + bdyn[jj]
#pragma unroll
    for (int k = 0; k < 9; k++) {
        int o = t + k * 512;
        if (o < NN * NKD) {
            int m = o / NKD, jj = o - m * NKD;
            const float* kzr = sKz + m * CC;
            const float* wc  = sU + jj;
            float a0 = 0.f, a1 = 0.f, a2 = 0.f, a3 = 0.f;
#pragma unroll 4
            for (int c = 0; c < CC; c += 4) {
                float4 kv = *(const float4*)(kzr + c);
                a0 += kv.x * wc[(c + 0) * 68];
                a1 += kv.y * wc[(c + 1) * 68];
                a2 += kv.z * wc[(c + 2) * 68];
                a3 += kv.w * wc[(c + 3) * 68];
            }
            sDy[m * 68 + jj] = bdyn[jj] + ((a0 + a1) + (a2 + a3));
        }
    }
    __syncthreads();

    // depth(m,c) = relu(w0*v[c-1] + w1*v[c] + w2*v[c+1])   (overwrites sU)
    for (int idx = t; idx < NN * CC; idx += 512) {
        int m = idx >> 8, c = idx & 255;
        float w0 = sDy[m * 68 + 0], w1 = sDy[m * 68 + 1], w2 = sDy[m * 68 + 2];
        float vm = (c > 0)   ? sV[idx - 1] : 0.f;
        float v0 = sV[idx];
        float vp = (c < 255) ? sV[idx + 1] : 0.f;
        float d = w0 * vm + w1 * v0 + w2 * vp;
        sU[idx] = d > 0.f ? d : 0.f;
    }
    __syncthreads();

    // point(n,c) = sum_m wp[n,m]*depth[m,c]; then layernorm over c
    int tx = t & 31, ty = t >> 5;   // ty 0..15, n = ty*4+i, c = tx*4 + u*128
    float4 acc[4][2];
#pragma unroll
    for (int i = 0; i < 4; i++) {
        acc[i][0] = make_float4(0.f, 0.f, 0.f, 0.f);
        acc[i][1] = make_float4(0.f, 0.f, 0.f, 0.f);
    }
#pragma unroll 2
    for (int m = 0; m < NN; m++) {
        float4 d0 = *(const float4*)(sU + m * CC + tx * 4);
        float4 d1 = *(const float4*)(sU + m * CC + tx * 4 + 128);
#pragma unroll
        for (int i = 0; i < 4; i++) {
            float w = sDy[(ty * 4 + i) * 68 + 3 + m];
            acc[i][0].x += w * d0.x; acc[i][0].y += w * d0.y;
            acc[i][0].z += w * d0.z; acc[i][0].w += w * d0.w;
            acc[i][1].x += w * d1.x; acc[i][1].y += w * d1.y;
            acc[i][1].z += w * d1.z; acc[i][1].w += w * d1.w;
        }
    }
    __syncthreads();   // sKz free now

    float* sP = sKz;
    float* kab = g_ka + (size_t)b * NN * CC;
    float4 gg0 = *(const float4*)(gn + tx * 4);
    float4 gg1 = *(const float4*)(gn + tx * 4 + 128);
    float4 bb0 = *(const float4*)(bn + tx * 4);
    float4 bb1 = *(const float4*)(bn + tx * 4 + 128);
#pragma unroll
    for (int i = 0; i < 4; i++) {
        int n = ty * 4 + i;
        float4 v0 = acc[i][0], v1 = acc[i][1];
        float sum = v0.x + v0.y + v0.z + v0.w + v1.x + v1.y + v1.z + v1.w;
        float sq  = v0.x * v0.x + v0.y * v0.y + v0.z * v0.z + v0.w * v0.w
                  + v1.x * v1.x + v1.y * v1.y + v1.z * v1.z + v1.w * v1.w;
#pragma unroll
        for (int off = 16; off >= 1; off >>= 1) {
            sum += __shfl_xor_sync(0xffffffffu, sum, off);
            sq  += __shfl_xor_sync(0xffffffffu, sq, off);
        }
        float mu = sum * (1.f / 256.f);
        float var = sq * (1.f / 256.f) - mu * mu;
        float rs = rsqrtf(var + EPSV);
        float4 o0, o1;
        o0.x = (v0.x - mu) * rs * gg0.x + bb0.x;
        o0.y = (v0.y - mu) * rs * gg0.y + bb0.y;
        o0.z = (v0.z - mu) * rs * gg0.z + bb0.z;
        o0.w = (v0.w - mu) * rs * gg0.w + bb0.w;
        o1.x = (v1.x - mu) * rs * gg1.x + bb1.x;
        o1.y = (v1.y - mu) * rs * gg1.y + bb1.y;
        o1.z = (v1.z - mu) * rs * gg1.z + bb1.z;
        o1.w = (v1.w - mu) * rs * gg1.w + bb1.w;
        *(float4*)(sP + n * CC + tx * 4) = o0;
        *(float4*)(sP + n * CC + tx * 4 + 128) = o1;
        *(float4*)(kab + n * CC + tx * 4) = o0;
        *(float4*)(kab + n * CC + tx * 4 + 128) = o1;
    }
    __syncthreads();

    // proto[n] = ka[n,:] . Wp + bp
    if (t < NN) {
        float a0 = 0.f, a1 = 0.f, a2 = 0.f, a3 = 0.f;
        for (int c = 0; c < CC; c += 4) {
            float4 p = *(const float4*)(sP + t * CC + c);
            float4 w = *(const float4*)(Wp + c);
            a0 += p.x * w.x; a1 += p.y * w.y; a2 += p.z * w.z; a3 += p.w * w.w;
        }
        sPr[t] = bp[0] + ((a0 + a1) + (a2 + a3));
    }
    __syncthreads();

    // tem[c] = sigmoid(sum_n proto[n] * ka[n,c])
    if (t < CC) {
        float a0 = 0.f, a1 = 0.f, a2 = 0.f, a3 = 0.f;
#pragma unroll 4
        for (int n = 0; n < NN; n += 4) {
            a0 += sPr[n + 0] * sP[(n + 0) * CC + t];
            a1 += sPr[n + 1] * sP[(n + 1) * CC + t];
            a2 += sPr[n + 2] * sP[(n + 2) * CC + t];
            a3 += sPr[n + 3] * sP[(n + 3) * CC + t];
        }
        float s = (a0 + a1) + (a2 + a3);
        g_tem[b * CC + t] = 1.f / (1.f + expf(-s));
    }
}

// ---------------------------------------------------------------------------
// kF: x_corr = x_n @ ka, *tem, layernorm, relu, +x_feat -> out
// grid(16, 64), 256 threads. thread: tx=t&31 (c=tx*4+jj*128), ty=t>>5 (r=ty*8..)
// ---------------------------------------------------------------------------
__global__ void kF(const float* __restrict__ x_feat, const float* __restrict__ g_ln,
                   const float* __restrict__ b_ln, float* __restrict__ out) {
    extern __shared__ float sm[];
    float* sKa  = sm;            // 64 x 256
    float* sXn  = sm + 16384;    // 64 x 64
    float* sTem = sm + 20480;    // 256
    float* sG   = sm + 20736;    // 256
    float* sB2  = sm + 20992;    // 256
    int b = blockIdx.y;
    int r0 = blockIdx.x * 64;
    int t = threadIdx.x, tx = t & 31, ty = t >> 5;
    const float* kab = g_ka + (size_t)b * NN * CC;
    const float* xnb = g_xn + ((size_t)b * SS + r0) * NN;

    for (int f = t; f < 4096; f += 256) ((float4*)sKa)[f] = ((const float4*)kab)[f];
    for (int f = t; f < 1024; f += 256) ((float4*)sXn)[f] = ((const float4*)xnb)[f];
    if (t < 256) { sTem[t] = g_tem[b * CC + t]; sG[t] = g_ln[t]; sB2[t] = b_ln[t]; }
    __syncthreads();

    float4 acc[8][2];
#pragma unroll
    for (int i = 0; i < 8; i++) {
        acc[i][0] = make_float4(0.f, 0.f, 0.f, 0.f);
        acc[i][1] = make_float4(0.f, 0.f, 0.f, 0.f);
    }
#pragma unroll 2
    for (int n = 0; n < NN; n++) {
        float4 k0 = *(const float4*)(sKa + n * CC + tx * 4);
        float4 k1 = *(const float4*)(sKa + n * CC + tx * 4 + 128);
#pragma unroll
        for (int i = 0; i < 8; i++) {
            float a = sXn[(ty * 8 + i) * NN + n];
            acc[i][0].x += a * k0.x; acc[i][0].y += a * k0.y;
            acc[i][0].z += a * k0.z; acc[i][0].w += a * k0.w;
            acc[i][1].x += a * k1.x; acc[i][1].y += a * k1.y;
            acc[i][1].z += a * k1.z; acc[i][1].w += a * k1.w;
        }
    }

    float4 t0 = *(const float4*)(sTem + tx * 4);
    float4 t1 = *(const float4*)(sTem + tx * 4 + 128);
    float4 gg0 = *(const float4*)(sG + tx * 4);
    float4 gg1 = *(const float4*)(sG + tx * 4 + 128);
    float4 bb0 = *(const float4*)(sB2 + tx * 4);
    float4 bb1 = *(const float4*)(sB2 + tx * 4 + 128);
    const float* Xb = x_feat + ((size_t)b * SS + r0) * CC;
    float* Ob = out + ((size_t)b * SS + r0) * CC;
#pragma unroll
    for (int i = 0; i < 8; i++) {
        int r = ty * 8 + i;
        float4 v0 = acc[i][0], v1 = acc[i][1];
        v0.x *= t0.x; v0.y *= t0.y; v0.z *= t0.z; v0.w *= t0.w;
        v1.x *= t1.x; v1.y *= t1.y; v1.z *= t1.z; v1.w *= t1.w;
        float sum = v0.x + v0.y + v0.z + v0.w + v1.x + v1.y + v1.z + v1.w;
        float sq  = v0.x * v0.x + v0.y * v0.y + v0.z * v0.z + v0.w * v0.w
                  + v1.x * v1.x + v1.y * v1.y + v1.z * v1.z + v1.w * v1.w;
#pragma unroll
        for (int off = 16; off >= 1; off >>= 1) {
            sum += __shfl_xor_sync(0xffffffffu, sum, off);
            sq  += __shfl_xor_sync(0xffffffffu, sq, off);
        }
        float mu = sum * (1.f / 256.f);
        float var = sq * (1.f / 256.f) - mu * mu;
        float rs = rsqrtf(var + EPSV);
        float4 xf0 = *(const float4*)(Xb + (size_t)r * CC + tx * 4);
        float4 xf1 = *(const float4*)(Xb + (size_t)r * CC + tx * 4 + 128);
        float4 o0, o1;
        o0.x = fmaxf((v0.x - mu) * rs * gg0.x + bb0.x, 0.f) + xf0.x;
        o0.y = fmaxf((v0.y - mu) * rs * gg0.y + bb0.y, 0.f) + xf0.y;
        o0.z = fmaxf((v0.z - mu) * rs * gg0.z + bb0.z, 0.f) + xf0.z;
        o0.w = fmaxf((v0.w - mu) * rs * gg0.w + bb0.w, 0.f) + xf0.w;
        o1.x = fmaxf((v1.x - mu) * rs * gg1.x + bb1.x, 0.f) + xf1.x;
        o1.y = fmaxf((v1.y - mu) * rs * gg1.y + bb1.y, 0.f) + xf1.y;
        o1.z = fmaxf((v1.z - mu) * rs * gg1.z + bb1.z, 0.f) + xf1.z;
        o1.w = fmaxf((v1.w - mu) * rs * gg1.w + bb1.w, 0.f) + xf1.w;
        *(float4*)(Ob + (size_t)r * CC + tx * 4) = o0;
        *(float4*)(Ob + (size_t)r * CC + tx * 4 + 128) = o1;
    }
}

// ---------------------------------------------------------------------------
extern "C" void kernel_launch(void* const* d_in, const int* in_sizes, int n_in,
                              void* d_out, int out_size) {
    const float* x_feat = (const float*)d_in[0];
    const float* z_feat = (const float*)d_in[1];
    const float* Wz     = (const float*)d_in[2];
    const float* bz     = (const float*)d_in[3];
    const float* Wx     = (const float*)d_in[4];
    const float* bx     = (const float*)d_in[5];
    const float* Wdyn   = (const float*)d_in[6];
    const float* bdyn   = (const float*)d_in[7];
    const float* gnorm  = (const float*)d_in[8];
    const float* bnorm  = (const float*)d_in[9];
    const float* Wp     = (const float*)d_in[10];
    const float* bp     = (const float*)d_in[11];
    const float* g_ln   = (const float*)d_in[12];
    const float* b_ln   = (const float*)d_in[13];
    float* out = (float*)d_out;

    float* zc = nullptr; float* xn = nullptr; float* kzp = nullptr;
    float* kxp = nullptr;
    cudaGetSymbolAddress((void**)&zc, g_zc);
    cudaGetSymbolAddress((void**)&xn, g_xn);
    cudaGetSymbolAddress((void**)&kzp, g_kzp);
    cudaGetSymbolAddress((void**)&kxp, g_kxp);

    cudaFuncSetAttribute(kD, cudaFuncAttributeMaxDynamicSharedMemorySize, 218368);
    cudaFuncSetAttribute(kF, cudaFuncAttributeMaxDynamicSharedMemorySize, 84992);

    // z path
    kLin<128><<<dim3(2, BB), 256, (128 * 17 + 1024) * 4>>>(z_feat, Wz, bz, zc, SZS);
    kOuter<128><<<dim3(2, 2, BB), 256, (2048 + 4096) * 4>>>(z_feat, zc, kzp);
    // x path
    kLin<256><<<dim3(4, BB), 256, (256 * 17 + 1024) * 4>>>(x_feat, Wx, bx, xn, SS);
    kOuter<512><<<dim3(2, 2, BB), 256, (2048 + 4096) * 4>>>(x_feat, xn, kxp);
    // attention core
    kD<<<BB, 512, 218368>>>(Wdyn, bdyn, gnorm, bnorm, Wp, bp);
    // epilogue
    kF<<<dim3(16, BB), 256, 84992>>>(x_feat, g_ln, b_ln, out);
}

// round 4
// speedup vs baseline: 1.6008x; 1.1682x over previous
#include <cuda_runtime.h>
#include <cuda_bf16.h>
#include <math.h>
#include <stdint.h>

#define BB   64
#define SS   1024
#define SZS  256
#define CC   256
#define NN   64
#define NKD  67
#define EPSV 1e-5f
#define PAD  257

// ------------------------- scratch (device globals) -------------------------
__device__ float g_xn [BB * SS * NN];    // x_n    [b][s][n]  16MB
__device__ float g_zc [BB * SZS * NN];   // z_core [b][s][n]   4MB
__device__ float g_kz [BB * CC * NN];    // kernels (z path)  [b][c][n]
__device__ float g_kx [BB * CC * NN];    // kernels_x raw     [b][c][n]
__device__ float g_kaT[BB * CC * NN];    // kernels_x post-LN [b][c][n]
__device__ float g_tem[BB * CC];

// ------------------------- helpers -------------------------
__device__ __forceinline__ uint32_t smem_u32(const void* p) {
    uint32_t a;
    asm("{ .reg .u64 tmp; cvta.to.shared.u64 tmp, %1; cvt.u32.u64 %0, tmp; }"
        : "=r"(a) : "l"(p));
    return a;
}
__device__ __forceinline__ void split_pack(float x0, float x1, uint32_t& h, uint32_t& l) {
    __nv_bfloat162 hp = __floats2bfloat162_rn(x0, x1);
    float r0 = x0 - __bfloat162float(hp.x);
    float r1 = x1 - __bfloat162float(hp.y);
    __nv_bfloat162 lp = __floats2bfloat162_rn(r0, r1);
    h = *reinterpret_cast<uint32_t*>(&hp);
    l = *reinterpret_cast<uint32_t*>(&lp);
}
__device__ __forceinline__ void ldm4(uint32_t addr, uint32_t* r) {
    asm volatile("ldmatrix.sync.aligned.m8n8.x4.shared.b16 {%0,%1,%2,%3}, [%4];"
                 : "=r"(r[0]), "=r"(r[1]), "=r"(r[2]), "=r"(r[3]) : "r"(addr));
}
__device__ __forceinline__ void mma16816(float* d, const uint32_t* a, const uint32_t* b) {
    asm volatile(
        "mma.sync.aligned.m16n8k16.row.col.f32.bf16.bf16.f32 "
        "{%0,%1,%2,%3}, {%4,%5,%6,%7}, {%8,%9}, {%0,%1,%2,%3};"
        : "+f"(d[0]), "+f"(d[1]), "+f"(d[2]), "+f"(d[3])
        : "r"(a[0]), "r"(a[1]), "r"(a[2]), "r"(a[3]), "r"(b[0]), "r"(b[1]));
}

// smem strides (bf16 elements): row stride 72 halves = 144B (conflict-free ldmatrix)
#define RS 144

// ---------------------------------------------------------------------------
// kG<TRA,TRB>: D[m,n] = sum_k A[m,k]*B[n,k] (+bias[n]), split-bf16 via mma.sync
// CTA tile 128(M) x 64(N), K chunk 64. 256 threads = 8 warps (4M x 2N).
// TRA: A[m,k] at A[k*lda + m]; else A[m*lda + k].  TRB likewise for B.
// grid(M/128, batch)
// ---------------------------------------------------------------------------
template<bool TRA, bool TRB>
__global__ void __launch_bounds__(256, 2) kG(
    const float* __restrict__ A, int lda, size_t strA,
    const float* __restrict__ B, int ldb, size_t strB,
    float* __restrict__ D, int ldd, size_t strD,
    int Ktot, const float* __restrict__ bias)
{
    extern __shared__ char sm[];
    char* sAh = sm;            // 128 * 144 = 18432
    char* sAl = sm + 18432;
    char* sBh = sm + 36864;    //  64 * 144 = 9216
    char* sBl = sm + 46080;
    float* sBias = (float*)(sm + 55296);
    uint32_t sb = smem_u32(sm);

    int t = threadIdx.x, warp = t >> 5, l = t & 31;
    int b = blockIdx.y;
    int m0 = blockIdx.x * 128;
    int wm = (warp & 3) * 32;
    int wn = (warp >> 2) * 32;

    const float* Ab = A + (size_t)b * strA;
    const float* Bb = B + (size_t)b * strB;

    if (bias && t < 64) sBias[t] = bias[t];

    float acc[2][4][4];
#pragma unroll
    for (int i = 0; i < 2; i++)
#pragma unroll
        for (int j = 0; j < 4; j++)
#pragma unroll
            for (int q = 0; q < 4; q++) acc[i][j][q] = 0.f;

    // ldmatrix per-lane base addresses
    uint32_t aRow = wm + (l & 15);
    uint32_t aOff = ((l >> 4) & 1) * 16;
    uint32_t aHi = sb + 0     + aRow * RS + aOff;
    uint32_t aLo = sb + 18432 + aRow * RS + aOff;
    uint32_t bRow = wn + (l & 7) + ((l & 16) ? 8 : 0);
    uint32_t bOff = (l & 8) ? 16 : 0;
    uint32_t bHi = sb + 36864 + bRow * RS + bOff;
    uint32_t bLo = sb + 46080 + bRow * RS + bOff;

    int nch = Ktot >> 6;
    for (int ch = 0; ch < nch; ch++) {
        int k0 = ch << 6;
        // ---- stage A (128 x 64) ----
        if (!TRA) {
            for (int idx = t; idx < 2048; idx += 256) {
                int r = idx >> 4, kq = idx & 15;
                float4 v = *(const float4*)(Ab + (size_t)(m0 + r) * lda + k0 + kq * 4);
                uint32_t h0, l0, h1, l1;
                split_pack(v.x, v.y, h0, l0);
                split_pack(v.z, v.w, h1, l1);
                *(uint2*)(sAh + r * RS + kq * 8) = make_uint2(h0, h1);
                *(uint2*)(sAl + r * RS + kq * 8) = make_uint2(l0, l1);
            }
        } else {
            for (int idx = t; idx < 2048; idx += 256) {
                int m = idx & 127, kg = idx >> 7;
                const float* p = Ab + (size_t)(k0 + kg * 4) * lda + m0 + m;
                float f0 = p[0], f1 = p[lda], f2 = p[2 * lda], f3 = p[3 * lda];
                uint32_t h0, l0, h1, l1;
                split_pack(f0, f1, h0, l0);
                split_pack(f2, f3, h1, l1);
                *(uint2*)(sAh + m * RS + kg * 8) = make_uint2(h0, h1);
                *(uint2*)(sAl + m * RS + kg * 8) = make_uint2(l0, l1);
            }
        }
        // ---- stage B (64 x 64) ----
        if (!TRB) {
            for (int idx = t; idx < 1024; idx += 256) {
                int r = idx >> 4, kq = idx & 15;
                float4 v = *(const float4*)(Bb + (size_t)r * ldb + k0 + kq * 4);
                uint32_t h0, l0, h1, l1;
                split_pack(v.x, v.y, h0, l0);
                split_pack(v.z, v.w, h1, l1);
                *(uint2*)(sBh + r * RS + kq * 8) = make_uint2(h0, h1);
                *(uint2*)(sBl + r * RS + kq * 8) = make_uint2(l0, l1);
            }
        } else {
            for (int idx = t; idx < 1024; idx += 256) {
                int n = idx & 63, kg = idx >> 6;
                const float* p = Bb + (size_t)(k0 + kg * 4) * ldb + n;
                float f0 = p[0], f1 = p[ldb], f2 = p[2 * ldb], f3 = p[3 * ldb];
                uint32_t h0, l0, h1, l1;
                split_pack(f0, f1, h0, l0);
                split_pack(f2, f3, h1, l1);
                *(uint2*)(sBh + n * RS + kg * 8) = make_uint2(h0, h1);
                *(uint2*)(sBl + n * RS + kg * 8) = make_uint2(l0, l1);
            }
        }
        __syncthreads();

#pragma unroll
        for (int ks = 0; ks < 4; ks++) {
            uint32_t ah[2][4], al[2][4], bh[2][4], bl[2][4];
#pragma unroll
            for (int mf = 0; mf < 2; mf++) {
                ldm4(aHi + mf * (16 * RS) + ks * 32, ah[mf]);
                ldm4(aLo + mf * (16 * RS) + ks * 32, al[mf]);
            }
#pragma unroll
            for (int p = 0; p < 2; p++) {
                ldm4(bHi + p * (16 * RS) + ks * 32, bh[p]);
                ldm4(bLo + p * (16 * RS) + ks * 32, bl[p]);
            }
#pragma unroll
            for (int mf = 0; mf < 2; mf++)
#pragma unroll
                for (int nf = 0; nf < 4; nf++) {
                    const uint32_t* bhp = &bh[nf >> 1][(nf & 1) * 2];
                    const uint32_t* blp = &bl[nf >> 1][(nf & 1) * 2];
                    mma16816(acc[mf][nf], ah[mf], bhp);
                    mma16816(acc[mf][nf], ah[mf], blp);
                    mma16816(acc[mf][nf], al[mf], bhp);
                }
        }
        __syncthreads();
    }

    // ---- epilogue ----
    float* Db = D + (size_t)b * strD;
#pragma unroll
    for (int mf = 0; mf < 2; mf++)
#pragma unroll
        for (int nf = 0; nf < 4; nf++) {
            int row = m0 + wm + mf * 16 + (l >> 2);
            int col = wn + nf * 8 + (l & 3) * 2;
            float b0 = bias ? sBias[col] : 0.f;
            float b1 = bias ? sBias[col + 1] : 0.f;
            *(float2*)(Db + (size_t)row * ldd + col) =
                make_float2(acc[mf][nf][0] + b0, acc[mf][nf][1] + b1);
            *(float2*)(Db + (size_t)(row + 8) * ldd + col) =
                make_float2(acc[mf][nf][2] + b0, acc[mf][nf][3] + b1);
        }
}

// ---------------------------------------------------------------------------
// kXC: x_corr = xn @ ka  fused with  out = x_feat + relu(LN(x_corr * tem))
// CTA tile 64(S) x 256(C), K = 64. 256 threads = 8 warps (2M x 4N).
// grid(SS/64, batch)
// ---------------------------------------------------------------------------
__global__ void __launch_bounds__(256) kXC(
    const float* __restrict__ xn, const float* __restrict__ kaT,
    const float* __restrict__ xf, const float* __restrict__ gl,
    const float* __restrict__ bl, float* __restrict__ out)
{
    extern __shared__ char sm[];
    char* sAh = sm;            // 64*144  = 9216
    char* sAl = sm + 9216;
    char* sBh = sm + 18432;    // 256*144 = 36864
    char* sBl = sm + 55296;
    float* sTem = (float*)(sm + 92160);
    float* sG   = (float*)(sm + 93184);
    float* sB2  = (float*)(sm + 94208);
    float* sSum = (float*)(sm + 95232);   // [64][4]
    float* sSq  = (float*)(sm + 96256);   // [64][4]
    float* sOut = (float*)sm;             // [64][260], overlaps A/B after MMA
    uint32_t sb = smem_u32(sm);

    int t = threadIdx.x, warp = t >> 5, l = t & 31;
    int b = blockIdx.y;
    int s0 = blockIdx.x * 64;
    int wm = (warp & 1) * 32;
    int wn = (warp >> 1) * 64;

    const float* Ab = xn + ((size_t)b * SS + s0) * NN;
    const float* Bb = kaT + (size_t)b * CC * NN;

    if (t < 256) { sTem[t] = g_tem[b * CC + t]; sG[t] = gl[t]; sB2[t] = bl[t]; }

    // stage A (64x64) and B (256x64), K-major, split bf16
    for (int idx = t; idx < 1024; idx += 256) {
        int r = idx >> 4, kq = idx & 15;
        float4 v = *(const float4*)(Ab + (size_t)r * NN + kq * 4);
        uint32_t h0, l0, h1, l1;
        split_pack(v.x, v.y, h0, l0);
        split_pack(v.z, v.w, h1, l1);
        *(uint2*)(sAh + r * RS + kq * 8) = make_uint2(h0, h1);
        *(uint2*)(sAl + r * RS + kq * 8) = make_uint2(l0, l1);
    }
    for (int idx = t; idx < 4096; idx += 256) {
        int r = idx >> 4, kq = idx & 15;
        float4 v = *(const float4*)(Bb + (size_t)r * NN + kq * 4);
        uint32_t h0, l0, h1, l1;
        split_pack(v.x, v.y, h0, l0);
        split_pack(v.z, v.w, h1, l1);
        *(uint2*)(sBh + r * RS + kq * 8) = make_uint2(h0, h1);
        *(uint2*)(sBl + r * RS + kq * 8) = make_uint2(l0, l1);
    }
    __syncthreads();

    uint32_t aRow = wm + (l & 15);
    uint32_t aOff = ((l >> 4) & 1) * 16;
    uint32_t aHi = sb + 0    + aRow * RS + aOff;
    uint32_t aLo = sb + 9216 + aRow * RS + aOff;
    uint32_t bRow = wn + (l & 7) + ((l & 16) ? 8 : 0);
    uint32_t bOff = (l & 8) ? 16 : 0;
    uint32_t bHi = sb + 18432 + bRow * RS + bOff;
    uint32_t bLo = sb + 55296 + bRow * RS + bOff;

    float acc[2][8][4];
#pragma unroll
    for (int i = 0; i < 2; i++)
#pragma unroll
        for (int j = 0; j < 8; j++)
#pragma unroll
            for (int q = 0; q < 4; q++) acc[i][j][q] = 0.f;

#pragma unroll
    for (int ks = 0; ks < 4; ks++) {
        uint32_t ah[2][4], al[2][4], bh[4][4], blr[4][4];
#pragma unroll
        for (int mf = 0; mf < 2; mf++) {
            ldm4(aHi + mf * (16 * RS) + ks * 32, ah[mf]);
            ldm4(aLo + mf * (16 * RS) + ks * 32, al[mf]);
        }
#pragma unroll
        for (int p = 0; p < 4; p++) {
            ldm4(bHi + p * (16 * RS) + ks * 32, bh[p]);
            ldm4(bLo + p * (16 * RS) + ks * 32, blr[p]);
        }
#pragma unroll
        for (int mf = 0; mf < 2; mf++)
#pragma unroll
            for (int nf = 0; nf < 8; nf++) {
                const uint32_t* bhp = &bh[nf >> 1][(nf & 1) * 2];
                const uint32_t* blp = &blr[nf >> 1][(nf & 1) * 2];
                mma16816(acc[mf][nf], ah[mf], bhp);
                mma16816(acc[mf][nf], ah[mf], blp);
                mma16816(acc[mf][nf], al[mf], bhp);
            }
    }

    // apply tem, per-row partial sums (rows split across 4 n-warps)
    float psum[2][2], psq[2][2];
#pragma unroll
    for (int mf = 0; mf < 2; mf++)
#pragma unroll
        for (int h = 0; h < 2; h++) { psum[mf][h] = 0.f; psq[mf][h] = 0.f; }
#pragma unroll
    for (int nf = 0; nf < 8; nf++) {
        int col = wn + nf * 8 + (l & 3) * 2;
        float t0 = sTem[col], t1 = sTem[col + 1];
#pragma unroll
        for (int mf = 0; mf < 2; mf++) {
            acc[mf][nf][0] *= t0; acc[mf][nf][1] *= t1;
            acc[mf][nf][2] *= t0; acc[mf][nf][3] *= t1;
            psum[mf][0] += acc[mf][nf][0] + acc[mf][nf][1];
            psq [mf][0] += acc[mf][nf][0] * acc[mf][nf][0] + acc[mf][nf][1] * acc[mf][nf][1];
            psum[mf][1] += acc[mf][nf][2] + acc[mf][nf][3];
            psq [mf][1] += acc[mf][nf][2] * acc[mf][nf][2] + acc[mf][nf][3] * acc[mf][nf][3];
        }
    }
#pragma unroll
    for (int mf = 0; mf < 2; mf++)
#pragma unroll
        for (int h = 0; h < 2; h++) {
#pragma unroll
            for (int off = 1; off <= 2; off <<= 1) {
                psum[mf][h] += __shfl_xor_sync(0xffffffffu, psum[mf][h], off);
                psq [mf][h] += __shfl_xor_sync(0xffffffffu, psq [mf][h], off);
            }
            if ((l & 3) == 0) {
                int r = wm + mf * 16 + h * 8 + (l >> 2);
                sSum[r * 4 + (warp >> 1)] = psum[mf][h];
                sSq [r * 4 + (warp >> 1)] = psq [mf][h];
            }
        }
    __syncthreads();

    // LN + relu into sOut
#pragma unroll
    for (int mf = 0; mf < 2; mf++)
#pragma unroll
        for (int h = 0; h < 2; h++) {
            int r = wm + mf * 16 + h * 8 + (l >> 2);
            float sum = sSum[r * 4] + sSum[r * 4 + 1] + sSum[r * 4 + 2] + sSum[r * 4 + 3];
            float sq  = sSq [r * 4] + sSq [r * 4 + 1] + sSq [r * 4 + 2] + sSq [r * 4 + 3];
            float mu = sum * (1.f / 256.f);
            float var = sq * (1.f / 256.f) - mu * mu;
            float rs = rsqrtf(var + EPSV);
#pragma unroll
            for (int nf = 0; nf < 8; nf++) {
                int col = wn + nf * 8 + (l & 3) * 2;
                float v0 = acc[mf][nf][h * 2], v1 = acc[mf][nf][h * 2 + 1];
                float o0 = fmaxf((v0 - mu) * rs * sG[col] + sB2[col], 0.f);
                float o1 = fmaxf((v1 - mu) * rs * sG[col + 1] + sB2[col + 1], 0.f);
                *(float2*)(sOut + r * 260 + col) = make_float2(o0, o1);
            }
        }
    __syncthreads();

    // coalesced: out = sOut + x_feat
    const float* Xb = xf + ((size_t)b * SS + s0) * CC;
    float* Ob = out + ((size_t)b * SS + s0) * CC;
    for (int idx = t; idx < 4096; idx += 256) {
        int r = idx >> 6, cq = idx & 63;
        float4 o = *(float4*)(sOut + r * 260 + cq * 4);
        float4 x = *(const float4*)(Xb + (size_t)r * CC + cq * 4);
        o.x += x.x; o.y += x.y; o.z += x.z; o.w += x.w;
        *(float4*)(Ob + (size_t)r * CC + cq * 4) = o;
    }
}

// ---------------------------------------------------------------------------
// kD: dysep conv atten + layernorm + proto + tem. grid(64), 512 threads.
// Consumes g_kz / g_kx [c][n]; writes g_kaT [c][n] and g_tem.
// ---------------------------------------------------------------------------
__global__ void kD(const float* __restrict__ Wdyn, const float* __restrict__ bdyn,
                   const float* __restrict__ gn, const float* __restrict__ bn,
                   const float* __restrict__ Wp, const float* __restrict__ bp) {
    extern __shared__ float smf[];
    float* sKz = smf;            // 64 x PAD (reused later as sP)
    float* sV  = smf + 16448;    // 64 x PAD
    float* sU  = smf + 32896;    // WdynT staging (68-stride), then depth 64x256
    float* sDy = smf + 50304;    // 64 x 68
    float* sPr = smf + 54656;    // 64
    int b = blockIdx.x, t = threadIdx.x;

    const float* kzb = g_kz + (size_t)b * CC * NN;
    const float* kxb = g_kx + (size_t)b * CC * NN;
    for (int idx = t; idx < CC * NN; idx += 512) {
        int c = idx >> 6, n = idx & 63;
        sKz[n * PAD + c] = kzb[idx];
        sV [n * PAD + c] = kxb[idx];
    }
    for (int idx = t; idx < CC * NKD; idx += 512) {
        int c = idx / NKD, jj = idx - c * NKD;
        sU[c * 68 + jj] = Wdyn[idx];
    }
    __syncthreads();

    // dy[m,jj] = kz[m,:] . Wdyn[:,jj] + bdyn[jj]
#pragma unroll
    for (int k = 0; k < 9; k++) {
        int o = t + k * 512;
        if (o < NN * NKD) {
            int m = o / NKD, jj = o - m * NKD;
            const float* kzr = sKz + m * PAD;
            const float* wc  = sU + jj;
            float a0 = 0.f, a1 = 0.f, a2 = 0.f, a3 = 0.f;
            for (int c = 0; c < CC; c += 4) {
                a0 += kzr[c + 0] * wc[(c + 0) * 68];
                a1 += kzr[c + 1] * wc[(c + 1) * 68];
                a2 += kzr[c + 2] * wc[(c + 2) * 68];
                a3 += kzr[c + 3] * wc[(c + 3) * 68];
            }
            sDy[m * 68 + jj] = bdyn[jj] + ((a0 + a1) + (a2 + a3));
        }
    }
    __syncthreads();

    // depth(m,c) = relu(w0*v[c-1] + w1*v[c] + w2*v[c+1])  (overwrites sU)
    for (int idx = t; idx < NN * CC; idx += 512) {
        int m = idx >> 8, c = idx & 255;
        float w0 = sDy[m * 68 + 0], w1 = sDy[m * 68 + 1], w2 = sDy[m * 68 + 2];
        float vm = (c > 0)   ? sV[m * PAD + c - 1] : 0.f;
        float v0 = sV[m * PAD + c];
        float vp = (c < 255) ? sV[m * PAD + c + 1] : 0.f;
        float d = w0 * vm + w1 * v0 + w2 * vp;
        sU[idx] = d > 0.f ? d : 0.f;
    }
    __syncthreads();

    // point(n,c) = sum_m wp[n,m]*depth[m,c]; layernorm over c
    int tx = t & 31, ty = t >> 5;
    float4 acc[4][2];
#pragma unroll
    for (int i = 0; i < 4; i++) {
        acc[i][0] = make_float4(0.f, 0.f, 0.f, 0.f);
        acc[i][1] = make_float4(0.f, 0.f, 0.f, 0.f);
    }
#pragma unroll 2
    for (int m = 0; m < NN; m++) {
        float4 d0 = *(const float4*)(sU + m * CC + tx * 4);
        float4 d1 = *(const float4*)(sU + m * CC + tx * 4 + 128);
#pragma unroll
        for (int i = 0; i < 4; i++) {
            float w = sDy[(ty * 4 + i) * 68 + 3 + m];
            acc[i][0].x += w * d0.x; acc[i][0].y += w * d0.y;
            acc[i][0].z += w * d0.z; acc[i][0].w += w * d0.w;
            acc[i][1].x += w * d1.x; acc[i][1].y += w * d1.y;
            acc[i][1].z += w * d1.z; acc[i][1].w += w * d1.w;
        }
    }
    __syncthreads();

    float* sP = sKz;
    float4 gg0 = *(const float4*)(gn + tx * 4);
    float4 gg1 = *(const float4*)(gn + tx * 4 + 128);
    float4 bb0 = *(const float4*)(bn + tx * 4);
    float4 bb1 = *(const float4*)(bn + tx * 4 + 128);
#pragma unroll
    for (int i = 0; i < 4; i++) {
        int n = ty * 4 + i;
        float4 v0 = acc[i][0], v1 = acc[i][1];
        float sum = v0.x + v0.y + v0.z + v0.w + v1.x + v1.y + v1.z + v1.w;
        float sq  = v0.x * v0.x + v0.y * v0.y + v0.z * v0.z + v0.w * v0.w
                  + v1.x * v1.x + v1.y * v1.y + v1.z * v1.z + v1.w * v1.w;
#pragma unroll
        for (int off = 16; off >= 1; off >>= 1) {
            sum += __shfl_xor_sync(0xffffffffu, sum, off);
            sq  += __shfl_xor_sync(0xffffffffu, sq, off);
        }
        float mu = sum * (1.f / 256.f);
        float var = sq * (1.f / 256.f) - mu * mu;
        float rs = rsqrtf(var + EPSV);
        float4 o0, o1;
        o0.x = (v0.x - mu) * rs * gg0.x + bb0.x;
        o0.y = (v0.y - mu) * rs * gg0.y + bb0.y;
        o0.z = (v0.z - mu) * rs * gg0.z + bb0.z;
        o0.w = (v0.w - mu) * rs * gg0.w + bb0.w;
        o1.x = (v1.x - mu) * rs * gg1.x + bb1.x;
        o1.y = (v1.y - mu) * rs * gg1.y + bb1.y;
        o1.z = (v1.z - mu) * rs * gg1.z + bb1.z;
        o1.w = (v1.w - mu) * rs * gg1.w + bb1.w;
        *(float4*)(sP + n * CC + tx * 4) = o0;
        *(float4*)(sP + n * CC + tx * 4 + 128) = o1;
    }
    __syncthreads();

    // write kaT [c][n]
    float* katb = g_kaT + (size_t)b * CC * NN;
    for (int idx = t; idx < NN * CC; idx += 512) {
        int n = idx >> 8, c = idx & 255;
        katb[c * NN + n] = sP[idx];
    }

    // proto[n] = ka[n,:] . Wp + bp
    if (t < NN) {
        float a0 = 0.f, a1 = 0.f, a2 = 0.f, a3 = 0.f;
        for (int c = 0; c < CC; c += 4) {
            float4 p = *(const float4*)(sP + t * CC + c);
            float4 w = *(const float4*)(Wp + c);
            a0 += p.x * w.x; a1 += p.y * w.y; a2 += p.z * w.z; a3 += p.w * w.w;
        }
        sPr[t] = bp[0] + ((a0 + a1) + (a2 + a3));
    }
    __syncthreads();

    // tem[c] = sigmoid(sum_n proto[n] * ka[n,c])
    if (t < CC) {
        float a0 = 0.f, a1 = 0.f, a2 = 0.f, a3 = 0.f;
        for (int n = 0; n < NN; n += 4) {
            a0 += sPr[n + 0] * sP[(n + 0) * CC + t];
            a1 += sPr[n + 1] * sP[(n + 1) * CC + t];
            a2 += sPr[n + 2] * sP[(n + 2) * CC + t];
            a3 += sPr[n + 3] * sP[(n + 3) * CC + t];
        }
        float s = (a0 + a1) + (a2 + a3);
        g_tem[b * CC + t] = 1.f / (1.f + expf(-s));
    }
}

// ---------------------------------------------------------------------------
extern "C" void kernel_launch(void* const* d_in, const int* in_sizes, int n_in,
                              void* d_out, int out_size) {
    const float* x_feat = (const float*)d_in[0];
    const float* z_feat = (const float*)d_in[1];
    const float* Wz     = (const float*)d_in[2];
    const float* bz     = (const float*)d_in[3];
    const float* Wx     = (const float*)d_in[4];
    const float* bx     = (const float*)d_in[5];
    const float* Wdyn   = (const float*)d_in[6];
    const float* bdyn   = (const float*)d_in[7];
    const float* gnorm  = (const float*)d_in[8];
    const float* bnorm  = (const float*)d_in[9];
    const float* Wp     = (const float*)d_in[10];
    const float* bp     = (const float*)d_in[11];
    const float* g_ln   = (const float*)d_in[12];
    const float* b_ln   = (const float*)d_in[13];
    float* out = (float*)d_out;

    float *xn, *zc, *kz, *kx, *kaT;
    cudaGetSymbolAddress((void**)&xn,  g_xn);
    cudaGetSymbolAddress((void**)&zc,  g_zc);
    cudaGetSymbolAddress((void**)&kz,  g_kz);
    cudaGetSymbolAddress((void**)&kx,  g_kx);
    cudaGetSymbolAddress((void**)&kaT, g_kaT);

    cudaFuncSetAttribute(kG<false, true>, cudaFuncAttributeMaxDynamicSharedMemorySize, 56576);
    cudaFuncSetAttribute(kG<true, true>,  cudaFuncAttributeMaxDynamicSharedMemorySize, 56576);
    cudaFuncSetAttribute(kXC, cudaFuncAttributeMaxDynamicSharedMemorySize, 97280);
    cudaFuncSetAttribute(kD,  cudaFuncAttributeMaxDynamicSharedMemorySize, 218880);

    // x_n = X @ Wx + bx       (A: [s][c] normal, B: Wx [c][n] -> transposed)
    kG<false, true><<<dim3(8, BB), 256, 56576>>>(
        x_feat, CC, (size_t)SS * CC, Wx, NN, 0,
        xn, NN, (size_t)SS * NN, CC, bx);
    // z_core = Z @ Wz + bz
    kG<false, true><<<dim3(2, BB), 256, 56576>>>(
        z_feat, CC, (size_t)SZS * CC, Wz, NN, 0,
        zc, NN, (size_t)SZS * NN, CC, bz);
    // kx[c,n] = sum_s X[s,c] * xn[s,n]   (both transposed-on-load)
    kG<true, true><<<dim3(2, BB), 256, 56576>>>(
        x_feat, CC, (size_t)SS * CC, xn, NN, (size_t)SS * NN,
        kx, NN, (size_t)CC * NN, SS, nullptr);
    // kz[c,n] = sum_s Z[s,c] * zc[s,n]
    kG<true, true><<<dim3(2, BB), 256, 56576>>>(
        z_feat, CC, (size_t)SZS * CC, zc, NN, (size_t)SZS * NN,
        kz, NN, (size_t)CC * NN, SZS, nullptr);
    // attention core
    kD<<<BB, 512, 218880>>>(Wdyn, bdyn, gnorm, bnorm, Wp, bp);
    // fused x_corr + epilogue
    kXC<<<dim3(16, BB), 256, 97280>>>(xn, kaT, x_feat, g_ln, b_ln, out);
}

// round 7
// speedup vs baseline: 1.8701x; 1.1683x over previous
#include <cuda_runtime.h>
#include <cuda_bf16.h>
#include <math.h>
#include <stdint.h>

#define BB   64
#define SS   1024
#define SZS  256
#define CC   256
#define NN   64
#define NKD  67
#define EPSV 1e-5f
#define PAD  257

// ------------------------- scratch (device globals) -------------------------
__device__ float g_xn [BB * SS * NN];       // x_n    [b][s][n]  16MB
__device__ float g_zc [BB * SZS * NN];      // z_core [b][s][n]   4MB
__device__ float g_kz [BB * CC * NN];       // kernels (z path)  [b][c][n]
__device__ float g_kxp[2 * BB * CC * NN];   // kernels_x partials [b][c][n]
__device__ float g_kaT[BB * CC * NN];       // kernels_x post-LN [b][c][n]
__device__ float g_tem[BB * CC];

// ------------------------- helpers -------------------------
__device__ __forceinline__ uint32_t smem_u32(const void* p) {
    uint32_t a;
    asm("{ .reg .u64 tmp; cvta.to.shared.u64 tmp, %1; cvt.u32.u64 %0, tmp; }"
        : "=r"(a) : "l"(p));
    return a;
}
__device__ __forceinline__ void split_pack(float x0, float x1, uint32_t& h, uint32_t& l) {
    __nv_bfloat162 hp = __floats2bfloat162_rn(x0, x1);
    float r0 = x0 - __bfloat162float(hp.x);
    float r1 = x1 - __bfloat162float(hp.y);
    __nv_bfloat162 lp = __floats2bfloat162_rn(r0, r1);
    h = *reinterpret_cast<uint32_t*>(&hp);
    l = *reinterpret_cast<uint32_t*>(&lp);
}
__device__ __forceinline__ void ldm4(uint32_t addr, uint32_t* r) {
    asm volatile("ldmatrix.sync.aligned.m8n8.x4.shared.b16 {%0,%1,%2,%3}, [%4];"
                 : "=r"(r[0]), "=r"(r[1]), "=r"(r[2]), "=r"(r[3]) : "r"(addr));
}
__device__ __forceinline__ void mma16816(float* d, const uint32_t* a, const uint32_t* b) {
    asm volatile(
        "mma.sync.aligned.m16n8k16.row.col.f32.bf16.bf16.f32 "
        "{%0,%1,%2,%3}, {%4,%5,%6,%7}, {%8,%9}, {%0,%1,%2,%3};"
        : "+f"(d[0]), "+f"(d[1]), "+f"(d[2]), "+f"(d[3])
        : "r"(a[0]), "r"(a[1]), "r"(a[2]), "r"(a[3]), "r"(b[0]), "r"(b[1]));
}
__device__ __forceinline__ void cp16(uint32_t dst, const void* src) {
    asm volatile("cp.async.cg.shared.global [%0], [%1], 16;" :: "r"(dst), "l"(src));
}
__device__ __forceinline__ void cpcommit() {
    asm volatile("cp.async.commit_group;" ::: "memory");
}
template<int N> __device__ __forceinline__ void cpwait() {
    asm volatile("cp.async.wait_group %0;" :: "n"(N) : "memory");
}

// bf16 smem row stride (bytes): 72 halves = 144B
#define RS 144
// raw staging strides (floats)
#define RAWA_F  68    // non-TRA: 128 rows x 64+pad
#define RAWAT_F 132   // TRA: 64 k-rows x 128+pad
#define RAWB_F  68    // 64 rows x 64+pad
#define RAW_A_BYTES 34816
#define RAW_B_BYTES 17408
// smem layout offsets (bytes)
#define OFF_AH   0
#define OFF_AL   18432
#define OFF_BH   36864
#define OFF_BL   46080
#define OFF_RAWA 55296
#define OFF_RAWB 124928
#define OFF_BIAS 159744
#define SMEM_KG  160000

// ---------------------------------------------------------------------------
// pipelined chunk loaders: gmem -> raw fp32 smem via cp.async (all coalesced)
// ---------------------------------------------------------------------------
template<bool TRA, bool TRB>
__device__ __forceinline__ void kg_load(const float* Ab, int lda, const float* Bb,
                                        int ldb, int m0, int k0, char* sm, int stg, int t) {
    uint32_t ra = smem_u32(sm + OFF_RAWA + stg * RAW_A_BYTES);
    uint32_t rb = smem_u32(sm + OFF_RAWB + stg * RAW_B_BYTES);
    if (!TRA) {
#pragma unroll
        for (int i = 0; i < 8; i++) {
            int u = t + i * 256;
            int r = u >> 4, kq = u & 15;
            cp16(ra + r * (RAWA_F * 4) + kq * 16,
                 Ab + (size_t)(m0 + r) * lda + k0 + kq * 4);
        }
    } else {
#pragma unroll
        for (int i = 0; i < 8; i++) {
            int u = t + i * 256;
            int r = u >> 5, mq = u & 31;
            cp16(ra + r * (RAWAT_F * 4) + mq * 16,
                 Ab + (size_t)(k0 + r) * lda + m0 + mq * 4);
        }
    }
    if (!TRB) {
#pragma unroll
        for (int i = 0; i < 4; i++) {
            int u = t + i * 256;
            int r = u >> 4, kq = u & 15;
            cp16(rb + r * (RAWB_F * 4) + kq * 16,
                 Bb + (size_t)r * ldb + k0 + kq * 4);
        }
    } else {
#pragma unroll
        for (int i = 0; i < 4; i++) {
            int u = t + i * 256;
            int r = u >> 4, nq = u & 15;
            cp16(rb + r * (RAWB_F * 4) + nq * 16,
                 Bb + (size_t)(k0 + r) * ldb + nq * 4);
        }
    }
}

// convert raw fp32 stage -> split-bf16 operand buffers (transpose happens here)
template<bool TRA, bool TRB>
__device__ __forceinline__ void kg_convert(char* sm, int stg, int t) {
    float* rawA = (float*)(sm + OFF_RAWA + stg * RAW_A_BYTES);
    float* rawB = (float*)(sm + OFF_RAWB + stg * RAW_B_BYTES);
    char* sAh = sm + OFF_AH; char* sAl = sm + OFF_AL;
    char* sBh = sm + OFF_BH; char* sBl = sm + OFF_BL;
    if (!TRA) {
#pragma unroll
        for (int i = 0; i < 8; i++) {
            int u = t + i * 256;
            int r = u >> 4, kq = u & 15;
            float4 v = *(const float4*)(rawA + r * RAWA_F + kq * 4);
            uint32_t h0, l0, h1, l1;
            split_pack(v.x, v.y, h0, l0);
            split_pack(v.z, v.w, h1, l1);
            *(uint2*)(sAh + r * RS + kq * 8) = make_uint2(h0, h1);
            *(uint2*)(sAl + r * RS + kq * 8) = make_uint2(l0, l1);
        }
    } else {
#pragma unroll
        for (int i = 0; i < 8; i++) {
            int u = t + i * 256;
            int m = u & 127, kg = u >> 7;  // kg 0..15
            float f0 = rawA[(kg * 4 + 0) * RAWAT_F + m];
            float f1 = rawA[(kg * 4 + 1) * RAWAT_F + m];
            float f2 = rawA[(kg * 4 + 2) * RAWAT_F + m];
            float f3 = rawA[(kg * 4 + 3) * RAWAT_F + m];
            uint32_t h0, l0, h1, l1;
            split_pack(f0, f1, h0, l0);
            split_pack(f2, f3, h1, l1);
            *(uint2*)(sAh + m * RS + kg * 8) = make_uint2(h0, h1);
            *(uint2*)(sAl + m * RS + kg * 8) = make_uint2(l0, l1);
        }
    }
    if (!TRB) {
#pragma unroll
        for (int i = 0; i < 4; i++) {
            int u = t + i * 256;
            int r = u >> 4, kq = u & 15;
            float4 v = *(const float4*)(rawB + r * RAWB_F + kq * 4);
            uint32_t h0, l0, h1, l1;
            split_pack(v.x, v.y, h0, l0);
            split_pack(v.z, v.w, h1, l1);
            *(uint2*)(sBh + r * RS + kq * 8) = make_uint2(h0, h1);
            *(uint2*)(sBl + r * RS + kq * 8) = make_uint2(l0, l1);
        }
    } else {
#pragma unroll
        for (int i = 0; i < 4; i++) {
            int u = t + i * 256;
            int n = u & 63, kg = u >> 6;  // kg 0..15
            float f0 = rawB[(kg * 4 + 0) * RAWB_F + n];
            float f1 = rawB[(kg * 4 + 1) * RAWB_F + n];
            float f2 = rawB[(kg * 4 + 2) * RAWB_F + n];
            float f3 = rawB[(kg * 4 + 3) * RAWB_F + n];
            uint32_t h0, l0, h1, l1;
            split_pack(f0, f1, h0, l0);
            split_pack(f2, f3, h1, l1);
            *(uint2*)(sBh + n * RS + kg * 8) = make_uint2(h0, h1);
            *(uint2*)(sBl + n * RS + kg * 8) = make_uint2(l0, l1);
        }
    }
}

// ---------------------------------------------------------------------------
// gemm_tile<TRA,TRB>: D[m0..m0+127, 0..63] += sum_k A*B (+bias), pipelined.
// 256 threads = 8 warps (4M x 2N).
// ---------------------------------------------------------------------------
template<bool TRA, bool TRB>
__device__ void gemm_tile(const float* __restrict__ Ab, int lda,
                          const float* __restrict__ Bb, int ldb,
                          float* __restrict__ Db, int ldd,
                          int m0, int Ktot, const float* __restrict__ bias,
                          char* sm) {
    uint32_t sb = smem_u32(sm);
    int t = threadIdx.x, warp = t >> 5, l = t & 31;
    int wm = (warp & 3) * 32;
    int wn = (warp >> 2) * 32;
    float* sBias = (float*)(sm + OFF_BIAS);
    if (bias && t < 64) sBias[t] = bias[t];

    float acc[2][4][4];
#pragma unroll
    for (int i = 0; i < 2; i++)
#pragma unroll
        for (int j = 0; j < 4; j++)
#pragma unroll
            for (int q = 0; q < 4; q++) acc[i][j][q] = 0.f;

    uint32_t aRow = wm + (l & 15);
    uint32_t aOff = ((l >> 4) & 1) * 16;
    uint32_t aHi = sb + OFF_AH + aRow * RS + aOff;
    uint32_t aLo = sb + OFF_AL + aRow * RS + aOff;
    uint32_t bRow = wn + (l & 7) + ((l & 16) ? 8 : 0);
    uint32_t bOff = (l & 8) ? 16 : 0;
    uint32_t bHi = sb + OFF_BH + bRow * RS + bOff;
    uint32_t bLo = sb + OFF_BL + bRow * RS + bOff;

    int nch = Ktot >> 6;
    kg_load<TRA, TRB>(Ab, lda, Bb, ldb, m0, 0, sm, 0, t);
    cpcommit();

    for (int ch = 0; ch < nch; ch++) {
        if (ch + 1 < nch) {
            kg_load<TRA, TRB>(Ab, lda, Bb, ldb, m0, (ch + 1) << 6, sm, (ch + 1) & 1, t);
            cpcommit();
            cpwait<1>();
        } else {
            cpwait<0>();
        }
        __syncthreads();
        kg_convert<TRA, TRB>(sm, ch & 1, t);
        __syncthreads();
#pragma unroll
        for (int ks = 0; ks < 4; ks++) {
            uint32_t ah[2][4], al[2][4], bh[2][4], bl[2][4];
#pragma unroll
            for (int mf = 0; mf < 2; mf++) {
                ldm4(aHi + mf * (16 * RS) + ks * 32, ah[mf]);
                ldm4(aLo + mf * (16 * RS) + ks * 32, al[mf]);
            }
#pragma unroll
            for (int p = 0; p < 2; p++) {
                ldm4(bHi + p * (16 * RS) + ks * 32, bh[p]);
                ldm4(bLo + p * (16 * RS) + ks * 32, bl[p]);
            }
#pragma unroll
            for (int mf = 0; mf < 2; mf++)
#pragma unroll
                for (int nf = 0; nf < 4; nf++) {
                    const uint32_t* bhp = &bh[nf >> 1][(nf & 1) * 2];
                    const uint32_t* blp = &bl[nf >> 1][(nf & 1) * 2];
                    mma16816(acc[mf][nf], ah[mf], bhp);
                    mma16816(acc[mf][nf], ah[mf], blp);
                    mma16816(acc[mf][nf], al[mf], bhp);
                }
        }
        __syncthreads();
    }

#pragma unroll
    for (int mf = 0; mf < 2; mf++)
#pragma unroll
        for (int nf = 0; nf < 4; nf++) {
            int row = m0 + wm + mf * 16 + (l >> 2);
            int col = wn + nf * 8 + (l & 3) * 2;
            float b0 = bias ? sBias[col] : 0.f;
            float b1 = bias ? sBias[col + 1] : 0.f;
            *(float2*)(Db + (size_t)row * ldd + col) =
                make_float2(acc[mf][nf][0] + b0, acc[mf][nf][1] + b1);
            *(float2*)(Db + (size_t)(row + 8) * ldd + col) =
                make_float2(acc[mf][nf][2] + b0, acc[mf][nf][3] + b1);
        }
}

// ---------------------------------------------------------------------------
// merged launch 1: x_n = X@Wx+bx (512 tiles) and z_core = Z@Wz+bz (128 tiles)
// ---------------------------------------------------------------------------
__global__ void __launch_bounds__(256) kLinAll(
    const float* __restrict__ xf, const float* __restrict__ Wx, const float* __restrict__ bx,
    const float* __restrict__ zf, const float* __restrict__ Wz, const float* __restrict__ bz,
    float* __restrict__ xn, float* __restrict__ zcp) {
    extern __shared__ char sm[];
    int bid = blockIdx.x;
    if (bid < 512) {
        int b = bid >> 3, m0 = (bid & 7) * 128;
        gemm_tile<false, true>(xf + (size_t)b * SS * CC, CC, Wx, NN,
                               xn + (size_t)b * SS * NN, NN, m0, CC, bx, sm);
    } else {
        int zi = bid - 512;
        int b = zi >> 1, m0 = (zi & 1) * 128;
        gemm_tile<false, true>(zf + (size_t)b * SZS * CC, CC, Wz, NN,
                               zcp + (size_t)b * SZS * NN, NN, m0, CC, bz, sm);
    }
}

// ---------------------------------------------------------------------------
// merged launch 2: kx partials (s-split x2, 256 tiles) and kz (128 tiles)
// ---------------------------------------------------------------------------
__global__ void __launch_bounds__(256) kOuterAll(
    const float* __restrict__ xf, const float* __restrict__ zf,
    const float* __restrict__ xn, const float* __restrict__ zcp,
    float* __restrict__ kxp, float* __restrict__ kz) {
    extern __shared__ char sm[];
    int bid = blockIdx.x;
    if (bid < 256) {
        int b = bid >> 2, q = bid & 3, tile = q & 1, half = q >> 1;
        gemm_tile<true, true>(
            xf + (size_t)b * SS * CC + (size_t)half * 512 * CC, CC,
            xn + (size_t)b * SS * NN + (size_t)half * 512 * NN, NN,
            kxp + (size_t)half * BB * CC * NN + (size_t)b * CC * NN, NN,
            tile * 128, 512, nullptr, sm);
    } else {
        int zi = bid - 256;
        int b = zi >> 1, tile = zi & 1;
        gemm_tile<true, true>(
            zf + (size_t)b * SZS * CC, CC, zcp + (size_t)b * SZS * NN, NN,
            kz + (size_t)b * CC * NN, NN, tile * 128, SZS, nullptr, sm);
    }
}

// ---------------------------------------------------------------------------
// kD: dysep conv atten + layernorm + proto + tem. grid(64), 512 threads.
// ---------------------------------------------------------------------------
__global__ void kD(const float* __restrict__ Wdyn, const float* __restrict__ bdyn,
                   const float* __restrict__ gn, const float* __restrict__ bn,
                   const float* __restrict__ Wp, const float* __restrict__ bp) {
    extern __shared__ float smf[];
    float* sKz = smf;            // 64 x PAD (reused later as sP)
    float* sV  = smf + 16448;    // 64 x PAD
    float* sU  = smf + 32896;    // WdynT staging (68-stride), then depth 64x256
    float* sDy = smf + 50304;    // 64 x 68
    float* sPr = smf + 54656;    // 64
    int b = blockIdx.x, t = threadIdx.x;

    const float* kzb = g_kz + (size_t)b * CC * NN;
    const float* kx0 = g_kxp + (size_t)b * CC * NN;
    const float* kx1 = g_kxp + (size_t)BB * CC * NN + (size_t)b * CC * NN;
    for (int idx = t; idx < CC * NN; idx += 512) {
        int c = idx >> 6, n = idx & 63;
        sKz[n * PAD + c] = kzb[idx];
        sV [n * PAD + c] = kx0[idx] + kx1[idx];
    }
    for (int idx = t; idx < CC * NKD; idx += 512) {
        int c = idx / NKD, jj = idx - c * NKD;
        sU[c * 68 + jj] = Wdyn[idx];
    }
    __syncthreads();

    // dy[m,jj] = kz[m,:] . Wdyn[:,jj] + bdyn[jj]
#pragma unroll
    for (int k = 0; k < 9; k++) {
        int o = t + k * 512;
        if (o < NN * NKD) {
            int m = o / NKD, jj = o - m * NKD;
            const float* kzr = sKz + m * PAD;
            const float* wc  = sU + jj;
            float a0 = 0.f, a1 = 0.f, a2 = 0.f, a3 = 0.f;
            for (int c = 0; c < CC; c += 4) {
                a0 += kzr[c + 0] * wc[(c + 0) * 68];
                a1 += kzr[c + 1] * wc[(c + 1) * 68];
                a2 += kzr[c + 2] * wc[(c + 2) * 68];
                a3 += kzr[c + 3] * wc[(c + 3) * 68];
            }
            sDy[m * 68 + jj] = bdyn[jj] + ((a0 + a1) + (a2 + a3));
        }
    }
    __syncthreads();

    // depth(m,c) = relu(w0*v[c-1] + w1*v[c] + w2*v[c+1])  (overwrites sU)
    for (int idx = t; idx < NN * CC; idx += 512) {
        int m = idx >> 8, c = idx & 255;
        float w0 = sDy[m * 68 + 0], w1 = sDy[m * 68 + 1], w2 = sDy[m * 68 + 2];
        float vm = (c > 0)   ? sV[m * PAD + c - 1] : 0.f;
        float v0 = sV[m * PAD + c];
        float vp = (c < 255) ? sV[m * PAD + c + 1] : 0.f;
        float d = w0 * vm + w1 * v0 + w2 * vp;
        sU[idx] = d > 0.f ? d : 0.f;
    }
    __syncthreads();

    // point(n,c) = sum_m wp[n,m]*depth[m,c]; layernorm over c
    int tx = t & 31, ty = t >> 5;
    float4 acc[4][2];
#pragma unroll
    for (int i = 0; i < 4; i++) {
        acc[i][0] = make_float4(0.f, 0.f, 0.f, 0.f);
        acc[i][1] = make_float4(0.f, 0.f, 0.f, 0.f);
    }
#pragma unroll 2
    for (int m = 0; m < NN; m++) {
        float4 d0 = *(const float4*)(sU + m * CC + tx * 4);
        float4 d1 = *(const float4*)(sU + m * CC + tx * 4 + 128);
#pragma unroll
        for (int i = 0; i < 4; i++) {
            float w = sDy[(ty * 4 + i) * 68 + 3 + m];
            acc[i][0].x += w * d0.x; acc[i][0].y += w * d0.y;
            acc[i][0].z += w * d0.z; acc[i][0].w += w * d0.w;
            acc[i][1].x += w * d1.x; acc[i][1].y += w * d1.y;
            acc[i][1].z += w * d1.z; acc[i][1].w += w * d1.w;
        }
    }
    __syncthreads();

    float* sP = sKz;
    float4 gg0 = *(const float4*)(gn + tx * 4);
    float4 gg1 = *(const float4*)(gn + tx * 4 + 128);
    float4 bb0 = *(const float4*)(bn + tx * 4);
    float4 bb1 = *(const float4*)(bn + tx * 4 + 128);
#pragma unroll
    for (int i = 0; i < 4; i++) {
        int n = ty * 4 + i;
        float4 v0 = acc[i][0], v1 = acc[i][1];
        float sum = v0.x + v0.y + v0.z + v0.w + v1.x + v1.y + v1.z + v1.w;
        float sq  = v0.x * v0.x + v0.y * v0.y + v0.z * v0.z + v0.w * v0.w
                  + v1.x * v1.x + v1.y * v1.y + v1.z * v1.z + v1.w * v1.w;
#pragma unroll
        for (int off = 16; off >= 1; off >>= 1) {
            sum += __shfl_xor_sync(0xffffffffu, sum, off);
            sq  += __shfl_xor_sync(0xffffffffu, sq, off);
        }
        float mu = sum * (1.f / 256.f);
        float var = sq * (1.f / 256.f) - mu * mu;
        float rs = rsqrtf(var + EPSV);
        float4 o0, o1;
        o0.x = (v0.x - mu) * rs * gg0.x + bb0.x;
        o0.y = (v0.y - mu) * rs * gg0.y + bb0.y;
        o0.z = (v0.z - mu) * rs * gg0.z + bb0.z;
        o0.w = (v0.w - mu) * rs * gg0.w + bb0.w;
        o1.x = (v1.x - mu) * rs * gg1.x + bb1.x;
        o1.y = (v1.y - mu) * rs * gg1.y + bb1.y;
        o1.z = (v1.z - mu) * rs * gg1.z + bb1.z;
        o1.w = (v1.w - mu) * rs * gg1.w + bb1.w;
        *(float4*)(sP + n * CC + tx * 4) = o0;
        *(float4*)(sP + n * CC + tx * 4 + 128) = o1;
    }
    __syncthreads();

    // write kaT [c][n]
    float* katb = g_kaT + (size_t)b * CC * NN;
    for (int idx = t; idx < NN * CC; idx += 512) {
        int n = idx >> 8, c = idx & 255;
        katb[c * NN + n] = sP[idx];
    }

    // proto[n] = ka[n,:] . Wp + bp
    if (t < NN) {
        float a0 = 0.f, a1 = 0.f, a2 = 0.f, a3 = 0.f;
        for (int c = 0; c < CC; c += 4) {
            float4 p = *(const float4*)(sP + t * CC + c);
            float4 w = *(const float4*)(Wp + c);
            a0 += p.x * w.x; a1 += p.y * w.y; a2 += p.z * w.z; a3 += p.w * w.w;
        }
        sPr[t] = bp[0] + ((a0 + a1) + (a2 + a3));
    }
    __syncthreads();

    // tem[c] = sigmoid(sum_n proto[n] * ka[n,c])
    if (t < CC) {
        float a0 = 0.f, a1 = 0.f, a2 = 0.f, a3 = 0.f;
        for (int n = 0; n < NN; n += 4) {
            a0 += sPr[n + 0] * sP[(n + 0) * CC + t];
            a1 += sPr[n + 1] * sP[(n + 1) * CC + t];
            a2 += sPr[n + 2] * sP[(n + 2) * CC + t];
            a3 += sPr[n + 3] * sP[(n + 3) * CC + t];
        }
        float s = (a0 + a1) + (a2 + a3);
        g_tem[b * CC + t] = 1.f / (1.f + expf(-s));
    }
}

// ---------------------------------------------------------------------------
// kXC: x_corr = xn @ ka  fused with  out = x_feat + relu(LN(x_corr * tem))
// CTA tile 64(S) x 256(C), K = 64. 256 threads = 8 warps (2M x 4N).
// ---------------------------------------------------------------------------
__global__ void __launch_bounds__(256, 2) kXC(
    const float* __restrict__ xn, const float* __restrict__ kaT,
    const float* __restrict__ xf, const float* __restrict__ gl,
    const float* __restrict__ bl, float* __restrict__ out)
{
    extern __shared__ char sm[];
    char* sAh = sm;            // 64*144  = 9216
    char* sAl = sm + 9216;
    char* sBh = sm + 18432;    // 256*144 = 36864
    char* sBl = sm + 55296;
    float* sTem = (float*)(sm + 92160);
    float* sG   = (float*)(sm + 93184);
    float* sB2  = (float*)(sm + 94208);
    float* sSum = (float*)(sm + 95232);   // [64][4]
    float* sSq  = (float*)(sm + 96256);   // [64][4]
    float* sOut = (float*)sm;             // [64][260], overlaps A/B after MMA
    uint32_t sb = smem_u32(sm);

    int t = threadIdx.x, warp = t >> 5, l = t & 31;
    int b = blockIdx.y;
    int s0 = blockIdx.x * 64;
    int wm = (warp & 1) * 32;
    int wn = (warp >> 1) * 64;

    const float* Ab = xn + ((size_t)b * SS + s0) * NN;
    const float* Bb = kaT + (size_t)b * CC * NN;

    if (t < 256) { sTem[t] = g_tem[b * CC + t]; sG[t] = gl[t]; sB2[t] = bl[t]; }

    for (int idx = t; idx < 1024; idx += 256) {
        int r = idx >> 4, kq = idx & 15;
        float4 v = *(const float4*)(Ab + (size_t)r * NN + kq * 4);
        uint32_t h0, l0, h1, l1;
        split_pack(v.x, v.y, h0, l0);
        split_pack(v.z, v.w, h1, l1);
        *(uint2*)(sAh + r * RS + kq * 8) = make_uint2(h0, h1);
        *(uint2*)(sAl + r * RS + kq * 8) = make_uint2(l0, l1);
    }
    for (int idx = t; idx < 4096; idx += 256) {
        int r = idx >> 4, kq = idx & 15;
        float4 v = *(const float4*)(Bb + (size_t)r * NN + kq * 4);
        uint32_t h0, l0, h1, l1;
        split_pack(v.x, v.y, h0, l0);
        split_pack(v.z, v.w, h1, l1);
        *(uint2*)(sBh + r * RS + kq * 8) = make_uint2(h0, h1);
        *(uint2*)(sBl + r * RS + kq * 8) = make_uint2(l0, l1);
    }
    __syncthreads();

    uint32_t aRow = wm + (l & 15);
    uint32_t aOff = ((l >> 4) & 1) * 16;
    uint32_t aHi = sb + 0    + aRow * RS + aOff;
    uint32_t aLo = sb + 9216 + aRow * RS + aOff;
    uint32_t bRow = wn + (l & 7) + ((l & 16) ? 8 : 0);
    uint32_t bOff = (l & 8) ? 16 : 0;
    uint32_t bHi = sb + 18432 + bRow * RS + bOff;
    uint32_t bLo = sb + 55296 + bRow * RS + bOff;

    float acc[2][8][4];
#pragma unroll
    for (int i = 0; i < 2; i++)
#pragma unroll
        for (int j = 0; j < 8; j++)
#pragma unroll
            for (int q = 0; q < 4; q++) acc[i][j][q] = 0.f;

#pragma unroll
    for (int ks = 0; ks < 4; ks++) {
        uint32_t ah[2][4], al[2][4], bh[4][4], blr[4][4];
#pragma unroll
        for (int mf = 0; mf < 2; mf++) {
            ldm4(aHi + mf * (16 * RS) + ks * 32, ah[mf]);
            ldm4(aLo + mf * (16 * RS) + ks * 32, al[mf]);
        }
#pragma unroll
        for (int p = 0; p < 4; p++) {
            ldm4(bHi + p * (16 * RS) + ks * 32, bh[p]);
            ldm4(bLo + p * (16 * RS) + ks * 32, blr[p]);
        }
#pragma unroll
        for (int mf = 0; mf < 2; mf++)
#pragma unroll
            for (int nf = 0; nf < 8; nf++) {
                const uint32_t* bhp = &bh[nf >> 1][(nf & 1) * 2];
                const uint32_t* blp = &blr[nf >> 1][(nf & 1) * 2];
                mma16816(acc[mf][nf], ah[mf], bhp);
                mma16816(acc[mf][nf], ah[mf], blp);
                mma16816(acc[mf][nf], al[mf], bhp);
            }
    }

    float psum[2][2], psq[2][2];
#pragma unroll
    for (int mf = 0; mf < 2; mf++)
#pragma unroll
        for (int h = 0; h < 2; h++) { psum[mf][h] = 0.f; psq[mf][h] = 0.f; }
#pragma unroll
    for (int nf = 0; nf < 8; nf++) {
        int col = wn + nf * 8 + (l & 3) * 2;
        float t0 = sTem[col], t1 = sTem[col + 1];
#pragma unroll
        for (int mf = 0; mf < 2; mf++) {
            acc[mf][nf][0] *= t0; acc[mf][nf][1] *= t1;
            acc[mf][nf][2] *= t0; acc[mf][nf][3] *= t1;
            psum[mf][0] += acc[mf][nf][0] + acc[mf][nf][1];
            psq [mf][0] += acc[mf][nf][0] * acc[mf][nf][0] + acc[mf][nf][1] * acc[mf][nf][1];
            psum[mf][1] += acc[mf][nf][2] + acc[mf][nf][3];
            psq [mf][1] += acc[mf][nf][2] * acc[mf][nf][2] + acc[mf][nf][3] * acc[mf][nf][3];
        }
    }
#pragma unroll
    for (int mf = 0; mf < 2; mf++)
#pragma unroll
        for (int h = 0; h < 2; h++) {
#pragma unroll
            for (int off = 1; off <= 2; off <<= 1) {
                psum[mf][h] += __shfl_xor_sync(0xffffffffu, psum[mf][h], off);
                psq [mf][h] += __shfl_xor_sync(0xffffffffu, psq [mf][h], off);
            }
            if ((l & 3) == 0) {
                int r = wm + mf * 16 + h * 8 + (l >> 2);
                sSum[r * 4 + (warp >> 1)] = psum[mf][h];
                sSq [r * 4 + (warp >> 1)] = psq [mf][h];
            }
        }
    __syncthreads();

#pragma unroll
    for (int mf = 0; mf < 2; mf++)
#pragma unroll
        for (int h = 0; h < 2; h++) {
            int r = wm + mf * 16 + h * 8 + (l >> 2);
            float sum = sSum[r * 4] + sSum[r * 4 + 1] + sSum[r * 4 + 2] + sSum[r * 4 + 3];
            float sq  = sSq [r * 4] + sSq [r * 4 + 1] + sSq [r * 4 + 2] + sSq [r * 4 + 3];
            float mu = sum * (1.f / 256.f);
            float var = sq * (1.f / 256.f) - mu * mu;
            float rs = rsqrtf(var + EPSV);
#pragma unroll
            for (int nf = 0; nf < 8; nf++) {
                int col = wn + nf * 8 + (l & 3) * 2;
                float v0 = acc[mf][nf][h * 2], v1 = acc[mf][nf][h * 2 + 1];
                float o0 = fmaxf((v0 - mu) * rs * sG[col] + sB2[col], 0.f);
                float o1 = fmaxf((v1 - mu) * rs * sG[col + 1] + sB2[col + 1], 0.f);
                *(float2*)(sOut + r * 260 + col) = make_float2(o0, o1);
            }
        }
    __syncthreads();

    const float* Xb = xf + ((size_t)b * SS + s0) * CC;
    float* Ob = out + ((size_t)b * SS + s0) * CC;
    for (int idx = t; idx < 4096; idx += 256) {
        int r = idx >> 6, cq = idx & 63;
        float4 o = *(float4*)(sOut + r * 260 + cq * 4);
        float4 x = *(const float4*)(Xb + (size_t)r * CC + cq * 4);
        o.x += x.x; o.y += x.y; o.z += x.z; o.w += x.w;
        *(float4*)(Ob + (size_t)r * CC + cq * 4) = o;
    }
}

// ---------------------------------------------------------------------------
extern "C" void kernel_launch(void* const* d_in, const int* in_sizes, int n_in,
                              void* d_out, int out_size) {
    const float* x_feat = (const float*)d_in[0];
    const float* z_feat = (const float*)d_in[1];
    const float* Wz     = (const float*)d_in[2];
    const float* bz     = (const float*)d_in[3];
    const float* Wx     = (const float*)d_in[4];
    const float* bx     = (const float*)d_in[5];
    const float* Wdyn   = (const float*)d_in[6];
    const float* bdyn   = (const float*)d_in[7];
    const float* gnorm  = (const float*)d_in[8];
    const float* bnorm  = (const float*)d_in[9];
    const float* Wp     = (const float*)d_in[10];
    const float* bp     = (const float*)d_in[11];
    const float* g_ln   = (const float*)d_in[12];
    const float* b_ln   = (const float*)d_in[13];
    float* out = (float*)d_out;

    float *xn, *zc, *kz, *kxp, *kaT;
    cudaGetSymbolAddress((void**)&xn,  g_xn);
    cudaGetSymbolAddress((void**)&zc,  g_zc);
    cudaGetSymbolAddress((void**)&kz,  g_kz);
    cudaGetSymbolAddress((void**)&kxp, g_kxp);
    cudaGetSymbolAddress((void**)&kaT, g_kaT);

    cudaFuncSetAttribute(kLinAll,  cudaFuncAttributeMaxDynamicSharedMemorySize, SMEM_KG);
    cudaFuncSetAttribute(kOuterAll, cudaFuncAttributeMaxDynamicSharedMemorySize, SMEM_KG);
    cudaFuncSetAttribute(kD,  cudaFuncAttributeMaxDynamicSharedMemorySize, 218880);
    cudaFuncSetAttribute(kXC, cudaFuncAttributeMaxDynamicSharedMemorySize, 97280);

    kLinAll<<<640, 256, SMEM_KG>>>(x_feat, Wx, bx, z_feat, Wz, bz, xn, zc);
    kOuterAll<<<384, 256, SMEM_KG>>>(x_feat, z_feat, xn, zc, kxp, kz);
    kD<<<BB, 512, 218880>>>(Wdyn, bdyn, gnorm, bnorm, Wp, bp);
    kXC<<<dim3(16, BB), 256, 97280>>>(xn, kaT, x_feat, g_ln, b_ln, out);
}

// round 9
// speedup vs baseline: 2.0283x; 1.0846x over previous
#include <cuda_runtime.h>
#include <cuda_bf16.h>
#include <math.h>
#include <stdint.h>

#define BB   64
#define SS   1024
#define SZS  256
#define CC   256
#define NN   64
#define NKD  67
#define EPSV 1e-5f
#define PAD  257

// ------------------------- scratch (device globals) -------------------------
__device__ float g_xn [BB * SS * NN];       // x_n    [b][s][n]  16MB
__device__ float g_zc [BB * SZS * NN];      // z_core [b][s][n]   4MB
__device__ float g_kz [BB * CC * NN];       // kernels (z path)  [b][c][n]
__device__ float g_kxp[2 * BB * CC * NN];   // kernels_x partials [b][c][n]
__device__ __nv_bfloat16 g_kh[BB * CC * NN];  // kernels_x post-LN hi [b][c][n]
__device__ __nv_bfloat16 g_kl[BB * CC * NN];  // kernels_x post-LN lo [b][c][n]
__device__ float g_tem[BB * CC];

// ------------------------- helpers -------------------------
__device__ __forceinline__ uint32_t smem_u32(const void* p) {
    uint32_t a;
    asm("{ .reg .u64 tmp; cvta.to.shared.u64 tmp, %1; cvt.u32.u64 %0, tmp; }"
        : "=r"(a) : "l"(p));
    return a;
}
__device__ __forceinline__ void split_pack(float x0, float x1, uint32_t& h, uint32_t& l) {
    __nv_bfloat162 hp = __floats2bfloat162_rn(x0, x1);
    float r0 = x0 - __bfloat162float(hp.x);
    float r1 = x1 - __bfloat162float(hp.y);
    __nv_bfloat162 lp = __floats2bfloat162_rn(r0, r1);
    h = *reinterpret_cast<uint32_t*>(&hp);
    l = *reinterpret_cast<uint32_t*>(&lp);
}
__device__ __forceinline__ void ldm4(uint32_t addr, uint32_t* r) {
    asm volatile("ldmatrix.sync.aligned.m8n8.x4.shared.b16 {%0,%1,%2,%3}, [%4];"
                 : "=r"(r[0]), "=r"(r[1]), "=r"(r[2]), "=r"(r[3]) : "r"(addr));
}
__device__ __forceinline__ void mma16816(float* d, const uint32_t* a, const uint32_t* b) {
    asm volatile(
        "mma.sync.aligned.m16n8k16.row.col.f32.bf16.bf16.f32 "
        "{%0,%1,%2,%3}, {%4,%5,%6,%7}, {%8,%9}, {%0,%1,%2,%3};"
        : "+f"(d[0]), "+f"(d[1]), "+f"(d[2]), "+f"(d[3])
        : "r"(a[0]), "r"(a[1]), "r"(a[2]), "r"(a[3]), "r"(b[0]), "r"(b[1]));
}
__device__ __forceinline__ void cp16(uint32_t dst, const void* src) {
    asm volatile("cp.async.cg.shared.global [%0], [%1], 16;" :: "r"(dst), "l"(src));
}
__device__ __forceinline__ void cpcommit() {
    asm volatile("cp.async.commit_group;" ::: "memory");
}
template<int N> __device__ __forceinline__ void cpwait() {
    asm volatile("cp.async.wait_group %0;" :: "n"(N) : "memory");
}

// bf16 smem row stride (bytes): 72 halves = 144B
#define RS 144
// raw staging strides (floats)
#define RAWA_F  68    // non-TRA: 128 rows x 64+pad
#define RAWAT_F 132   // TRA: 64 k-rows x 128+pad
#define RAWB_F  68    // 64 rows x 64+pad
#define RAW_A_BYTES 34816
#define RAW_B_BYTES 17408
// smem layout offsets (bytes)
#define OFF_AH   0
#define OFF_AL   18432
#define OFF_BH   36864
#define OFF_BL   46080
#define OFF_RAWA 55296
#define OFF_RAWB 124928
#define OFF_BIAS 159744
#define SMEM_KG  160000

// ---------------------------------------------------------------------------
// pipelined chunk loaders: gmem -> raw fp32 smem via cp.async (all coalesced)
// ---------------------------------------------------------------------------
template<bool TRA, bool TRB>
__device__ __forceinline__ void kg_load(const float* Ab, int lda, const float* Bb,
                                        int ldb, int m0, int k0, char* sm, int stg, int t) {
    uint32_t ra = smem_u32(sm + OFF_RAWA + stg * RAW_A_BYTES);
    uint32_t rb = smem_u32(sm + OFF_RAWB + stg * RAW_B_BYTES);
    if (!TRA) {
#pragma unroll
        for (int i = 0; i < 8; i++) {
            int u = t + i * 256;
            int r = u >> 4, kq = u & 15;
            cp16(ra + r * (RAWA_F * 4) + kq * 16,
                 Ab + (size_t)(m0 + r) * lda + k0 + kq * 4);
        }
    } else {
#pragma unroll
        for (int i = 0; i < 8; i++) {
            int u = t + i * 256;
            int r = u >> 5, mq = u & 31;
            cp16(ra + r * (RAWAT_F * 4) + mq * 16,
                 Ab + (size_t)(k0 + r) * lda + m0 + mq * 4);
        }
    }
    if (!TRB) {
#pragma unroll
        for (int i = 0; i < 4; i++) {
            int u = t + i * 256;
            int r = u >> 4, kq = u & 15;
            cp16(rb + r * (RAWB_F * 4) + kq * 16,
                 Bb + (size_t)r * ldb + k0 + kq * 4);
        }
    } else {
#pragma unroll
        for (int i = 0; i < 4; i++) {
            int u = t + i * 256;
            int r = u >> 4, nq = u & 15;
            cp16(rb + r * (RAWB_F * 4) + nq * 16,
                 Bb + (size_t)(k0 + r) * ldb + nq * 4);
        }
    }
}

// convert raw fp32 stage -> split-bf16 operand buffers (transpose happens here)
template<bool TRA, bool TRB>
__device__ __forceinline__ void kg_convert(char* sm, int stg, int t) {
    float* rawA = (float*)(sm + OFF_RAWA + stg * RAW_A_BYTES);
    float* rawB = (float*)(sm + OFF_RAWB + stg * RAW_B_BYTES);
    char* sAh = sm + OFF_AH; char* sAl = sm + OFF_AL;
    char* sBh = sm + OFF_BH; char* sBl = sm + OFF_BL;
    if (!TRA) {
#pragma unroll
        for (int i = 0; i < 8; i++) {
            int u = t + i * 256;
            int r = u >> 4, kq = u & 15;
            float4 v = *(const float4*)(rawA + r * RAWA_F + kq * 4);
            uint32_t h0, l0, h1, l1;
            split_pack(v.x, v.y, h0, l0);
            split_pack(v.z, v.w, h1, l1);
            *(uint2*)(sAh + r * RS + kq * 8) = make_uint2(h0, h1);
            *(uint2*)(sAl + r * RS + kq * 8) = make_uint2(l0, l1);
        }
    } else {
#pragma unroll
        for (int i = 0; i < 8; i++) {
            int u = t + i * 256;
            int m = u & 127, kg = u >> 7;  // kg 0..15
            float f0 = rawA[(kg * 4 + 0) * RAWAT_F + m];
            float f1 = rawA[(kg * 4 + 1) * RAWAT_F + m];
            float f2 = rawA[(kg * 4 + 2) * RAWAT_F + m];
            float f3 = rawA[(kg * 4 + 3) * RAWAT_F + m];
            uint32_t h0, l0, h1, l1;
            split_pack(f0, f1, h0, l0);
            split_pack(f2, f3, h1, l1);
            *(uint2*)(sAh + m * RS + kg * 8) = make_uint2(h0, h1);
            *(uint2*)(sAl + m * RS + kg * 8) = make_uint2(l0, l1);
        }
    }
    if (!TRB) {
#pragma unroll
        for (int i = 0; i < 4; i++) {
            int u = t + i * 256;
            int r = u >> 4, kq = u & 15;
            float4 v = *(const float4*)(rawB + r * RAWB_F + kq * 4);
            uint32_t h0, l0, h1, l1;
            split_pack(v.x, v.y, h0, l0);
            split_pack(v.z, v.w, h1, l1);
            *(uint2*)(sBh + r * RS + kq * 8) = make_uint2(h0, h1);
            *(uint2*)(sBl + r * RS + kq * 8) = make_uint2(l0, l1);
        }
    } else {
#pragma unroll
        for (int i = 0; i < 4; i++) {
            int u = t + i * 256;
            int n = u & 63, kg = u >> 6;  // kg 0..15
            float f0 = rawB[(kg * 4 + 0) * RAWB_F + n];
            float f1 = rawB[(kg * 4 + 1) * RAWB_F + n];
            float f2 = rawB[(kg * 4 + 2) * RAWB_F + n];
            float f3 = rawB[(kg * 4 + 3) * RAWB_F + n];
            uint32_t h0, l0, h1, l1;
            split_pack(f0, f1, h0, l0);
            split_pack(f2, f3, h1, l1);
            *(uint2*)(sBh + n * RS + kg * 8) = make_uint2(h0, h1);
            *(uint2*)(sBl + n * RS + kg * 8) = make_uint2(l0, l1);
        }
    }
}

// ---------------------------------------------------------------------------
// gemm_tile<TRA,TRB>: D[m0..m0+127, 0..63] += sum_k A*B (+bias), pipelined.
// 256 threads = 8 warps (4M x 2N).
// ---------------------------------------------------------------------------
template<bool TRA, bool TRB>
__device__ void gemm_tile(const float* __restrict__ Ab, int lda,
                          const float* __restrict__ Bb, int ldb,
                          float* __restrict__ Db, int ldd,
                          int m0, int Ktot, const float* __restrict__ bias,
                          char* sm) {
    uint32_t sb = smem_u32(sm);
    int t = threadIdx.x, warp = t >> 5, l = t & 31;
    int wm = (warp & 3) * 32;
    int wn = (warp >> 2) * 32;
    float* sBias = (float*)(sm + OFF_BIAS);
    if (bias && t < 64) sBias[t] = bias[t];

    float acc[2][4][4];
#pragma unroll
    for (int i = 0; i < 2; i++)
#pragma unroll
        for (int j = 0; j < 4; j++)
#pragma unroll
            for (int q = 0; q < 4; q++) acc[i][j][q] = 0.f;

    uint32_t aRow = wm + (l & 15);
    uint32_t aOff = ((l >> 4) & 1) * 16;
    uint32_t aHi = sb + OFF_AH + aRow * RS + aOff;
    uint32_t aLo = sb + OFF_AL + aRow * RS + aOff;
    uint32_t bRow = wn + (l & 7) + ((l & 16) ? 8 : 0);
    uint32_t bOff = (l & 8) ? 16 : 0;
    uint32_t bHi = sb + OFF_BH + bRow * RS + bOff;
    uint32_t bLo = sb + OFF_BL + bRow * RS + bOff;

    int nch = Ktot >> 6;
    kg_load<TRA, TRB>(Ab, lda, Bb, ldb, m0, 0, sm, 0, t);
    cpcommit();

    for (int ch = 0; ch < nch; ch++) {
        if (ch + 1 < nch) {
            kg_load<TRA, TRB>(Ab, lda, Bb, ldb, m0, (ch + 1) << 6, sm, (ch + 1) & 1, t);
            cpcommit();
            cpwait<1>();
        } else {
            cpwait<0>();
        }
        __syncthreads();
        kg_convert<TRA, TRB>(sm, ch & 1, t);
        __syncthreads();
#pragma unroll
        for (int ks = 0; ks < 4; ks++) {
            uint32_t ah[2][4], al[2][4], bh[2][4], bl[2][4];
#pragma unroll
            for (int mf = 0; mf < 2; mf++) {
                ldm4(aHi + mf * (16 * RS) + ks * 32, ah[mf]);
                ldm4(aLo + mf * (16 * RS) + ks * 32, al[mf]);
            }
#pragma unroll
            for (int p = 0; p < 2; p++) {
                ldm4(bHi + p * (16 * RS) + ks * 32, bh[p]);
                ldm4(bLo + p * (16 * RS) + ks * 32, bl[p]);
            }
#pragma unroll
            for (int mf = 0; mf < 2; mf++)
#pragma unroll
                for (int nf = 0; nf < 4; nf++) {
                    const uint32_t* bhp = &bh[nf >> 1][(nf & 1) * 2];
                    const uint32_t* blp = &bl[nf >> 1][(nf & 1) * 2];
                    mma16816(acc[mf][nf], ah[mf], bhp);
                    mma16816(acc[mf][nf], ah[mf], blp);
                    mma16816(acc[mf][nf], al[mf], bhp);
                }
        }
        __syncthreads();
    }

#pragma unroll
    for (int mf = 0; mf < 2; mf++)
#pragma unroll
        for (int nf = 0; nf < 4; nf++) {
            int row = m0 + wm + mf * 16 + (l >> 2);
            int col = wn + nf * 8 + (l & 3) * 2;
            float b0 = bias ? sBias[col] : 0.f;
            float b1 = bias ? sBias[col + 1] : 0.f;
            *(float2*)(Db + (size_t)row * ldd + col) =
                make_float2(acc[mf][nf][0] + b0, acc[mf][nf][1] + b1);
            *(float2*)(Db + (size_t)(row + 8) * ldd + col) =
                make_float2(acc[mf][nf][2] + b0, acc[mf][nf][3] + b1);
        }
}

// ---------------------------------------------------------------------------
// merged launch 1: x_n = X@Wx+bx (512 tiles) and z_core = Z@Wz+bz (128 tiles)
// ---------------------------------------------------------------------------
__global__ void __launch_bounds__(256) kLinAll(
    const float* __restrict__ xf, const float* __restrict__ Wx, const float* __restrict__ bx,
    const float* __restrict__ zf, const float* __restrict__ Wz, const float* __restrict__ bz,
    float* __restrict__ xn, float* __restrict__ zcp) {
    extern __shared__ char sm[];
    int bid = blockIdx.x;
    if (bid < 512) {
        int b = bid >> 3, m0 = (bid & 7) * 128;
        gemm_tile<false, true>(xf + (size_t)b * SS * CC, CC, Wx, NN,
                               xn + (size_t)b * SS * NN, NN, m0, CC, bx, sm);
    } else {
        int zi = bid - 512;
        int b = zi >> 1, m0 = (zi & 1) * 128;
        gemm_tile<false, true>(zf + (size_t)b * SZS * CC, CC, Wz, NN,
                               zcp + (size_t)b * SZS * NN, NN, m0, CC, bz, sm);
    }
}

// ---------------------------------------------------------------------------
// merged launch 2: kx partials (s-split x2, 256 tiles) and kz (128 tiles)
// ---------------------------------------------------------------------------
__global__ void __launch_bounds__(256) kOuterAll(
    const float* __restrict__ xf, const float* __restrict__ zf,
    const float* __restrict__ xn, const float* __restrict__ zcp,
    float* __restrict__ kxp, float* __restrict__ kz) {
    extern __shared__ char sm[];
    int bid = blockIdx.x;
    if (bid < 256) {
        int b = bid >> 2, q = bid & 3, tile = q & 1, half = q >> 1;
        gemm_tile<true, true>(
            xf + (size_t)b * SS * CC + (size_t)half * 512 * CC, CC,
            xn + (size_t)b * SS * NN + (size_t)half * 512 * NN, NN,
            kxp + (size_t)half * BB * CC * NN + (size_t)b * CC * NN, NN,
            tile * 128, 512, nullptr, sm);
    } else {
        int zi = bid - 256;
        int b = zi >> 1, tile = zi & 1;
        gemm_tile<true, true>(
            zf + (size_t)b * SZS * CC, CC, zcp + (size_t)b * SZS * NN, NN,
            kz + (size_t)b * CC * NN, NN, tile * 128, SZS, nullptr, sm);
    }
}

// ---------------------------------------------------------------------------
// kD: dysep conv atten + layernorm + proto + tem. grid(64), 512 threads.
// Writes split-bf16 kernels (g_kh/g_kl, [b][c][n]) and g_tem.
// ---------------------------------------------------------------------------
__global__ void kD(const float* __restrict__ Wdyn, const float* __restrict__ bdyn,
                   const float* __restrict__ gn, const float* __restrict__ bn,
                   const float* __restrict__ Wp, const float* __restrict__ bp) {
    extern __shared__ float smf[];
    float* sKz = smf;            // 64 x PAD (reused later as sP)
    float* sV  = smf + 16448;    // 64 x PAD
    float* sU  = smf + 32896;    // WdynT staging (68-stride), then depth 64x256
    float* sDy = smf + 50304;    // 64 x 68
    float* sPr = smf + 54656;    // 64
    int b = blockIdx.x, t = threadIdx.x;

    const float* kzb = g_kz + (size_t)b * CC * NN;
    const float* kx0 = g_kxp + (size_t)b * CC * NN;
    const float* kx1 = g_kxp + (size_t)BB * CC * NN + (size_t)b * CC * NN;
    for (int idx = t; idx < CC * NN; idx += 512) {
        int c = idx >> 6, n = idx & 63;
        sKz[n * PAD + c] = kzb[idx];
        sV [n * PAD + c] = kx0[idx] + kx1[idx];
    }
    for (int idx = t; idx < CC * NKD; idx += 512) {
        int c = idx / NKD, jj = idx - c * NKD;
        sU[c * 68 + jj] = Wdyn[idx];
    }
    __syncthreads();

    // dy[m,jj] = kz[m,:] . Wdyn[:,jj] + bdyn[jj]
#pragma unroll
    for (int k = 0; k < 9; k++) {
        int o = t + k * 512;
        if (o < NN * NKD) {
            int m = o / NKD, jj = o - m * NKD;
            const float* kzr = sKz + m * PAD;
            const float* wc  = sU + jj;
            float a0 = 0.f, a1 = 0.f, a2 = 0.f, a3 = 0.f;
            for (int c = 0; c < CC; c += 4) {
                a0 += kzr[c + 0] * wc[(c + 0) * 68];
                a1 += kzr[c + 1] * wc[(c + 1) * 68];
                a2 += kzr[c + 2] * wc[(c + 2) * 68];
                a3 += kzr[c + 3] * wc[(c + 3) * 68];
            }
            sDy[m * 68 + jj] = bdyn[jj] + ((a0 + a1) + (a2 + a3));
        }
    }
    __syncthreads();

    // depth(m,c) = relu(w0*v[c-1] + w1*v[c] + w2*v[c+1])  (overwrites sU)
    for (int idx = t; idx < NN * CC; idx += 512) {
        int m = idx >> 8, c = idx & 255;
        float w0 = sDy[m * 68 + 0], w1 = sDy[m * 68 + 1], w2 = sDy[m * 68 + 2];
        float vm = (c > 0)   ? sV[m * PAD + c - 1] : 0.f;
        float v0 = sV[m * PAD + c];
        float vp = (c < 255) ? sV[m * PAD + c + 1] : 0.f;
        float d = w0 * vm + w1 * v0 + w2 * vp;
        sU[idx] = d > 0.f ? d : 0.f;
    }
    __syncthreads();

    // point(n,c) = sum_m wp[n,m]*depth[m,c]; layernorm over c
    int tx = t & 31, ty = t >> 5;
    float4 acc[4][2];
#pragma unroll
    for (int i = 0; i < 4; i++) {
        acc[i][0] = make_float4(0.f, 0.f, 0.f, 0.f);
        acc[i][1] = make_float4(0.f, 0.f, 0.f, 0.f);
    }
#pragma unroll 2
    for (int m = 0; m < NN; m++) {
        float4 d0 = *(const float4*)(sU + m * CC + tx * 4);
        float4 d1 = *(const float4*)(sU + m * CC + tx * 4 + 128);
#pragma unroll
        for (int i = 0; i < 4; i++) {
            float w = sDy[(ty * 4 + i) * 68 + 3 + m];
            acc[i][0].x += w * d0.x; acc[i][0].y += w * d0.y;
            acc[i][0].z += w * d0.z; acc[i][0].w += w * d0.w;
            acc[i][1].x += w * d1.x; acc[i][1].y += w * d1.y;
            acc[i][1].z += w * d1.z; acc[i][1].w += w * d1.w;
        }
    }
    __syncthreads();

    float* sP = sKz;
    float4 gg0 = *(const float4*)(gn + tx * 4);
    float4 gg1 = *(const float4*)(gn + tx * 4 + 128);
    float4 bb0 = *(const float4*)(bn + tx * 4);
    float4 bb1 = *(const float4*)(bn + tx * 4 + 128);
#pragma unroll
    for (int i = 0; i < 4; i++) {
        int n = ty * 4 + i;
        float4 v0 = acc[i][0], v1 = acc[i][1];
        float sum = v0.x + v0.y + v0.z + v0.w + v1.x + v1.y + v1.z + v1.w;
        float sq  = v0.x * v0.x + v0.y * v0.y + v0.z * v0.z + v0.w * v0.w
                  + v1.x * v1.x + v1.y * v1.y + v1.z * v1.z + v1.w * v1.w;
#pragma unroll
        for (int off = 16; off >= 1; off >>= 1) {
            sum += __shfl_xor_sync(0xffffffffu, sum, off);
            sq  += __shfl_xor_sync(0xffffffffu, sq, off);
        }
        float mu = sum * (1.f / 256.f);
        float var = sq * (1.f / 256.f) - mu * mu;
        float rs = rsqrtf(var + EPSV);
        float4 o0, o1;
        o0.x = (v0.x - mu) * rs * gg0.x + bb0.x;
        o0.y = (v0.y - mu) * rs * gg0.y + bb0.y;
        o0.z = (v0.z - mu) * rs * gg0.z + bb0.z;
        o0.w = (v0.w - mu) * rs * gg0.w + bb0.w;
        o1.x = (v1.x - mu) * rs * gg1.x + bb1.x;
        o1.y = (v1.y - mu) * rs * gg1.y + bb1.y;
        o1.z = (v1.z - mu) * rs * gg1.z + bb1.z;
        o1.w = (v1.w - mu) * rs * gg1.w + bb1.w;
        *(float4*)(sP + n * CC + tx * 4) = o0;
        *(float4*)(sP + n * CC + tx * 4 + 128) = o1;
    }
    __syncthreads();

    // write split-bf16 kernels [c][n]
    __nv_bfloat16* kh = g_kh + (size_t)b * CC * NN;
    __nv_bfloat16* kl = g_kl + (size_t)b * CC * NN;
    for (int idx = t; idx < NN * CC; idx += 512) {
        int c = idx >> 6, n = idx & 63;
        float v = sP[n * CC + c];
        __nv_bfloat16 h = __float2bfloat16(v);
        float lo = v - __bfloat162float(h);
        kh[idx] = h;
        kl[idx] = __float2bfloat16(lo);
    }

    // proto[n] = ka[n,:] . Wp + bp
    if (t < NN) {
        float a0 = 0.f, a1 = 0.f, a2 = 0.f, a3 = 0.f;
        for (int c = 0; c < CC; c += 4) {
            float4 p = *(const float4*)(sP + t * CC + c);
            float4 w = *(const float4*)(Wp + c);
            a0 += p.x * w.x; a1 += p.y * w.y; a2 += p.z * w.z; a3 += p.w * w.w;
        }
        sPr[t] = bp[0] + ((a0 + a1) + (a2 + a3));
    }
    __syncthreads();

    // tem[c] = sigmoid(sum_n proto[n] * ka[n,c])
    if (t < CC) {
        float a0 = 0.f, a1 = 0.f, a2 = 0.f, a3 = 0.f;
        for (int n = 0; n < NN; n += 4) {
            a0 += sPr[n + 0] * sP[(n + 0) * CC + t];
            a1 += sPr[n + 1] * sP[(n + 1) * CC + t];
            a2 += sPr[n + 2] * sP[(n + 2) * CC + t];
            a3 += sPr[n + 3] * sP[(n + 3) * CC + t];
        }
        float s = (a0 + a1) + (a2 + a3);
        g_tem[b * CC + t] = 1.f / (1.f + expf(-s));
    }
}

// ---------------------------------------------------------------------------
// kXC v2: x_corr = xn @ ka  fused with  out = x_feat + relu(LN(x_corr * tem))
// CTA tile 128(S) x 256(C), K = 64. 512 threads = 16 warps (4M x 4N).
// B comes pre-split (g_kh/g_kl) -> pure cp.async staging, no conversion.
// ---------------------------------------------------------------------------
#define XC_AH   0
#define XC_AL   18432
#define XC_BH   36864
#define XC_BL   73728
#define XC_RAWA 110592
#define XC_TEM  145408
#define XC_G    146432
#define XC_B2   147456
#define XC_SUM  148480
#define XC_SQ   150528
#define SMEM_XC 152576

__global__ void __launch_bounds__(512, 1) kXC(
    const float* __restrict__ xn, const __nv_bfloat16* __restrict__ kh,
    const __nv_bfloat16* __restrict__ kl, const float* __restrict__ xf,
    const float* __restrict__ gl, const float* __restrict__ bl,
    float* __restrict__ out)
{
    extern __shared__ char sm[];
    uint32_t sb = smem_u32(sm);
    float* sTem = (float*)(sm + XC_TEM);
    float* sG   = (float*)(sm + XC_G);
    float* sB2  = (float*)(sm + XC_B2);
    float* sSum = (float*)(sm + XC_SUM);   // [128][4]
    float* sSq  = (float*)(sm + XC_SQ);    // [128][4]
    float* sOut = (float*)sm;              // [128][260]

    int t = threadIdx.x, warp = t >> 5, l = t & 31;
    int b = blockIdx.y;
    int s0 = blockIdx.x * 128;
    int wm = (warp & 3) * 32;
    int wn = (warp >> 2) * 64;

    const float* Ab = xn + ((size_t)b * SS + s0) * NN;
    const __nv_bfloat16* Bh = kh + (size_t)b * CC * NN;
    const __nv_bfloat16* Bl = kl + (size_t)b * CC * NN;

    // stage A raw fp32 (128x64 = 2048 x 16B) + B hi/lo bf16 (256 rows x 8 x 16B each)
    {
        uint32_t ra = sb + XC_RAWA;
#pragma unroll
        for (int i = 0; i < 4; i++) {
            int u = t + i * 512;
            int r = u >> 4, kq = u & 15;
            cp16(ra + r * (RAWA_F * 4) + kq * 16, Ab + (size_t)r * NN + kq * 4);
        }
#pragma unroll
        for (int i = 0; i < 4; i++) {
            int u = t + i * 512;
            int r = u >> 3, kq = u & 7;
            cp16(sb + XC_BH + r * RS + kq * 16, Bh + r * NN + kq * 8);
        }
#pragma unroll
        for (int i = 0; i < 4; i++) {
            int u = t + i * 512;
            int r = u >> 3, kq = u & 7;
            cp16(sb + XC_BL + r * RS + kq * 16, Bl + r * NN + kq * 8);
        }
        cpcommit();
    }
    if (t < 256) { sTem[t] = g_tem[b * CC + t]; sG[t] = gl[t]; sB2[t] = bl[t]; }
    cpwait<0>();
    __syncthreads();

    // convert A to split bf16
    {
        float* rawA = (float*)(sm + XC_RAWA);
        char* sAh = sm + XC_AH;
        char* sAl = sm + XC_AL;
#pragma unroll
        for (int i = 0; i < 4; i++) {
            int u = t + i * 512;
            int r = u >> 4, kq = u & 15;
            float4 v = *(const float4*)(rawA + r * RAWA_F + kq * 4);
            uint32_t h0, l0, h1, l1;
            split_pack(v.x, v.y, h0, l0);
            split_pack(v.z, v.w, h1, l1);
            *(uint2*)(sAh + r * RS + kq * 8) = make_uint2(h0, h1);
            *(uint2*)(sAl + r * RS + kq * 8) = make_uint2(l0, l1);
        }
    }
    __syncthreads();

    uint32_t aRow = wm + (l & 15);
    uint32_t aOff = ((l >> 4) & 1) * 16;
    uint32_t aHi = sb + XC_AH + aRow * RS + aOff;
    uint32_t aLo = sb + XC_AL + aRow * RS + aOff;
    uint32_t bRow = wn + (l & 7) + ((l & 16) ? 8 : 0);
    uint32_t bOff = (l & 8) ? 16 : 0;
    uint32_t bHi = sb + XC_BH + bRow * RS + bOff;
    uint32_t bLo = sb + XC_BL + bRow * RS + bOff;

    float acc[2][8][4];
#pragma unroll
    for (int i = 0; i < 2; i++)
#pragma unroll
        for (int j = 0; j < 8; j++)
#pragma unroll
            for (int q = 0; q < 4; q++) acc[i][j][q] = 0.f;

#pragma unroll
    for (int ks = 0; ks < 4; ks++) {
        uint32_t ah[2][4], al[2][4], bh[4][4], blr[4][4];
#pragma unroll
        for (int mf = 0; mf < 2; mf++) {
            ldm4(aHi + mf * (16 * RS) + ks * 32, ah[mf]);
            ldm4(aLo + mf * (16 * RS) + ks * 32, al[mf]);
        }
#pragma unroll
        for (int p = 0; p < 4; p++) {
            ldm4(bHi + p * (16 * RS) + ks * 32, bh[p]);
            ldm4(bLo + p * (16 * RS) + ks * 32, blr[p]);
        }
#pragma unroll
        for (int mf = 0; mf < 2; mf++)
#pragma unroll
            for (int nf = 0; nf < 8; nf++) {
                const uint32_t* bhp = &bh[nf >> 1][(nf & 1) * 2];
                const uint32_t* blp = &blr[nf >> 1][(nf & 1) * 2];
                mma16816(acc[mf][nf], ah[mf], bhp);
                mma16816(acc[mf][nf], ah[mf], blp);
                mma16816(acc[mf][nf], al[mf], bhp);
            }
    }

    // apply tem, per-row partial sums (rows split across 4 n-warps)
    float psum[2][2], psq[2][2];
#pragma unroll
    for (int mf = 0; mf < 2; mf++)
#pragma unroll
        for (int h = 0; h < 2; h++) { psum[mf][h] = 0.f; psq[mf][h] = 0.f; }
#pragma unroll
    for (int nf = 0; nf < 8; nf++) {
        int col = wn + nf * 8 + (l & 3) * 2;
        float t0 = sTem[col], t1 = sTem[col + 1];
#pragma unroll
        for (int mf = 0; mf < 2; mf++) {
            acc[mf][nf][0] *= t0; acc[mf][nf][1] *= t1;
            acc[mf][nf][2] *= t0; acc[mf][nf][3] *= t1;
            psum[mf][0] += acc[mf][nf][0] + acc[mf][nf][1];
            psq [mf][0] += acc[mf][nf][0] * acc[mf][nf][0] + acc[mf][nf][1] * acc[mf][nf][1];
            psum[mf][1] += acc[mf][nf][2] + acc[mf][nf][3];
            psq [mf][1] += acc[mf][nf][2] * acc[mf][nf][2] + acc[mf][nf][3] * acc[mf][nf][3];
        }
    }
#pragma unroll
    for (int mf = 0; mf < 2; mf++)
#pragma unroll
        for (int h = 0; h < 2; h++) {
#pragma unroll
            for (int off = 1; off <= 2; off <<= 1) {
                psum[mf][h] += __shfl_xor_sync(0xffffffffu, psum[mf][h], off);
                psq [mf][h] += __shfl_xor_sync(0xffffffffu, psq [mf][h], off);
            }
            if ((l & 3) == 0) {
                int r = wm + mf * 16 + h * 8 + (l >> 2);
                sSum[r * 4 + (warp >> 2)] = psum[mf][h];
                sSq [r * 4 + (warp >> 2)] = psq [mf][h];
            }
        }
    __syncthreads();

    // LN + relu into sOut
#pragma unroll
    for (int mf = 0; mf < 2; mf++)
#pragma unroll
        for (int h = 0; h < 2; h++) {
            int r = wm + mf * 16 + h * 8 + (l >> 2);
            float sum = sSum[r * 4] + sSum[r * 4 + 1] + sSum[r * 4 + 2] + sSum[r * 4 + 3];
            float sq  = sSq [r * 4] + sSq [r * 4 + 1] + sSq [r * 4 + 2] + sSq [r * 4 + 3];
            float mu = sum * (1.f / 256.f);
            float var = sq * (1.f / 256.f) - mu * mu;
            float rs = rsqrtf(var + EPSV);
#pragma unroll
            for (int nf = 0; nf < 8; nf++) {
                int col = wn + nf * 8 + (l & 3) * 2;
                float v0 = acc[mf][nf][h * 2], v1 = acc[mf][nf][h * 2 + 1];
                float o0 = fmaxf((v0 - mu) * rs * sG[col] + sB2[col], 0.f);
                float o1 = fmaxf((v1 - mu) * rs * sG[col + 1] + sB2[col + 1], 0.f);
                *(float2*)(sOut + r * 260 + col) = make_float2(o0, o1);
            }
        }
    __syncthreads();

    // coalesced: out = sOut + x_feat  (128 rows x 256 cols)
    const float* Xb = xf + ((size_t)b * SS + s0) * CC;
    float* Ob = out + ((size_t)b * SS + s0) * CC;
    for (int idx = t; idx < 8192; idx += 512) {
        int r = idx >> 6, cq = idx & 63;
        float4 o = *(float4*)(sOut + r * 260 + cq * 4);
        float4 x = *(const float4*)(Xb + (size_t)r * CC + cq * 4);
        o.x += x.x; o.y += x.y; o.z += x.z; o.w += x.w;
        *(float4*)(Ob + (size_t)r * CC + cq * 4) = o;
    }
}

// ---------------------------------------------------------------------------
extern "C" void kernel_launch(void* const* d_in, const int* in_sizes, int n_in,
                              void* d_out, int out_size) {
    const float* x_feat = (const float*)d_in[0];
    const float* z_feat = (const float*)d_in[1];
    const float* Wz     = (const float*)d_in[2];
    const float* bz     = (const float*)d_in[3];
    const float* Wx     = (const float*)d_in[4];
    const float* bx     = (const float*)d_in[5];
    const float* Wdyn   = (const float*)d_in[6];
    const float* bdyn   = (const float*)d_in[7];
    const float* gnorm  = (const float*)d_in[8];
    const float* bnorm  = (const float*)d_in[9];
    const float* Wp     = (const float*)d_in[10];
    const float* bp     = (const float*)d_in[11];
    const float* g_ln   = (const float*)d_in[12];
    const float* b_ln   = (const float*)d_in[13];
    float* out = (float*)d_out;

    float *xn, *zc, *kz, *kxp;
    __nv_bfloat16 *kh, *kl;
    cudaGetSymbolAddress((void**)&xn,  g_xn);
    cudaGetSymbolAddress((void**)&zc,  g_zc);
    cudaGetSymbolAddress((void**)&kz,  g_kz);
    cudaGetSymbolAddress((void**)&kxp, g_kxp);
    cudaGetSymbolAddress((void**)&kh,  g_kh);
    cudaGetSymbolAddress((void**)&kl,  g_kl);

    cudaFuncSetAttribute(kLinAll,   cudaFuncAttributeMaxDynamicSharedMemorySize, SMEM_KG);
    cudaFuncSetAttribute(kOuterAll, cudaFuncAttributeMaxDynamicSharedMemorySize, SMEM_KG);
    cudaFuncSetAttribute(kD,  cudaFuncAttributeMaxDynamicSharedMemorySize, 218880);
    cudaFuncSetAttribute(kXC, cudaFuncAttributeMaxDynamicSharedMemorySize, SMEM_XC);

    kLinAll<<<640, 256, SMEM_KG>>>(x_feat, Wx, bx, z_feat, Wz, bz, xn, zc);
    kOuterAll<<<384, 256, SMEM_KG>>>(x_feat, z_feat, xn, zc, kxp, kz);
    kD<<<BB, 512, 218880>>>(Wdyn, bdyn, gnorm, bnorm, Wp, bp);
    kXC<<<dim3(8, BB), 512, SMEM_XC>>>(xn, kh, kl, x_feat, g_ln, b_ln, out);
}

// round 10
// speedup vs baseline: 2.1617x; 1.0657x over previous
#include <cuda_runtime.h>
#include <cuda_bf16.h>
#include <math.h>
#include <stdint.h>

#define BB   64
#define SS   1024
#define SZS  256
#define CC   256
#define NN   64
#define NKD  67
#define EPSV 1e-5f
#define PAD  257

// ------------------------- scratch (device globals) -------------------------
__device__ float g_xn [BB * SS * NN];       // x_n    [b][s][n]  16MB
__device__ float g_zc [BB * SZS * NN];      // z_core [b][s][n]   4MB
__device__ float g_kz [BB * CC * NN];       // kernels (z path)  [b][c][n]
__device__ float g_kxp[2 * BB * CC * NN];   // kernels_x partials [b][c][n]
__device__ __nv_bfloat16 g_kh[BB * CC * NN];  // kernels_x post-LN hi [b][c][n]
__device__ __nv_bfloat16 g_kl[BB * CC * NN];  // kernels_x post-LN lo [b][c][n]
__device__ float g_tem[BB * CC];

// ------------------------- helpers -------------------------
__device__ __forceinline__ uint32_t smem_u32(const void* p) {
    uint32_t a;
    asm("{ .reg .u64 tmp; cvta.to.shared.u64 tmp, %1; cvt.u32.u64 %0, tmp; }"
        : "=r"(a) : "l"(p));
    return a;
}
__device__ __forceinline__ void split_pack(float x0, float x1, uint32_t& h, uint32_t& l) {
    __nv_bfloat162 hp = __floats2bfloat162_rn(x0, x1);
    float r0 = x0 - __bfloat162float(hp.x);
    float r1 = x1 - __bfloat162float(hp.y);
    __nv_bfloat162 lp = __floats2bfloat162_rn(r0, r1);
    h = *reinterpret_cast<uint32_t*>(&hp);
    l = *reinterpret_cast<uint32_t*>(&lp);
}
__device__ __forceinline__ void ldm4(uint32_t addr, uint32_t* r) {
    asm volatile("ldmatrix.sync.aligned.m8n8.x4.shared.b16 {%0,%1,%2,%3}, [%4];"
                 : "=r"(r[0]), "=r"(r[1]), "=r"(r[2]), "=r"(r[3]) : "r"(addr));
}
__device__ __forceinline__ void mma16816(float* d, const uint32_t* a, const uint32_t* b) {
    asm volatile(
        "mma.sync.aligned.m16n8k16.row.col.f32.bf16.bf16.f32 "
        "{%0,%1,%2,%3}, {%4,%5,%6,%7}, {%8,%9}, {%0,%1,%2,%3};"
        : "+f"(d[0]), "+f"(d[1]), "+f"(d[2]), "+f"(d[3])
        : "r"(a[0]), "r"(a[1]), "r"(a[2]), "r"(a[3]), "r"(b[0]), "r"(b[1]));
}
__device__ __forceinline__ void cp16(uint32_t dst, const void* src) {
    asm volatile("cp.async.cg.shared.global [%0], [%1], 16;" :: "r"(dst), "l"(src));
}
__device__ __forceinline__ void cpcommit() {
    asm volatile("cp.async.commit_group;" ::: "memory");
}
template<int N> __device__ __forceinline__ void cpwait() {
    asm volatile("cp.async.wait_group %0;" :: "n"(N) : "memory");
}

// bf16 smem row stride (bytes): 72 halves = 144B
#define RS 144
// raw staging strides (floats)
#define RAWA_F  68    // non-TRA: 128 rows x 64+pad
#define RAWAT_F 132   // TRA: 64 k-rows x 128+pad
#define RAWB_F  68    // 64 rows x 64+pad
// smem layout offsets (bytes) — single-buffered raw, 2 CTAs/SM
#define OFF_AH   0        // 128*144 = 18432
#define OFF_AL   18432
#define OFF_BH   36864    // 64*144 = 9216
#define OFF_BL   46080
#define OFF_RAWA 55296    // 34816
#define OFF_RAWB 90112    // 17408
#define OFF_BIAS 107520   // 256
#define SMEM_KG  107776

// ---------------------------------------------------------------------------
// chunk loader: gmem -> raw fp32 smem via cp.async (all coalesced)
// ---------------------------------------------------------------------------
template<bool TRA, bool TRB>
__device__ __forceinline__ void kg_load(const float* Ab, int lda, const float* Bb,
                                        int ldb, int m0, int k0, char* sm, int t) {
    uint32_t ra = smem_u32(sm + OFF_RAWA);
    uint32_t rb = smem_u32(sm + OFF_RAWB);
    if (!TRA) {
#pragma unroll
        for (int i = 0; i < 8; i++) {
            int u = t + i * 256;
            int r = u >> 4, kq = u & 15;
            cp16(ra + r * (RAWA_F * 4) + kq * 16,
                 Ab + (size_t)(m0 + r) * lda + k0 + kq * 4);
        }
    } else {
#pragma unroll
        for (int i = 0; i < 8; i++) {
            int u = t + i * 256;
            int r = u >> 5, mq = u & 31;
            cp16(ra + r * (RAWAT_F * 4) + mq * 16,
                 Ab + (size_t)(k0 + r) * lda + m0 + mq * 4);
        }
    }
    if (!TRB) {
#pragma unroll
        for (int i = 0; i < 4; i++) {
            int u = t + i * 256;
            int r = u >> 4, kq = u & 15;
            cp16(rb + r * (RAWB_F * 4) + kq * 16,
                 Bb + (size_t)r * ldb + k0 + kq * 4);
        }
    } else {
#pragma unroll
        for (int i = 0; i < 4; i++) {
            int u = t + i * 256;
            int r = u >> 4, nq = u & 15;
            cp16(rb + r * (RAWB_F * 4) + nq * 16,
                 Bb + (size_t)(k0 + r) * ldb + nq * 4);
        }
    }
}

// convert raw fp32 -> split-bf16 operand buffers (transpose happens here)
template<bool TRA, bool TRB>
__device__ __forceinline__ void kg_convert(char* sm, int t) {
    float* rawA = (float*)(sm + OFF_RAWA);
    float* rawB = (float*)(sm + OFF_RAWB);
    char* sAh = sm + OFF_AH; char* sAl = sm + OFF_AL;
    char* sBh = sm + OFF_BH; char* sBl = sm + OFF_BL;
    if (!TRA) {
#pragma unroll
        for (int i = 0; i < 8; i++) {
            int u = t + i * 256;
            int r = u >> 4, kq = u & 15;
            float4 v = *(const float4*)(rawA + r * RAWA_F + kq * 4);
            uint32_t h0, l0, h1, l1;
            split_pack(v.x, v.y, h0, l0);
            split_pack(v.z, v.w, h1, l1);
            *(uint2*)(sAh + r * RS + kq * 8) = make_uint2(h0, h1);
            *(uint2*)(sAl + r * RS + kq * 8) = make_uint2(l0, l1);
        }
    } else {
#pragma unroll
        for (int i = 0; i < 8; i++) {
            int u = t + i * 256;
            int m = u & 127, kg = u >> 7;  // kg 0..15
            float f0 = rawA[(kg * 4 + 0) * RAWAT_F + m];
            float f1 = rawA[(kg * 4 + 1) * RAWAT_F + m];
            float f2 = rawA[(kg * 4 + 2) * RAWAT_F + m];
            float f3 = rawA[(kg * 4 + 3) * RAWAT_F + m];
            uint32_t h0, l0, h1, l1;
            split_pack(f0, f1, h0, l0);
            split_pack(f2, f3, h1, l1);
            *(uint2*)(sAh + m * RS + kg * 8) = make_uint2(h0, h1);
            *(uint2*)(sAl + m * RS + kg * 8) = make_uint2(l0, l1);
        }
    }
    if (!TRB) {
#pragma unroll
        for (int i = 0; i < 4; i++) {
            int u = t + i * 256;
            int r = u >> 4, kq = u & 15;
            float4 v = *(const float4*)(rawB + r * RAWB_F + kq * 4);
            uint32_t h0, l0, h1, l1;
            split_pack(v.x, v.y, h0, l0);
            split_pack(v.z, v.w, h1, l1);
            *(uint2*)(sBh + r * RS + kq * 8) = make_uint2(h0, h1);
            *(uint2*)(sBl + r * RS + kq * 8) = make_uint2(l0, l1);
        }
    } else {
#pragma unroll
        for (int i = 0; i < 4; i++) {
            int u = t + i * 256;
            int n = u & 63, kg = u >> 6;  // kg 0..15
            float f0 = rawB[(kg * 4 + 0) * RAWB_F + n];
            float f1 = rawB[(kg * 4 + 1) * RAWB_F + n];
            float f2 = rawB[(kg * 4 + 2) * RAWB_F + n];
            float f3 = rawB[(kg * 4 + 3) * RAWB_F + n];
            uint32_t h0, l0, h1, l1;
            split_pack(f0, f1, h0, l0);
            split_pack(f2, f3, h1, l1);
            *(uint2*)(sBh + n * RS + kg * 8) = make_uint2(h0, h1);
            *(uint2*)(sBl + n * RS + kg * 8) = make_uint2(l0, l1);
        }
    }
}

// ---------------------------------------------------------------------------
// gemm_tile<TRA,TRB>: D[m0..m0+127, 0..63] += sum_k A*B (+bias).
// 256 threads = 8 warps (4M x 2N). Single-buffered; residency=2 gives overlap.
// ---------------------------------------------------------------------------
template<bool TRA, bool TRB>
__device__ void gemm_tile(const float* __restrict__ Ab, int lda,
                          const float* __restrict__ Bb, int ldb,
                          float* __restrict__ Db, int ldd,
                          int m0, int Ktot, const float* __restrict__ bias,
                          char* sm) {
    uint32_t sb = smem_u32(sm);
    int t = threadIdx.x, warp = t >> 5, l = t & 31;
    int wm = (warp & 3) * 32;
    int wn = (warp >> 2) * 32;
    float* sBias = (float*)(sm + OFF_BIAS);
    if (bias && t < 64) sBias[t] = bias[t];

    float acc[2][4][4];
#pragma unroll
    for (int i = 0; i < 2; i++)
#pragma unroll
        for (int j = 0; j < 4; j++)
#pragma unroll
            for (int q = 0; q < 4; q++) acc[i][j][q] = 0.f;

    uint32_t aRow = wm + (l & 15);
    uint32_t aOff = ((l >> 4) & 1) * 16;
    uint32_t aHi = sb + OFF_AH + aRow * RS + aOff;
    uint32_t aLo = sb + OFF_AL + aRow * RS + aOff;
    uint32_t bRow = wn + (l & 7) + ((l & 16) ? 8 : 0);
    uint32_t bOff = (l & 8) ? 16 : 0;
    uint32_t bHi = sb + OFF_BH + bRow * RS + bOff;
    uint32_t bLo = sb + OFF_BL + bRow * RS + bOff;

    int nch = Ktot >> 6;
    for (int ch = 0; ch < nch; ch++) {
        kg_load<TRA, TRB>(Ab, lda, Bb, ldb, m0, ch << 6, sm, t);
        cpcommit();
        cpwait<0>();
        __syncthreads();
        kg_convert<TRA, TRB>(sm, t);
        __syncthreads();
#pragma unroll
        for (int ks = 0; ks < 4; ks++) {
            uint32_t ah[2][4], al[2][4], bh[2][4], bl[2][4];
#pragma unroll
            for (int mf = 0; mf < 2; mf++) {
                ldm4(aHi + mf * (16 * RS) + ks * 32, ah[mf]);
                ldm4(aLo + mf * (16 * RS) + ks * 32, al[mf]);
            }
#pragma unroll
            for (int p = 0; p < 2; p++) {
                ldm4(bHi + p * (16 * RS) + ks * 32, bh[p]);
                ldm4(bLo + p * (16 * RS) + ks * 32, bl[p]);
            }
#pragma unroll
            for (int mf = 0; mf < 2; mf++)
#pragma unroll
                for (int nf = 0; nf < 4; nf++) {
                    const uint32_t* bhp = &bh[nf >> 1][(nf & 1) * 2];
                    const uint32_t* blp = &bl[nf >> 1][(nf & 1) * 2];
                    mma16816(acc[mf][nf], ah[mf], bhp);
                    mma16816(acc[mf][nf], ah[mf], blp);
                    mma16816(acc[mf][nf], al[mf], bhp);
                }
        }
        __syncthreads();
    }

#pragma unroll
    for (int mf = 0; mf < 2; mf++)
#pragma unroll
        for (int nf = 0; nf < 4; nf++) {
            int row = m0 + wm + mf * 16 + (l >> 2);
            int col = wn + nf * 8 + (l & 3) * 2;
            float b0 = bias ? sBias[col] : 0.f;
            float b1 = bias ? sBias[col + 1] : 0.f;
            *(float2*)(Db + (size_t)row * ldd + col) =
                make_float2(acc[mf][nf][0] + b0, acc[mf][nf][1] + b1);
            *(float2*)(Db + (size_t)(row + 8) * ldd + col) =
                make_float2(acc[mf][nf][2] + b0, acc[mf][nf][3] + b1);
        }
}

// ---------------------------------------------------------------------------
// merged launch 1: x_n = X@Wx+bx (512 tiles) and z_core = Z@Wz+bz (128 tiles)
// ---------------------------------------------------------------------------
__global__ void __launch_bounds__(256, 2) kLinAll(
    const float* __restrict__ xf, const float* __restrict__ Wx, const float* __restrict__ bx,
    const float* __restrict__ zf, const float* __restrict__ Wz, const float* __restrict__ bz,
    float* __restrict__ xn, float* __restrict__ zcp) {
    extern __shared__ char sm[];
    int bid = blockIdx.x;
    if (bid < 512) {
        int b = bid >> 3, m0 = (bid & 7) * 128;
        gemm_tile<false, true>(xf + (size_t)b * SS * CC, CC, Wx, NN,
                               xn + (size_t)b * SS * NN, NN, m0, CC, bx, sm);
    } else {
        int zi = bid - 512;
        int b = zi >> 1, m0 = (zi & 1) * 128;
        gemm_tile<false, true>(zf + (size_t)b * SZS * CC, CC, Wz, NN,
                               zcp + (size_t)b * SZS * NN, NN, m0, CC, bz, sm);
    }
}

// ---------------------------------------------------------------------------
// merged launch 2: kx partials (s-split x2, 256 tiles) and kz (128 tiles)
// ---------------------------------------------------------------------------
__global__ void __launch_bounds__(256, 2) kOuterAll(
    const float* __restrict__ xf, const float* __restrict__ zf,
    const float* __restrict__ xn, const float* __restrict__ zcp,
    float* __restrict__ kxp, float* __restrict__ kz) {
    extern __shared__ char sm[];
    int bid = blockIdx.x;
    if (bid < 256) {
        int b = bid >> 2, q = bid & 3, tile = q & 1, half = q >> 1;
        gemm_tile<true, true>(
            xf + (size_t)b * SS * CC + (size_t)half * 512 * CC, CC,
            xn + (size_t)b * SS * NN + (size_t)half * 512 * NN, NN,
            kxp + (size_t)half * BB * CC * NN + (size_t)b * CC * NN, NN,
            tile * 128, 512, nullptr, sm);
    } else {
        int zi = bid - 256;
        int b = zi >> 1, tile = zi & 1;
        gemm_tile<true, true>(
            zf + (size_t)b * SZS * CC, CC, zcp + (size_t)b * SZS * NN, NN,
            kz + (size_t)b * CC * NN, NN, tile * 128, SZS, nullptr, sm);
    }
}

// ---------------------------------------------------------------------------
// kD: dysep conv atten + layernorm + proto + tem. grid(64), 512 threads.
// Writes split-bf16 kernels (g_kh/g_kl, [b][c][n]) and g_tem.
// ---------------------------------------------------------------------------
__global__ void kD(const float* __restrict__ Wdyn, const float* __restrict__ bdyn,
                   const float* __restrict__ gn, const float* __restrict__ bn,
                   const float* __restrict__ Wp, const float* __restrict__ bp) {
    extern __shared__ float smf[];
    float* sKz = smf;            // 64 x PAD (reused later as sP)
    float* sV  = smf + 16448;    // 64 x PAD
    float* sU  = smf + 32896;    // WdynT staging (68-stride), then depth 64x256
    float* sDy = smf + 50304;    // 64 x 68
    float* sPr = smf + 54656;    // 64
    int b = blockIdx.x, t = threadIdx.x;

    const float* kzb = g_kz + (size_t)b * CC * NN;
    const float* kx0 = g_kxp + (size_t)b * CC * NN;
    const float* kx1 = g_kxp + (size_t)BB * CC * NN + (size_t)b * CC * NN;
    for (int idx = t; idx < CC * NN; idx += 512) {
        int c = idx >> 6, n = idx & 63;
        sKz[n * PAD + c] = kzb[idx];
        sV [n * PAD + c] = kx0[idx] + kx1[idx];
    }
    for (int idx = t; idx < CC * NKD; idx += 512) {
        int c = idx / NKD, jj = idx - c * NKD;
        sU[c * 68 + jj] = Wdyn[idx];
    }
    __syncthreads();

    // dy[m,jj] = kz[m,:] . Wdyn[:,jj] + bdyn[jj]
#pragma unroll
    for (int k = 0; k < 9; k++) {
        int o = t + k * 512;
        if (o < NN * NKD) {
            int m = o / NKD, jj = o - m * NKD;
            const float* kzr = sKz + m * PAD;
            const float* wc  = sU + jj;
            float a0 = 0.f, a1 = 0.f, a2 = 0.f, a3 = 0.f;
            for (int c = 0; c < CC; c += 4) {
                a0 += kzr[c + 0] * wc[(c + 0) * 68];
                a1 += kzr[c + 1] * wc[(c + 1) * 68];
                a2 += kzr[c + 2] * wc[(c + 2) * 68];
                a3 += kzr[c + 3] * wc[(c + 3) * 68];
            }
            sDy[m * 68 + jj] = bdyn[jj] + ((a0 + a1) + (a2 + a3));
        }
    }
    __syncthreads();

    // depth(m,c) = relu(w0*v[c-1] + w1*v[c] + w2*v[c+1])  (overwrites sU)
    for (int idx = t; idx < NN * CC; idx += 512) {
        int m = idx >> 8, c = idx & 255;
        float w0 = sDy[m * 68 + 0], w1 = sDy[m * 68 + 1], w2 = sDy[m * 68 + 2];
        float vm = (c > 0)   ? sV[m * PAD + c - 1] : 0.f;
        float v0 = sV[m * PAD + c];
        float vp = (c < 255) ? sV[m * PAD + c + 1] : 0.f;
        float d = w0 * vm + w1 * v0 + w2 * vp;
        sU[idx] = d > 0.f ? d : 0.f;
    }
    __syncthreads();

    // point(n,c) = sum_m wp[n,m]*depth[m,c]; layernorm over c
    int tx = t & 31, ty = t >> 5;
    float4 acc[4][2];
#pragma unroll
    for (int i = 0; i < 4; i++) {
        acc[i][0] = make_float4(0.f, 0.f, 0.f, 0.f);
        acc[i][1] = make_float4(0.f, 0.f, 0.f, 0.f);
    }
#pragma unroll 2
    for (int m = 0; m < NN; m++) {
        float4 d0 = *(const float4*)(sU + m * CC + tx * 4);
        float4 d1 = *(const float4*)(sU + m * CC + tx * 4 + 128);
#pragma unroll
        for (int i = 0; i < 4; i++) {
            float w = sDy[(ty * 4 + i) * 68 + 3 + m];
            acc[i][0].x += w * d0.x; acc[i][0].y += w * d0.y;
            acc[i][0].z += w * d0.z; acc[i][0].w += w * d0.w;
            acc[i][1].x += w * d1.x; acc[i][1].y += w * d1.y;
            acc[i][1].z += w * d1.z; acc[i][1].w += w * d1.w;
        }
    }
    __syncthreads();

    float* sP = sKz;
    float4 gg0 = *(const float4*)(gn + tx * 4);
    float4 gg1 = *(const float4*)(gn + tx * 4 + 128);
    float4 bb0 = *(const float4*)(bn + tx * 4);
    float4 bb1 = *(const float4*)(bn + tx * 4 + 128);
#pragma unroll
    for (int i = 0; i < 4; i++) {
        int n = ty * 4 + i;
        float4 v0 = acc[i][0], v1 = acc[i][1];
        float sum = v0.x + v0.y + v0.z + v0.w + v1.x + v1.y + v1.z + v1.w;
        float sq  = v0.x * v0.x + v0.y * v0.y + v0.z * v0.z + v0.w * v0.w
                  + v1.x * v1.x + v1.y * v1.y + v1.z * v1.z + v1.w * v1.w;
#pragma unroll
        for (int off = 16; off >= 1; off >>= 1) {
            sum += __shfl_xor_sync(0xffffffffu, sum, off);
            sq  += __shfl_xor_sync(0xffffffffu, sq, off);
        }
        float mu = sum * (1.f / 256.f);
        float var = sq * (1.f / 256.f) - mu * mu;
        float rs = rsqrtf(var + EPSV);
        float4 o0, o1;
        o0.x = (v0.x - mu) * rs * gg0.x + bb0.x;
        o0.y = (v0.y - mu) * rs * gg0.y + bb0.y;
        o0.z = (v0.z - mu) * rs * gg0.z + bb0.z;
        o0.w = (v0.w - mu) * rs * gg0.w + bb0.w;
        o1.x = (v1.x - mu) * rs * gg1.x + bb1.x;
        o1.y = (v1.y - mu) * rs * gg1.y + bb1.y;
        o1.z = (v1.z - mu) * rs * gg1.z + bb1.z;
        o1.w = (v1.w - mu) * rs * gg1.w + bb1.w;
        *(float4*)(sP + n * CC + tx * 4) = o0;
        *(float4*)(sP + n * CC + tx * 4 + 128) = o1;
    }
    __syncthreads();

    // write split-bf16 kernels [c][n]
    __nv_bfloat16* kh = g_kh + (size_t)b * CC * NN;
    __nv_bfloat16* kl = g_kl + (size_t)b * CC * NN;
    for (int idx = t; idx < NN * CC; idx += 512) {
        int c = idx >> 6, n = idx & 63;
        float v = sP[n * CC + c];
        __nv_bfloat16 h = __float2bfloat16(v);
        float lo = v - __bfloat162float(h);
        kh[idx] = h;
        kl[idx] = __float2bfloat16(lo);
    }

    // proto[n] = ka[n,:] . Wp + bp
    if (t < NN) {
        float a0 = 0.f, a1 = 0.f, a2 = 0.f, a3 = 0.f;
        for (int c = 0; c < CC; c += 4) {
            float4 p = *(const float4*)(sP + t * CC + c);
            float4 w = *(const float4*)(Wp + c);
            a0 += p.x * w.x; a1 += p.y * w.y; a2 += p.z * w.z; a3 += p.w * w.w;
        }
        sPr[t] = bp[0] + ((a0 + a1) + (a2 + a3));
    }
    __syncthreads();

    // tem[c] = sigmoid(sum_n proto[n] * ka[n,c])
    if (t < CC) {
        float a0 = 0.f, a1 = 0.f, a2 = 0.f, a3 = 0.f;
        for (int n = 0; n < NN; n += 4) {
            a0 += sPr[n + 0] * sP[(n + 0) * CC + t];
            a1 += sPr[n + 1] * sP[(n + 1) * CC + t];
            a2 += sPr[n + 2] * sP[(n + 2) * CC + t];
            a3 += sPr[n + 3] * sP[(n + 3) * CC + t];
        }
        float s = (a0 + a1) + (a2 + a3);
        g_tem[b * CC + t] = 1.f / (1.f + expf(-s));
    }
}

// ---------------------------------------------------------------------------
// kXC v3: x_corr = xn @ ka fused with out = x_feat + relu(LN(x_corr * tem))
// CTA tile 64(S) x 256(C), 256 threads = 8 warps (2M x 4N), 2 CTAs/SM.
// B pre-split via cp.async; A converted from registers (no raw staging).
// smem: sAh 0(9216) sAl 9216 sBh 18432(36864) sBl 55296 | tem 92160 G 93184
//       B2 94208 sum 95232(1024) sq 96256(1024). total 97280. sOut overlaps.
// ---------------------------------------------------------------------------
#define XC_AH   0
#define XC_AL   9216
#define XC_BH   18432
#define XC_BL   55296
#define XC_TEM  92160
#define XC_G    93184
#define XC_B2   94208
#define XC_SUM  95232
#define XC_SQ   96256
#define SMEM_XC 97280

__global__ void __launch_bounds__(256, 2) kXC(
    const float* __restrict__ xn, const __nv_bfloat16* __restrict__ kh,
    const __nv_bfloat16* __restrict__ kl, const float* __restrict__ xf,
    const float* __restrict__ gl, const float* __restrict__ bl,
    float* __restrict__ out)
{
    extern __shared__ char sm[];
    uint32_t sb = smem_u32(sm);
    float* sTem = (float*)(sm + XC_TEM);
    float* sG   = (float*)(sm + XC_G);
    float* sB2  = (float*)(sm + XC_B2);
    float* sSum = (float*)(sm + XC_SUM);   // [64][4]
    float* sSq  = (float*)(sm + XC_SQ);    // [64][4]
    float* sOut = (float*)sm;              // [64][260] = 66560, overlaps operands

    int t = threadIdx.x, warp = t >> 5, l = t & 31;
    int b = blockIdx.y;
    int s0 = blockIdx.x * 64;
    int wm = (warp & 1) * 32;
    int wn = (warp >> 1) * 64;

    const float* Ab = xn + ((size_t)b * SS + s0) * NN;
    const __nv_bfloat16* Bh = kh + (size_t)b * CC * NN;
    const __nv_bfloat16* Bl = kl + (size_t)b * CC * NN;

    // B hi/lo pre-split: pure cp.async copy (256 rows x 128B each)
#pragma unroll
    for (int i = 0; i < 8; i++) {
        int u = t + i * 256;
        int r = u >> 3, kq = u & 7;
        cp16(sb + XC_BH + r * RS + kq * 16, Bh + r * NN + kq * 8);
    }
#pragma unroll
    for (int i = 0; i < 8; i++) {
        int u = t + i * 256;
        int r = u >> 3, kq = u & 7;
        cp16(sb + XC_BL + r * RS + kq * 16, Bl + r * NN + kq * 8);
    }
    cpcommit();

    // A: 64x64 fp32 -> split bf16 from registers (overlaps with B cp.async)
    {
        char* sAh = sm + XC_AH;
        char* sAl = sm + XC_AL;
        for (int idx = t; idx < 1024; idx += 256) {
            int r = idx >> 4, kq = idx & 15;
            float4 v = *(const float4*)(Ab + (size_t)r * NN + kq * 4);
            uint32_t h0, l0, h1, l1;
            split_pack(v.x, v.y, h0, l0);
            split_pack(v.z, v.w, h1, l1);
            *(uint2*)(sAh + r * RS + kq * 8) = make_uint2(h0, h1);
            *(uint2*)(sAl + r * RS + kq * 8) = make_uint2(l0, l1);
        }
    }
    { sTem[t] = g_tem[b * CC + t]; sG[t] = gl[t]; sB2[t] = bl[t]; }
    cpwait<0>();
    __syncthreads();

    uint32_t aRow = wm + (l & 15);
    uint32_t aOff = ((l >> 4) & 1) * 16;
    uint32_t aHi = sb + XC_AH + aRow * RS + aOff;
    uint32_t aLo = sb + XC_AL + aRow * RS + aOff;
    uint32_t bRow = wn + (l & 7) + ((l & 16) ? 8 : 0);
    uint32_t bOff = (l & 8) ? 16 : 0;
    uint32_t bHi = sb + XC_BH + bRow * RS + bOff;
    uint32_t bLo = sb + XC_BL + bRow * RS + bOff;

    float acc[2][8][4];
#pragma unroll
    for (int i = 0; i < 2; i++)
#pragma unroll
        for (int j = 0; j < 8; j++)
#pragma unroll
            for (int q = 0; q < 4; q++) acc[i][j][q] = 0.f;

#pragma unroll
    for (int ks = 0; ks < 4; ks++) {
        uint32_t ah[2][4], al[2][4], bh[4][4], blr[4][4];
#pragma unroll
        for (int mf = 0; mf < 2; mf++) {
            ldm4(aHi + mf * (16 * RS) + ks * 32, ah[mf]);
            ldm4(aLo + mf * (16 * RS) + ks * 32, al[mf]);
        }
#pragma unroll
        for (int p = 0; p < 4; p++) {
            ldm4(bHi + p * (16 * RS) + ks * 32, bh[p]);
            ldm4(bLo + p * (16 * RS) + ks * 32, blr[p]);
        }
#pragma unroll
        for (int mf = 0; mf < 2; mf++)
#pragma unroll
            for (int nf = 0; nf < 8; nf++) {
                const uint32_t* bhp = &bh[nf >> 1][(nf & 1) * 2];
                const uint32_t* blp = &blr[nf >> 1][(nf & 1) * 2];
                mma16816(acc[mf][nf], ah[mf], bhp);
                mma16816(acc[mf][nf], ah[mf], blp);
                mma16816(acc[mf][nf], al[mf], bhp);
            }
    }

    // apply tem, per-row partial sums (rows split across 4 n-warps)
    float psum[2][2], psq[2][2];
#pragma unroll
    for (int mf = 0; mf < 2; mf++)
#pragma unroll
        for (int h = 0; h < 2; h++) { psum[mf][h] = 0.f; psq[mf][h] = 0.f; }
#pragma unroll
    for (int nf = 0; nf < 8; nf++) {
        int col = wn + nf * 8 + (l & 3) * 2;
        float t0 = sTem[col], t1 = sTem[col + 1];
#pragma unroll
        for (int mf = 0; mf < 2; mf++) {
            acc[mf][nf][0] *= t0; acc[mf][nf][1] *= t1;
            acc[mf][nf][2] *= t0; acc[mf][nf][3] *= t1;
            psum[mf][0] += acc[mf][nf][0] + acc[mf][nf][1];
            psq [mf][0] += acc[mf][nf][0] * acc[mf][nf][0] + acc[mf][nf][1] * acc[mf][nf][1];
            psum[mf][1] += acc[mf][nf][2] + acc[mf][nf][3];
            psq [mf][1] += acc[mf][nf][2] * acc[mf][nf][2] + acc[mf][nf][3] * acc[mf][nf][3];
        }
    }
#pragma unroll
    for (int mf = 0; mf < 2; mf++)
#pragma unroll
        for (int h = 0; h < 2; h++) {
#pragma unroll
            for (int off = 1; off <= 2; off <<= 1) {
                psum[mf][h] += __shfl_xor_sync(0xffffffffu, psum[mf][h], off);
                psq [mf][h] += __shfl_xor_sync(0xffffffffu, psq [mf][h], off);
            }
            if ((l & 3) == 0) {
                int r = wm + mf * 16 + h * 8 + (l >> 2);
                sSum[r * 4 + (warp >> 1)] = psum[mf][h];
                sSq [r * 4 + (warp >> 1)] = psq [mf][h];
            }
        }
    __syncthreads();

    // LN + relu into sOut
#pragma unroll
    for (int mf = 0; mf < 2; mf++)
#pragma unroll
        for (int h = 0; h < 2; h++) {
            int r = wm + mf * 16 + h * 8 + (l >> 2);
            float sum = sSum[r * 4] + sSum[r * 4 + 1] + sSum[r * 4 + 2] + sSum[r * 4 + 3];
            float sq  = sSq [r * 4] + sSq [r * 4 + 1] + sSq [r * 4 + 2] + sSq [r * 4 + 3];
            float mu = sum * (1.f / 256.f);
            float var = sq * (1.f / 256.f) - mu * mu;
            float rs = rsqrtf(var + EPSV);
#pragma unroll
            for (int nf = 0; nf < 8; nf++) {
                int col = wn + nf * 8 + (l & 3) * 2;
                float v0 = acc[mf][nf][h * 2], v1 = acc[mf][nf][h * 2 + 1];
                float o0 = fmaxf((v0 - mu) * rs * sG[col] + sB2[col], 0.f);
                float o1 = fmaxf((v1 - mu) * rs * sG[col + 1] + sB2[col + 1], 0.f);
                *(float2*)(sOut + r * 260 + col) = make_float2(o0, o1);
            }
        }
    __syncthreads();

    // coalesced: out = sOut + x_feat  (64 rows x 256 cols)
    const float* Xb = xf + ((size_t)b * SS + s0) * CC;
    float* Ob = out + ((size_t)b * SS + s0) * CC;
    for (int idx = t; idx < 4096; idx += 256) {
        int r = idx >> 6, cq = idx & 63;
        float4 o = *(float4*)(sOut + r * 260 + cq * 4);
        float4 x = *(const float4*)(Xb + (size_t)r * CC + cq * 4);
        o.x += x.x; o.y += x.y; o.z += x.z; o.w += x.w;
        *(float4*)(Ob + (size_t)r * CC + cq * 4) = o;
    }
}

// ---------------------------------------------------------------------------
extern "C" void kernel_launch(void* const* d_in, const int* in_sizes, int n_in,
                              void* d_out, int out_size) {
    const float* x_feat = (const float*)d_in[0];
    const float* z_feat = (const float*)d_in[1];
    const float* Wz     = (const float*)d_in[2];
    const float* bz     = (const float*)d_in[3];
    const float* Wx     = (const float*)d_in[4];
    const float* bx     = (const float*)d_in[5];
    const float* Wdyn   = (const float*)d_in[6];
    const float* bdyn   = (const float*)d_in[7];
    const float* gnorm  = (const float*)d_in[8];
    const float* bnorm  = (const float*)d_in[9];
    const float* Wp     = (const float*)d_in[10];
    const float* bp     = (const float*)d_in[11];
    const float* g_ln   = (const float*)d_in[12];
    const float* b_ln   = (const float*)d_in[13];
    float* out = (float*)d_out;

    float *xn, *zc, *kz, *kxp;
    __nv_bfloat16 *kh, *kl;
    cudaGetSymbolAddress((void**)&xn,  g_xn);
    cudaGetSymbolAddress((void**)&zc,  g_zc);
    cudaGetSymbolAddress((void**)&kz,  g_kz);
    cudaGetSymbolAddress((void**)&kxp, g_kxp);
    cudaGetSymbolAddress((void**)&kh,  g_kh);
    cudaGetSymbolAddress((void**)&kl,  g_kl);

    cudaFuncSetAttribute(kLinAll,   cudaFuncAttributeMaxDynamicSharedMemorySize, SMEM_KG);
    cudaFuncSetAttribute(kOuterAll, cudaFuncAttributeMaxDynamicSharedMemorySize, SMEM_KG);
    cudaFuncSetAttribute(kD,  cudaFuncAttributeMaxDynamicSharedMemorySize, 218880);
    cudaFuncSetAttribute(kXC, cudaFuncAttributeMaxDynamicSharedMemorySize, SMEM_XC);

    kLinAll<<<640, 256, SMEM_KG>>>(x_feat, Wx, bx, z_feat, Wz, bz, xn, zc);
    kOuterAll<<<384, 256, SMEM_KG>>>(x_feat, z_feat, xn, zc, kxp, kz);
    kD<<<BB, 512, 218880>>>(Wdyn, bdyn, gnorm, bnorm, Wp, bp);
    kXC<<<dim3(16, BB), 256, SMEM_XC>>>(xn, kh, kl, x_feat, g_ln, b_ln, out);
}

// round 11
// speedup vs baseline: 2.3933x; 1.1071x over previous
#include <cuda_runtime.h>
#include <cuda_bf16.h>
#include <math.h>
#include <stdint.h>

#define BB   64
#define SS   1024
#define SZS  256
#define CC   256
#define NN   64
#define NKD  67
#define EPSV 1e-5f
#define PAD  257

// ------------------------- scratch (device globals) -------------------------
__device__ float g_xn [BB * SS * NN];       // x_n    [b][s][n]  16MB
__device__ float g_zc [BB * SZS * NN];      // z_core [b][s][n]   4MB
__device__ float g_kz [BB * CC * NN];       // kernels (z path)  [b][c][n]
__device__ float g_kxp[2 * BB * CC * NN];   // kernels_x partials [b][c][n]
__device__ __nv_bfloat16 g_kh[BB * CC * NN];  // kernels_x post-LN hi [b][c][n]
__device__ __nv_bfloat16 g_kl[BB * CC * NN];  // kernels_x post-LN lo [b][c][n]
__device__ float g_tem[BB * CC];

// ------------------------- helpers -------------------------
__device__ __forceinline__ uint32_t smem_u32(const void* p) {
    uint32_t a;
    asm("{ .reg .u64 tmp; cvta.to.shared.u64 tmp, %1; cvt.u32.u64 %0, tmp; }"
        : "=r"(a) : "l"(p));
    return a;
}
__device__ __forceinline__ void split_pack(float x0, float x1, uint32_t& h, uint32_t& l) {
    __nv_bfloat162 hp = __floats2bfloat162_rn(x0, x1);
    float r0 = x0 - __bfloat162float(hp.x);
    float r1 = x1 - __bfloat162float(hp.y);
    __nv_bfloat162 lp = __floats2bfloat162_rn(r0, r1);
    h = *reinterpret_cast<uint32_t*>(&hp);
    l = *reinterpret_cast<uint32_t*>(&lp);
}
__device__ __forceinline__ void ldm4(uint32_t addr, uint32_t* r) {
    asm volatile("ldmatrix.sync.aligned.m8n8.x4.shared.b16 {%0,%1,%2,%3}, [%4];"
                 : "=r"(r[0]), "=r"(r[1]), "=r"(r[2]), "=r"(r[3]) : "r"(addr));
}
__device__ __forceinline__ void mma16816(float* d, const uint32_t* a, const uint32_t* b) {
    asm volatile(
        "mma.sync.aligned.m16n8k16.row.col.f32.bf16.bf16.f32 "
        "{%0,%1,%2,%3}, {%4,%5,%6,%7}, {%8,%9}, {%0,%1,%2,%3};"
        : "+f"(d[0]), "+f"(d[1]), "+f"(d[2]), "+f"(d[3])
        : "r"(a[0]), "r"(a[1]), "r"(a[2]), "r"(a[3]), "r"(b[0]), "r"(b[1]));
}
__device__ __forceinline__ void cp16(uint32_t dst, const void* src) {
    asm volatile("cp.async.cg.shared.global [%0], [%1], 16;" :: "r"(dst), "l"(src));
}
__device__ __forceinline__ void cpcommit() {
    asm volatile("cp.async.commit_group;" ::: "memory");
}
template<int N> __device__ __forceinline__ void cpwait() {
    asm volatile("cp.async.wait_group %0;" :: "n"(N) : "memory");
}

// bf16 smem row stride (bytes): 72 halves = 144B
#define RS 144
// raw staging strides (floats)
#define RAWA_F  68    // non-TRA: 128 rows x 64+pad
#define RAWAT_F 132   // TRA: 64 k-rows x 128+pad
#define RAWB_F  68    // 64 rows x 64+pad
// smem layout offsets (bytes) — single-buffered raw, 2 CTAs/SM
#define OFF_AH   0        // 128*144 = 18432
#define OFF_AL   18432
#define OFF_BH   36864    // 64*144 = 9216
#define OFF_BL   46080
#define OFF_RAWA 55296    // 34816
#define OFF_RAWB 90112    // 17408
#define OFF_BIAS 107520   // 256
#define SMEM_KG  107776

// ---------------------------------------------------------------------------
// chunk loader: gmem -> raw fp32 smem via cp.async (all coalesced)
// ---------------------------------------------------------------------------
template<bool TRA, bool TRB>
__device__ __forceinline__ void kg_load(const float* Ab, int lda, const float* Bb,
                                        int ldb, int m0, int k0, char* sm, int t) {
    uint32_t ra = smem_u32(sm + OFF_RAWA);
    uint32_t rb = smem_u32(sm + OFF_RAWB);
    if (!TRA) {
#pragma unroll
        for (int i = 0; i < 8; i++) {
            int u = t + i * 256;
            int r = u >> 4, kq = u & 15;
            cp16(ra + r * (RAWA_F * 4) + kq * 16,
                 Ab + (size_t)(m0 + r) * lda + k0 + kq * 4);
        }
    } else {
#pragma unroll
        for (int i = 0; i < 8; i++) {
            int u = t + i * 256;
            int r = u >> 5, mq = u & 31;
            cp16(ra + r * (RAWAT_F * 4) + mq * 16,
                 Ab + (size_t)(k0 + r) * lda + m0 + mq * 4);
        }
    }
    if (!TRB) {
#pragma unroll
        for (int i = 0; i < 4; i++) {
            int u = t + i * 256;
            int r = u >> 4, kq = u & 15;
            cp16(rb + r * (RAWB_F * 4) + kq * 16,
                 Bb + (size_t)r * ldb + k0 + kq * 4);
        }
    } else {
#pragma unroll
        for (int i = 0; i < 4; i++) {
            int u = t + i * 256;
            int r = u >> 4, nq = u & 15;
            cp16(rb + r * (RAWB_F * 4) + nq * 16,
                 Bb + (size_t)(k0 + r) * ldb + nq * 4);
        }
    }
}

// convert raw fp32 -> split-bf16 operand buffers (transpose happens here)
template<bool TRA, bool TRB>
__device__ __forceinline__ void kg_convert(char* sm, int t) {
    float* rawA = (float*)(sm + OFF_RAWA);
    float* rawB = (float*)(sm + OFF_RAWB);
    char* sAh = sm + OFF_AH; char* sAl = sm + OFF_AL;
    char* sBh = sm + OFF_BH; char* sBl = sm + OFF_BL;
    if (!TRA) {
#pragma unroll
        for (int i = 0; i < 8; i++) {
            int u = t + i * 256;
            int r = u >> 4, kq = u & 15;
            float4 v = *(const float4*)(rawA + r * RAWA_F + kq * 4);
            uint32_t h0, l0, h1, l1;
            split_pack(v.x, v.y, h0, l0);
            split_pack(v.z, v.w, h1, l1);
            *(uint2*)(sAh + r * RS + kq * 8) = make_uint2(h0, h1);
            *(uint2*)(sAl + r * RS + kq * 8) = make_uint2(l0, l1);
        }
    } else {
#pragma unroll
        for (int i = 0; i < 8; i++) {
            int u = t + i * 256;
            int m = u & 127, kg = u >> 7;  // kg 0..15
            float f0 = rawA[(kg * 4 + 0) * RAWAT_F + m];
            float f1 = rawA[(kg * 4 + 1) * RAWAT_F + m];
            float f2 = rawA[(kg * 4 + 2) * RAWAT_F + m];
            float f3 = rawA[(kg * 4 + 3) * RAWAT_F + m];
            uint32_t h0, l0, h1, l1;
            split_pack(f0, f1, h0, l0);
            split_pack(f2, f3, h1, l1);
            *(uint2*)(sAh + m * RS + kg * 8) = make_uint2(h0, h1);
            *(uint2*)(sAl + m * RS + kg * 8) = make_uint2(l0, l1);
        }
    }
    if (!TRB) {
#pragma unroll
        for (int i = 0; i < 4; i++) {
            int u = t + i * 256;
            int r = u >> 4, kq = u & 15;
            float4 v = *(const float4*)(rawB + r * RAWB_F + kq * 4);
            uint32_t h0, l0, h1, l1;
            split_pack(v.x, v.y, h0, l0);
            split_pack(v.z, v.w, h1, l1);
            *(uint2*)(sBh + r * RS + kq * 8) = make_uint2(h0, h1);
            *(uint2*)(sBl + r * RS + kq * 8) = make_uint2(l0, l1);
        }
    } else {
#pragma unroll
        for (int i = 0; i < 4; i++) {
            int u = t + i * 256;
            int n = u & 63, kg = u >> 6;  // kg 0..15
            float f0 = rawB[(kg * 4 + 0) * RAWB_F + n];
            float f1 = rawB[(kg * 4 + 1) * RAWB_F + n];
            float f2 = rawB[(kg * 4 + 2) * RAWB_F + n];
            float f3 = rawB[(kg * 4 + 3) * RAWB_F + n];
            uint32_t h0, l0, h1, l1;
            split_pack(f0, f1, h0, l0);
            split_pack(f2, f3, h1, l1);
            *(uint2*)(sBh + n * RS + kg * 8) = make_uint2(h0, h1);
            *(uint2*)(sBl + n * RS + kg * 8) = make_uint2(l0, l1);
        }
    }
}

// ---------------------------------------------------------------------------
// gemm_tile<TRA,TRB>: D[m0..m0+127, 0..63] += sum_k A*B (+bias).
// 256 threads = 8 warps (4M x 2N). Single-buffered; residency=2 gives overlap.
// ---------------------------------------------------------------------------
template<bool TRA, bool TRB>
__device__ void gemm_tile(const float* __restrict__ Ab, int lda,
                          const float* __restrict__ Bb, int ldb,
                          float* __restrict__ Db, int ldd,
                          int m0, int Ktot, const float* __restrict__ bias,
                          char* sm) {
    uint32_t sb = smem_u32(sm);
    int t = threadIdx.x, warp = t >> 5, l = t & 31;
    int wm = (warp & 3) * 32;
    int wn = (warp >> 2) * 32;
    float* sBias = (float*)(sm + OFF_BIAS);
    if (bias && t < 64) sBias[t] = bias[t];

    float acc[2][4][4];
#pragma unroll
    for (int i = 0; i < 2; i++)
#pragma unroll
        for (int j = 0; j < 4; j++)
#pragma unroll
            for (int q = 0; q < 4; q++) acc[i][j][q] = 0.f;

    uint32_t aRow = wm + (l & 15);
    uint32_t aOff = ((l >> 4) & 1) * 16;
    uint32_t aHi = sb + OFF_AH + aRow * RS + aOff;
    uint32_t aLo = sb + OFF_AL + aRow * RS + aOff;
    uint32_t bRow = wn + (l & 7) + ((l & 16) ? 8 : 0);
    uint32_t bOff = (l & 8) ? 16 : 0;
    uint32_t bHi = sb + OFF_BH + bRow * RS + bOff;
    uint32_t bLo = sb + OFF_BL + bRow * RS + bOff;

    int nch = Ktot >> 6;
    for (int ch = 0; ch < nch; ch++) {
        kg_load<TRA, TRB>(Ab, lda, Bb, ldb, m0, ch << 6, sm, t);
        cpcommit();
        cpwait<0>();
        __syncthreads();
        kg_convert<TRA, TRB>(sm, t);
        __syncthreads();
#pragma unroll
        for (int ks = 0; ks < 4; ks++) {
            uint32_t ah[2][4], al[2][4], bh[2][4], bl[2][4];
#pragma unroll
            for (int mf = 0; mf < 2; mf++) {
                ldm4(aHi + mf * (16 * RS) + ks * 32, ah[mf]);
                ldm4(aLo + mf * (16 * RS) + ks * 32, al[mf]);
            }
#pragma unroll
            for (int p = 0; p < 2; p++) {
                ldm4(bHi + p * (16 * RS) + ks * 32, bh[p]);
                ldm4(bLo + p * (16 * RS) + ks * 32, bl[p]);
            }
#pragma unroll
            for (int mf = 0; mf < 2; mf++)
#pragma unroll
                for (int nf = 0; nf < 4; nf++) {
                    const uint32_t* bhp = &bh[nf >> 1][(nf & 1) * 2];
                    const uint32_t* blp = &bl[nf >> 1][(nf & 1) * 2];
                    mma16816(acc[mf][nf], ah[mf], bhp);
                    mma16816(acc[mf][nf], ah[mf], blp);
                    mma16816(acc[mf][nf], al[mf], bhp);
                }
        }
        __syncthreads();
    }

#pragma unroll
    for (int mf = 0; mf < 2; mf++)
#pragma unroll
        for (int nf = 0; nf < 4; nf++) {
            int row = m0 + wm + mf * 16 + (l >> 2);
            int col = wn + nf * 8 + (l & 3) * 2;
            float b0 = bias ? sBias[col] : 0.f;
            float b1 = bias ? sBias[col + 1] : 0.f;
            *(float2*)(Db + (size_t)row * ldd + col) =
                make_float2(acc[mf][nf][0] + b0, acc[mf][nf][1] + b1);
            *(float2*)(Db + (size_t)(row + 8) * ldd + col) =
                make_float2(acc[mf][nf][2] + b0, acc[mf][nf][3] + b1);
        }
}

// ---------------------------------------------------------------------------
// merged launch 1: x_n = X@Wx+bx (512 tiles) and z_core = Z@Wz+bz (128 tiles)
// ---------------------------------------------------------------------------
__global__ void __launch_bounds__(256, 2) kLinAll(
    const float* __restrict__ xf, const float* __restrict__ Wx, const float* __restrict__ bx,
    const float* __restrict__ zf, const float* __restrict__ Wz, const float* __restrict__ bz,
    float* __restrict__ xn, float* __restrict__ zcp) {
    extern __shared__ char sm[];
    int bid = blockIdx.x;
    if (bid < 512) {
        int b = bid >> 3, m0 = (bid & 7) * 128;
        gemm_tile<false, true>(xf + (size_t)b * SS * CC, CC, Wx, NN,
                               xn + (size_t)b * SS * NN, NN, m0, CC, bx, sm);
    } else {
        int zi = bid - 512;
        int b = zi >> 1, m0 = (zi & 1) * 128;
        gemm_tile<false, true>(zf + (size_t)b * SZS * CC, CC, Wz, NN,
                               zcp + (size_t)b * SZS * NN, NN, m0, CC, bz, sm);
    }
}

// ---------------------------------------------------------------------------
// merged launch 2: kx partials (s-split x2, 256 tiles) and kz (128 tiles)
// ---------------------------------------------------------------------------
__global__ void __launch_bounds__(256, 2) kOuterAll(
    const float* __restrict__ xf, const float* __restrict__ zf,
    const float* __restrict__ xn, const float* __restrict__ zcp,
    float* __restrict__ kxp, float* __restrict__ kz) {
    extern __shared__ char sm[];
    int bid = blockIdx.x;
    if (bid < 256) {
        int b = bid >> 2, q = bid & 3, tile = q & 1, half = q >> 1;
        gemm_tile<true, true>(
            xf + (size_t)b * SS * CC + (size_t)half * 512 * CC, CC,
            xn + (size_t)b * SS * NN + (size_t)half * 512 * NN, NN,
            kxp + (size_t)half * BB * CC * NN + (size_t)b * CC * NN, NN,
            tile * 128, 512, nullptr, sm);
    } else {
        int zi = bid - 256;
        int b = zi >> 1, tile = zi & 1;
        gemm_tile<true, true>(
            zf + (size_t)b * SZS * CC, CC, zcp + (size_t)b * SZS * NN, NN,
            kz + (size_t)b * CC * NN, NN, tile * 128, SZS, nullptr, sm);
    }
}

// ---------------------------------------------------------------------------
// kD: dysep conv atten + layernorm + proto + tem. grid(64), 512 threads.
// Writes split-bf16 kernels (g_kh/g_kl, [b][c][n]) and g_tem.
// ---------------------------------------------------------------------------
__global__ void kD(const float* __restrict__ Wdyn, const float* __restrict__ bdyn,
                   const float* __restrict__ gn, const float* __restrict__ bn,
                   const float* __restrict__ Wp, const float* __restrict__ bp) {
    extern __shared__ float smf[];
    float* sKz = smf;            // 64 x PAD (reused later as sP)
    float* sV  = smf + 16448;    // 64 x PAD
    float* sU  = smf + 32896;    // WdynT staging (68-stride), then depth 64x256
    float* sDy = smf + 50304;    // 64 x 68
    float* sPr = smf + 54656;    // 64
    int b = blockIdx.x, t = threadIdx.x;

    const float* kzb = g_kz + (size_t)b * CC * NN;
    const float* kx0 = g_kxp + (size_t)b * CC * NN;
    const float* kx1 = g_kxp + (size_t)BB * CC * NN + (size_t)b * CC * NN;
    for (int idx = t; idx < CC * NN; idx += 512) {
        int c = idx >> 6, n = idx & 63;
        sKz[n * PAD + c] = kzb[idx];
        sV [n * PAD + c] = kx0[idx] + kx1[idx];
    }
    for (int idx = t; idx < CC * NKD; idx += 512) {
        int c = idx / NKD, jj = idx - c * NKD;
        sU[c * 68 + jj] = Wdyn[idx];
    }
    __syncthreads();

    // dy[m,jj] = kz[m,:] . Wdyn[:,jj] + bdyn[jj]
#pragma unroll
    for (int k = 0; k < 9; k++) {
        int o = t + k * 512;
        if (o < NN * NKD) {
            int m = o / NKD, jj = o - m * NKD;
            const float* kzr = sKz + m * PAD;
            const float* wc  = sU + jj;
            float a0 = 0.f, a1 = 0.f, a2 = 0.f, a3 = 0.f;
            for (int c = 0; c < CC; c += 4) {
                a0 += kzr[c + 0] * wc[(c + 0) * 68];
                a1 += kzr[c + 1] * wc[(c + 1) * 68];
                a2 += kzr[c + 2] * wc[(c + 2) * 68];
                a3 += kzr[c + 3] * wc[(c + 3) * 68];
            }
            sDy[m * 68 + jj] = bdyn[jj] + ((a0 + a1) + (a2 + a3));
        }
    }
    __syncthreads();

    // depth(m,c) = relu(w0*v[c-1] + w1*v[c] + w2*v[c+1])  (overwrites sU)
    for (int idx = t; idx < NN * CC; idx += 512) {
        int m = idx >> 8, c = idx & 255;
        float w0 = sDy[m * 68 + 0], w1 = sDy[m * 68 + 1], w2 = sDy[m * 68 + 2];
        float vm = (c > 0)   ? sV[m * PAD + c - 1] : 0.f;
        float v0 = sV[m * PAD + c];
        float vp = (c < 255) ? sV[m * PAD + c + 1] : 0.f;
        float d = w0 * vm + w1 * v0 + w2 * vp;
        sU[idx] = d > 0.f ? d : 0.f;
    }
    __syncthreads();

    // point(n,c) = sum_m wp[n,m]*depth[m,c]; layernorm over c
    int tx = t & 31, ty = t >> 5;
    float4 acc[4][2];
#pragma unroll
    for (int i = 0; i < 4; i++) {
        acc[i][0] = make_float4(0.f, 0.f, 0.f, 0.f);
        acc[i][1] = make_float4(0.f, 0.f, 0.f, 0.f);
    }
#pragma unroll 2
    for (int m = 0; m < NN; m++) {
        float4 d0 = *(const float4*)(sU + m * CC + tx * 4);
        float4 d1 = *(const float4*)(sU + m * CC + tx * 4 + 128);
#pragma unroll
        for (int i = 0; i < 4; i++) {
            float w = sDy[(ty * 4 + i) * 68 + 3 + m];
            acc[i][0].x += w * d0.x; acc[i][0].y += w * d0.y;
            acc[i][0].z += w * d0.z; acc[i][0].w += w * d0.w;
            acc[i][1].x += w * d1.x; acc[i][1].y += w * d1.y;
            acc[i][1].z += w * d1.z; acc[i][1].w += w * d1.w;
        }
    }
    __syncthreads();

    float* sP = sKz;
    float4 gg0 = *(const float4*)(gn + tx * 4);
    float4 gg1 = *(const float4*)(gn + tx * 4 + 128);
    float4 bb0 = *(const float4*)(bn + tx * 4);
    float4 bb1 = *(const float4*)(bn + tx * 4 + 128);
#pragma unroll
    for (int i = 0; i < 4; i++) {
        int n = ty * 4 + i;
        float4 v0 = acc[i][0], v1 = acc[i][1];
        float sum = v0.x + v0.y + v0.z + v0.w + v1.x + v1.y + v1.z + v1.w;
        float sq  = v0.x * v0.x + v0.y * v0.y + v0.z * v0.z + v0.w * v0.w
                  + v1.x * v1.x + v1.y * v1.y + v1.z * v1.z + v1.w * v1.w;
#pragma unroll
        for (int off = 16; off >= 1; off >>= 1) {
            sum += __shfl_xor_sync(0xffffffffu, sum, off);
            sq  += __shfl_xor_sync(0xffffffffu, sq, off);
        }
        float mu = sum * (1.f / 256.f);
        float var = sq * (1.f / 256.f) - mu * mu;
        float rs = rsqrtf(var + EPSV);
        float4 o0, o1;
        o0.x = (v0.x - mu) * rs * gg0.x + bb0.x;
        o0.y = (v0.y - mu) * rs * gg0.y + bb0.y;
        o0.z = (v0.z - mu) * rs * gg0.z + bb0.z;
        o0.w = (v0.w - mu) * rs * gg0.w + bb0.w;
        o1.x = (v1.x - mu) * rs * gg1.x + bb1.x;
        o1.y = (v1.y - mu) * rs * gg1.y + bb1.y;
        o1.z = (v1.z - mu) * rs * gg1.z + bb1.z;
        o1.w = (v1.w - mu) * rs * gg1.w + bb1.w;
        *(float4*)(sP + n * CC + tx * 4) = o0;
        *(float4*)(sP + n * CC + tx * 4 + 128) = o1;
    }
    __syncthreads();

    // write split-bf16 kernels [c][n]
    __nv_bfloat16* kh = g_kh + (size_t)b * CC * NN;
    __nv_bfloat16* kl = g_kl + (size_t)b * CC * NN;
    for (int idx = t; idx < NN * CC; idx += 512) {
        int c = idx >> 6, n = idx & 63;
        float v = sP[n * CC + c];
        __nv_bfloat16 h = __float2bfloat16(v);
        float lo = v - __bfloat162float(h);
        kh[idx] = h;
        kl[idx] = __float2bfloat16(lo);
    }

    // proto[n] = ka[n,:] . Wp + bp
    if (t < NN) {
        float a0 = 0.f, a1 = 0.f, a2 = 0.f, a3 = 0.f;
        for (int c = 0; c < CC; c += 4) {
            float4 p = *(const float4*)(sP + t * CC + c);
            float4 w = *(const float4*)(Wp + c);
            a0 += p.x * w.x; a1 += p.y * w.y; a2 += p.z * w.z; a3 += p.w * w.w;
        }
        sPr[t] = bp[0] + ((a0 + a1) + (a2 + a3));
    }
    __syncthreads();

    // tem[c] = sigmoid(sum_n proto[n] * ka[n,c])
    if (t < CC) {
        float a0 = 0.f, a1 = 0.f, a2 = 0.f, a3 = 0.f;
        for (int n = 0; n < NN; n += 4) {
            a0 += sPr[n + 0] * sP[(n + 0) * CC + t];
            a1 += sPr[n + 1] * sP[(n + 1) * CC + t];
            a2 += sPr[n + 2] * sP[(n + 2) * CC + t];
            a3 += sPr[n + 3] * sP[(n + 3) * CC + t];
        }
        float s = (a0 + a1) + (a2 + a3);
        g_tem[b * CC + t] = 1.f / (1.f + expf(-s));
    }
}

// ---------------------------------------------------------------------------
// kXC v4: B-persistent. grid(4, 64): each CTA stages split-B once and loops
// over 4 S-tiles of 64 rows. LN+relu+residual applied in registers, direct
// float2 stores (no sOut smem round trip). 256 threads, 2 CTAs/SM.
// smem: sAh 0(9216) sAl 9216 sBh 18432(36864) sBl 55296 | tem 92160 G 93184
//       B2 94208 sum 95232(1024) sq 96256(1024). total 97280.
// ---------------------------------------------------------------------------
#define XC_AH   0
#define XC_AL   9216
#define XC_BH   18432
#define XC_BL   55296
#define XC_TEM  92160
#define XC_G    93184
#define XC_B2   94208
#define XC_SUM  95232
#define XC_SQ   96256
#define SMEM_XC 97280

__global__ void __launch_bounds__(256, 2) kXC(
    const float* __restrict__ xn, const __nv_bfloat16* __restrict__ kh,
    const __nv_bfloat16* __restrict__ kl, const float* __restrict__ xf,
    const float* __restrict__ gl, const float* __restrict__ bl,
    float* __restrict__ out)
{
    extern __shared__ char sm[];
    uint32_t sb = smem_u32(sm);
    float* sTem = (float*)(sm + XC_TEM);
    float* sG   = (float*)(sm + XC_G);
    float* sB2  = (float*)(sm + XC_B2);
    float* sSum = (float*)(sm + XC_SUM);   // [64][4]
    float* sSq  = (float*)(sm + XC_SQ);    // [64][4]

    int t = threadIdx.x, warp = t >> 5, l = t & 31;
    int b = blockIdx.y;
    int sbase = blockIdx.x * 256;          // this CTA covers rows [sbase, sbase+256)
    int wm = (warp & 1) * 32;
    int wn = (warp >> 1) * 64;

    const __nv_bfloat16* Bh = kh + (size_t)b * CC * NN;
    const __nv_bfloat16* Bl = kl + (size_t)b * CC * NN;

    // stage split-B ONCE: pure cp.async copy (256 rows x 128B each, hi+lo)
#pragma unroll
    for (int i = 0; i < 8; i++) {
        int u = t + i * 256;
        int r = u >> 3, kq = u & 7;
        cp16(sb + XC_BH + r * RS + kq * 16, Bh + r * NN + kq * 8);
    }
#pragma unroll
    for (int i = 0; i < 8; i++) {
        int u = t + i * 256;
        int r = u >> 3, kq = u & 7;
        cp16(sb + XC_BL + r * RS + kq * 16, Bl + r * NN + kq * 8);
    }
    cpcommit();
    { sTem[t] = g_tem[b * CC + t]; sG[t] = gl[t]; sB2[t] = bl[t]; }
    cpwait<0>();
    __syncthreads();

    uint32_t aRow = wm + (l & 15);
    uint32_t aOff = ((l >> 4) & 1) * 16;
    uint32_t aHi = sb + XC_AH + aRow * RS + aOff;
    uint32_t aLo = sb + XC_AL + aRow * RS + aOff;
    uint32_t bRow = wn + (l & 7) + ((l & 16) ? 8 : 0);
    uint32_t bOff = (l & 8) ? 16 : 0;
    uint32_t bHi = sb + XC_BH + bRow * RS + bOff;
    uint32_t bLo = sb + XC_BL + bRow * RS + bOff;

    for (int it = 0; it < 4; it++) {
        int s0 = sbase + it * 64;
        const float* Ab = xn + ((size_t)b * SS + s0) * NN;

        if (it > 0) __syncthreads();  // previous iter fully done before sAh reuse

        // A: 64x64 fp32 -> split bf16 from registers
        {
            char* sAh = sm + XC_AH;
            char* sAl = sm + XC_AL;
            for (int idx = t; idx < 1024; idx += 256) {
                int r = idx >> 4, kq = idx & 15;
                float4 v = *(const float4*)(Ab + (size_t)r * NN + kq * 4);
                uint32_t h0, l0, h1, l1;
                split_pack(v.x, v.y, h0, l0);
                split_pack(v.z, v.w, h1, l1);
                *(uint2*)(sAh + r * RS + kq * 8) = make_uint2(h0, h1);
                *(uint2*)(sAl + r * RS + kq * 8) = make_uint2(l0, l1);
            }
        }
        __syncthreads();

        float acc[2][8][4];
#pragma unroll
        for (int i = 0; i < 2; i++)
#pragma unroll
            for (int j = 0; j < 8; j++)
#pragma unroll
                for (int q = 0; q < 4; q++) acc[i][j][q] = 0.f;

#pragma unroll
        for (int ks = 0; ks < 4; ks++) {
            uint32_t ah[2][4], al[2][4], bh[4][4], blr[4][4];
#pragma unroll
            for (int mf = 0; mf < 2; mf++) {
                ldm4(aHi + mf * (16 * RS) + ks * 32, ah[mf]);
                ldm4(aLo + mf * (16 * RS) + ks * 32, al[mf]);
            }
#pragma unroll
            for (int p = 0; p < 4; p++) {
                ldm4(bHi + p * (16 * RS) + ks * 32, bh[p]);
                ldm4(bLo + p * (16 * RS) + ks * 32, blr[p]);
            }
#pragma unroll
            for (int mf = 0; mf < 2; mf++)
#pragma unroll
                for (int nf = 0; nf < 8; nf++) {
                    const uint32_t* bhp = &bh[nf >> 1][(nf & 1) * 2];
                    const uint32_t* blp = &blr[nf >> 1][(nf & 1) * 2];
                    mma16816(acc[mf][nf], ah[mf], bhp);
                    mma16816(acc[mf][nf], ah[mf], blp);
                    mma16816(acc[mf][nf], al[mf], bhp);
                }
        }

        // apply tem, per-row partial sums (rows split across 4 n-warps)
        float psum[2][2], psq[2][2];
#pragma unroll
        for (int mf = 0; mf < 2; mf++)
#pragma unroll
            for (int h = 0; h < 2; h++) { psum[mf][h] = 0.f; psq[mf][h] = 0.f; }
#pragma unroll
        for (int nf = 0; nf < 8; nf++) {
            int col = wn + nf * 8 + (l & 3) * 2;
            float t0 = sTem[col], t1 = sTem[col + 1];
#pragma unroll
            for (int mf = 0; mf < 2; mf++) {
                acc[mf][nf][0] *= t0; acc[mf][nf][1] *= t1;
                acc[mf][nf][2] *= t0; acc[mf][nf][3] *= t1;
                psum[mf][0] += acc[mf][nf][0] + acc[mf][nf][1];
                psq [mf][0] += acc[mf][nf][0] * acc[mf][nf][0] + acc[mf][nf][1] * acc[mf][nf][1];
                psum[mf][1] += acc[mf][nf][2] + acc[mf][nf][3];
                psq [mf][1] += acc[mf][nf][2] * acc[mf][nf][2] + acc[mf][nf][3] * acc[mf][nf][3];
            }
        }
#pragma unroll
        for (int mf = 0; mf < 2; mf++)
#pragma unroll
            for (int h = 0; h < 2; h++) {
#pragma unroll
                for (int off = 1; off <= 2; off <<= 1) {
                    psum[mf][h] += __shfl_xor_sync(0xffffffffu, psum[mf][h], off);
                    psq [mf][h] += __shfl_xor_sync(0xffffffffu, psq [mf][h], off);
                }
                if ((l & 3) == 0) {
                    int r = wm + mf * 16 + h * 8 + (l >> 2);
                    sSum[r * 4 + (warp >> 1)] = psum[mf][h];
                    sSq [r * 4 + (warp >> 1)] = psq [mf][h];
                }
            }
        __syncthreads();

        // LN + relu + residual, direct stores
        const float* Xb = xf + ((size_t)b * SS + s0) * CC;
        float* Ob = out + ((size_t)b * SS + s0) * CC;
#pragma unroll
        for (int mf = 0; mf < 2; mf++)
#pragma unroll
            for (int h = 0; h < 2; h++) {
                int r = wm + mf * 16 + h * 8 + (l >> 2);
                float sum = sSum[r * 4] + sSum[r * 4 + 1] + sSum[r * 4 + 2] + sSum[r * 4 + 3];
                float sq  = sSq [r * 4] + sSq [r * 4 + 1] + sSq [r * 4 + 2] + sSq [r * 4 + 3];
                float mu = sum * (1.f / 256.f);
                float var = sq * (1.f / 256.f) - mu * mu;
                float rs = rsqrtf(var + EPSV);
#pragma unroll
                for (int nf = 0; nf < 8; nf++) {
                    int col = wn + nf * 8 + (l & 3) * 2;
                    float v0 = acc[mf][nf][h * 2], v1 = acc[mf][nf][h * 2 + 1];
                    float2 xv = *(const float2*)(Xb + (size_t)r * CC + col);
                    float o0 = fmaxf((v0 - mu) * rs * sG[col] + sB2[col], 0.f) + xv.x;
                    float o1 = fmaxf((v1 - mu) * rs * sG[col + 1] + sB2[col + 1], 0.f) + xv.y;
                    *(float2*)(Ob + (size_t)r * CC + col) = make_float2(o0, o1);
                }
            }
    }
}

// ---------------------------------------------------------------------------
extern "C" void kernel_launch(void* const* d_in, const int* in_sizes, int n_in,
                              void* d_out, int out_size) {
    const float* x_feat = (const float*)d_in[0];
    const float* z_feat = (const float*)d_in[1];
    const float* Wz     = (const float*)d_in[2];
    const float* bz     = (const float*)d_in[3];
    const float* Wx     = (const float*)d_in[4];
    const float* bx     = (const float*)d_in[5];
    const float* Wdyn   = (const float*)d_in[6];
    const float* bdyn   = (const float*)d_in[7];
    const float* gnorm  = (const float*)d_in[8];
    const float* bnorm  = (const float*)d_in[9];
    const float* Wp     = (const float*)d_in[10];
    const float* bp     = (const float*)d_in[11];
    const float* g_ln   = (const float*)d_in[12];
    const float* b_ln   = (const float*)d_in[13];
    float* out = (float*)d_out;

    float *xn, *zc, *kz, *kxp;
    __nv_bfloat16 *kh, *kl;
    cudaGetSymbolAddress((void**)&xn,  g_xn);
    cudaGetSymbolAddress((void**)&zc,  g_zc);
    cudaGetSymbolAddress((void**)&kz,  g_kz);
    cudaGetSymbolAddress((void**)&kxp, g_kxp);
    cudaGetSymbolAddress((void**)&kh,  g_kh);
    cudaGetSymbolAddress((void**)&kl,  g_kl);

    cudaFuncSetAttribute(kLinAll,   cudaFuncAttributeMaxDynamicSharedMemorySize, SMEM_KG);
    cudaFuncSetAttribute(kOuterAll, cudaFuncAttributeMaxDynamicSharedMemorySize, SMEM_KG);
    cudaFuncSetAttribute(kD,  cudaFuncAttributeMaxDynamicSharedMemorySize, 218880);
    cudaFuncSetAttribute(kXC, cudaFuncAttributeMaxDynamicSharedMemorySize, SMEM_XC);

    kLinAll<<<640, 256, SMEM_KG>>>(x_feat, Wx, bx, z_feat, Wz, bz, xn, zc);
    kOuterAll<<<384, 256, SMEM_KG>>>(x_feat, z_feat, xn, zc, kxp, kz);
    kD<<<BB, 512, 218880>>>(Wdyn, bdyn, gnorm, bnorm, Wp, bp);
    kXC<<<dim3(4, BB), 256, SMEM_XC>>>(xn, kh, kl, x_feat, g_ln, b_ln, out);
}